// round 9
// baseline (speedup 1.0000x reference)
#include <cuda_runtime.h>
#include <math.h>
#include <stdint.h>

namespace {
constexpr int BATCH = 128, NNODE = 512, INC = 128, HID = 32, KA = 100, KB = 10, OC = 10;
constexpr int KAP = 128;
constexpr int TOT = BATCH * NNODE;
constexpr int MAXE = BATCH * 8192;
constexpr float EPSV = 1e-15f;

constexpr size_t OFF_DEG    = 0;
constexpr size_t OFF_DFLAT  = OFF_DEG + TOT;
constexpr size_t OFF_LOSSB  = OFF_DFLAT + TOT;
constexpr size_t OFF_XWP    = OFF_LOSSB + BATCH;
constexpr size_t OFF_H      = OFF_XWP   + (size_t)TOT * HID;
constexpr size_t OFF_S1     = OFF_H     + (size_t)TOT * HID;
constexpr size_t OFF_T1     = OFF_S1    + (size_t)TOT * KAP;
constexpr size_t OFF_ADJR1  = OFF_T1    + (size_t)TOT * KAP;
constexpr size_t OFF_SS1    = OFF_ADJR1 + (size_t)BATCH * KAP * KAP;
constexpr size_t OFF_X1     = OFF_SS1   + (size_t)BATCH * KAP * KAP;
constexpr size_t OFF_ADJ1   = OFF_X1    + (size_t)BATCH * KA * HID;
constexpr size_t OFF_DFLAT2 = OFF_ADJ1  + (size_t)BATCH * KA * KA;
constexpr size_t OFF_DUMMY  = OFF_DFLAT2+ (size_t)BATCH * KA;
constexpr size_t OFF_X2     = OFF_DUMMY + (size_t)BATCH * KB;
constexpr size_t OFF_S2     = OFF_X2    + (size_t)BATCH * KA * HID;
constexpr size_t OFF_ADJR2  = OFF_S2    + (size_t)BATCH * KA * KB;
constexpr size_t OFF_SS2    = OFF_ADJR2 + (size_t)BATCH * KB * KB;
constexpr size_t OFF_X3     = OFF_SS2   + (size_t)BATCH * KB * KB;
constexpr size_t OFF_ADJ2   = OFF_X3    + (size_t)BATCH * KB * HID;
constexpr size_t SCRATCH_TOTAL = OFF_ADJ2 + (size_t)BATCH * KB * KB;
}  // namespace

__device__ __align__(16) float g_scratch[SCRATCH_TOTAL];
__device__ __align__(16) int g_cnt_src[TOT];
__device__ __align__(16) int g_cnt_dst[TOT];
__device__ __align__(16) int g_off_src[TOT];
__device__ __align__(16) int g_off_dst[TOT];
__device__ __align__(16) int g_list_src[MAXE];
__device__ __align__(16) int g_list_dst[MAXE];

// ---------------------------------------------------------------------------
// Fused CSR build
// ---------------------------------------------------------------------------
__global__ __launch_bounds__(512) void build_csr_kernel(
    const int* __restrict__ ei, int E, int eper,
    int* __restrict__ off_src, int* __restrict__ cnt_src,
    int* __restrict__ off_dst, int* __restrict__ cnt_dst,
    int* __restrict__ list_src, int* __restrict__ list_dst,
    float* __restrict__ deg, float* __restrict__ dflat) {
    __shared__ int sc[512], sd[512], sscan[512];
    __shared__ int csrc[512], cdst[512];
    int b = blockIdx.x, tid = threadIdx.x;
    sc[tid] = 0; sd[tid] = 0;
    __syncthreads();
    const int* se = ei + (size_t)b * eper;
    const int* de = ei + E + (size_t)b * eper;
    for (int e = tid; e < eper; e += 512) {
        atomicAdd(&sc[se[e] & 511], 1);
        atomicAdd(&sd[de[e] & 511], 1);
    }
    __syncthreads();
    int vs = sc[tid], vd = sd[tid];
    int g = (b << 9) + tid;
    int base = b * eper;
    dflat[g] = (float)vs;
    deg[g]   = (float)vd;
    cnt_src[g] = vs;
    cnt_dst[g] = vd;
    sscan[tid] = vs; __syncthreads();
    for (int o = 1; o < 512; o <<= 1) {
        int t = (tid >= o) ? sscan[tid - o] : 0;
        __syncthreads(); sscan[tid] += t; __syncthreads();
    }
    int es = base + sscan[tid] - vs;
    off_src[g] = es; csrc[tid] = es;
    __syncthreads();
    sscan[tid] = vd; __syncthreads();
    for (int o = 1; o < 512; o <<= 1) {
        int t = (tid >= o) ? sscan[tid - o] : 0;
        __syncthreads(); sscan[tid] += t; __syncthreads();
    }
    int ed = base + sscan[tid] - vd;
    off_dst[g] = ed; cdst[tid] = ed;
    __syncthreads();
    for (int e = tid; e < eper; e += 512) {
        int s = se[e] & 511, d = de[e] & 511;
        int p = atomicAdd(&csrc[s], 1);
        list_src[p] = d;
        int q = atomicAdd(&cdst[d], 1);
        list_dst[q] = s;
    }
}

// ---------------------------------------------------------------------------
__global__ __launch_bounds__(256) void xwp_kernel(const float* __restrict__ x,
                                                  const float* __restrict__ W,
                                                  const float* __restrict__ deg,
                                                  float* __restrict__ xwp) {
    __shared__ float Ws[INC * HID];
    __shared__ float xs[8][INC];
    int tid = threadIdx.y * 32 + threadIdx.x;
    for (int t = tid; t < INC * HID; t += 256) Ws[t] = W[t];
    int r0 = blockIdx.x * 8;
    for (int t = tid; t < 8 * INC; t += 256) {
        int r = t >> 7, k = t & 127;
        xs[r][k] = x[(size_t)(r0 + r) * INC + k];
    }
    __syncthreads();
    int c = threadIdx.x, r = threadIdx.y;
    float acc = 0.f;
#pragma unroll 8
    for (int k = 0; k < INC; k++) acc += xs[r][k] * Ws[k * HID + c];
    int g = r0 + r;
    float dis = rsqrtf(deg[g] + 1.0f);
    xwp[(size_t)g * HID + c] = dis * acc;
}

// ---------------------------------------------------------------------------
__global__ __launch_bounds__(256) void agg_gather_kernel(
    const int* __restrict__ off_dst, const int* __restrict__ cnt_dst,
    const int* __restrict__ list_dst,
    const float* __restrict__ xwp, const float* __restrict__ deg,
    const float* __restrict__ bias, float* __restrict__ h) {
    int node = (blockIdx.x * blockDim.x + threadIdx.x) >> 5;
    int lane = threadIdx.x & 31;
    if (node >= TOT) return;
    int b = node >> 9;
    const float* xb = xwp + (((size_t)b << 9) << 5);
    int off = off_dst[node], cnt = cnt_dst[node];
    float acc = 0.f;
    int i = off, end = off + cnt;
    for (; i + 3 < end; i += 4) {
        int s0 = __ldg(&list_dst[i]),   s1 = __ldg(&list_dst[i + 1]);
        int s2 = __ldg(&list_dst[i + 2]), s3 = __ldg(&list_dst[i + 3]);
        acc += xb[(s0 << 5) + lane] + xb[(s1 << 5) + lane]
             + xb[(s2 << 5) + lane] + xb[(s3 << 5) + lane];
    }
    for (; i < end; i++) acc += xb[(__ldg(&list_dst[i]) << 5) + lane];
    float dis = rsqrtf(deg[node] + 1.0f);
    float xv = xwp[((size_t)node << 5) + lane];
    h[((size_t)node << 5) + lane] = fmaxf(dis * (acc + xv) + bias[lane], 0.f);
}

// ---------------------------------------------------------------------------
__global__ __launch_bounds__(256) void t1_gather_kernel(
    const int* __restrict__ off_src, const int* __restrict__ cnt_src,
    const int* __restrict__ list_src,
    const float* __restrict__ s1p, float* __restrict__ T1) {
    int node = (blockIdx.x * blockDim.x + threadIdx.x) >> 5;
    int lane = threadIdx.x & 31;
    if (node >= TOT) return;
    int b = node >> 9;
    const float4* sb = (const float4*)(s1p + (((size_t)b << 9) << 7)) + lane;
    int off = off_src[node], cnt = cnt_src[node];
    float4 acc = make_float4(0, 0, 0, 0);
    int i = off, end = off + cnt;
    for (; i + 3 < end; i += 4) {
        int d0 = __ldg(&list_src[i]),     d1 = __ldg(&list_src[i + 1]);
        int d2 = __ldg(&list_src[i + 2]), d3 = __ldg(&list_src[i + 3]);
        float4 v0 = __ldg(&sb[d0 << 5]);
        float4 v1 = __ldg(&sb[d1 << 5]);
        float4 v2 = __ldg(&sb[d2 << 5]);
        float4 v3 = __ldg(&sb[d3 << 5]);
        acc.x += (v0.x + v1.x) + (v2.x + v3.x);
        acc.y += (v0.y + v1.y) + (v2.y + v3.y);
        acc.z += (v0.z + v1.z) + (v2.z + v3.z);
        acc.w += (v0.w + v1.w) + (v2.w + v3.w);
    }
    for (; i < end; i++) {
        float4 v = __ldg(&sb[__ldg(&list_src[i]) << 5]);
        acc.x += v.x; acc.y += v.y; acc.z += v.z; acc.w += v.w;
    }
    ((float4*)(T1 + ((size_t)node << 7)))[lane] = acc;
}

// ---------------------------------------------------------------------------
// Warp-level tf32 mma.sync Gram kernel (3-pass hi/lo split, fp32-equivalent):
//   blockIdx.x==0: adjr1 = s1^T @ T1 ; blockIdx.x==1: ss1 = s1^T @ s1
// Both 128x128, K=512 per graph (blockIdx.y). 8 warps, warp = 16 rows.
// ---------------------------------------------------------------------------
__device__ __forceinline__ void mma_tf32(float* c, const uint32_t* a, const uint32_t* bq) {
    asm volatile(
        "mma.sync.aligned.m16n8k8.row.col.f32.tf32.tf32.f32 "
        "{%0,%1,%2,%3}, {%4,%5,%6,%7}, {%8,%9}, {%0,%1,%2,%3};"
        : "+f"(c[0]), "+f"(c[1]), "+f"(c[2]), "+f"(c[3])
        : "r"(a[0]), "r"(a[1]), "r"(a[2]), "r"(a[3]), "r"(bq[0]), "r"(bq[1]));
}

__global__ __launch_bounds__(256) void gram_mma_kernel(
    const float* __restrict__ s1p, const float* __restrict__ T1,
    float* __restrict__ adjr1, float* __restrict__ ss1) {
    __shared__ float Ah[16][136], Al[16][136], Bh[16][136], Bl[16][136];
    int sel = blockIdx.x, b = blockIdx.y;
    const float* A = s1p + ((size_t)b << 16);
    const float* B = T1 + ((size_t)b << 16);
    float* C = (sel ? ss1 : adjr1) + ((size_t)b << 14);
    int tid = threadIdx.x, lane = tid & 31, w = tid >> 5;
    int grp = lane >> 2, tig = lane & 3;
    int m0 = w << 4;
    float acc[16][4];
#pragma unroll
    for (int j = 0; j < 16; j++) {
        acc[j][0] = 0.f; acc[j][1] = 0.f; acc[j][2] = 0.f; acc[j][3] = 0.f;
    }

    for (int n0 = 0; n0 < NNODE; n0 += 16) {
        for (int idx = tid; idx < 2048; idx += 256) {
            int kk = idx >> 7, i = idx & 127;
            float av = A[(size_t)(n0 + kk) * KAP + i];
            float ah = __uint_as_float(__float_as_uint(av) & 0xFFFFE000u);
            Ah[kk][i] = ah;
            Al[kk][i] = av - ah;
            if (!sel) {
                float bv = B[(size_t)(n0 + kk) * KAP + i];
                float bh = __uint_as_float(__float_as_uint(bv) & 0xFFFFE000u);
                Bh[kk][i] = bh;
                Bl[kk][i] = bv - bh;
            }
        }
        __syncthreads();
        const float (*pBh)[136] = sel ? Ah : Bh;
        const float (*pBl)[136] = sel ? Al : Bl;
#pragma unroll
        for (int ks = 0; ks < 2; ks++) {
            int kb = ks << 3;
            uint32_t ahf[4], alf[4];
            ahf[0] = __float_as_uint(Ah[kb + tig][m0 + grp]);
            ahf[1] = __float_as_uint(Ah[kb + tig][m0 + grp + 8]);
            ahf[2] = __float_as_uint(Ah[kb + tig + 4][m0 + grp]);
            ahf[3] = __float_as_uint(Ah[kb + tig + 4][m0 + grp + 8]);
            alf[0] = __float_as_uint(Al[kb + tig][m0 + grp]);
            alf[1] = __float_as_uint(Al[kb + tig][m0 + grp + 8]);
            alf[2] = __float_as_uint(Al[kb + tig + 4][m0 + grp]);
            alf[3] = __float_as_uint(Al[kb + tig + 4][m0 + grp + 8]);
#pragma unroll
            for (int jt = 0; jt < 16; jt++) {
                int j = (jt << 3) + grp;
                uint32_t bhf[2], blf[2];
                bhf[0] = __float_as_uint(pBh[kb + tig][j]);
                bhf[1] = __float_as_uint(pBh[kb + tig + 4][j]);
                blf[0] = __float_as_uint(pBl[kb + tig][j]);
                blf[1] = __float_as_uint(pBl[kb + tig + 4][j]);
                mma_tf32(acc[jt], ahf, bhf);
                mma_tf32(acc[jt], ahf, blf);
                mma_tf32(acc[jt], alf, bhf);
            }
        }
        __syncthreads();
    }
#pragma unroll
    for (int jt = 0; jt < 16; jt++) {
        int col = (jt << 3) + (tig << 1);
        *(float2*)&C[(size_t)(m0 + grp) * KAP + col] = make_float2(acc[jt][0], acc[jt][1]);
        *(float2*)&C[(size_t)(m0 + grp + 8) * KAP + col] = make_float2(acc[jt][2], acc[jt][3]);
    }
}

// ---------------------------------------------------------------------------
__global__ __launch_bounds__(256) void atb8_32_kernel(const float* __restrict__ s1p,
                                                      const float* __restrict__ h,
                                                      float* __restrict__ x1) {
    __shared__ float As[16][128];
    __shared__ float Bs[16][32];
    int b = blockIdx.x;
    const float* A = s1p + ((size_t)b << 9) * KAP;
    const float* B = h + ((size_t)b << 9) * HID;
    float* C = x1 + (size_t)b * KA * HID;
    int tid = threadIdx.x;
    int tx = tid & 7, ty = tid >> 3;
    float acc[4][4] = {};
    for (int n0 = 0; n0 < NNODE; n0 += 16) {
#pragma unroll
        for (int r = 0; r < 2; r++) {
            int t4 = tid + r * 256;
            int kk = t4 >> 5, jf = (t4 & 31) << 2;
            *(float4*)&As[kk][jf] = *(const float4*)(A + (n0 + kk) * KAP + jf);
        }
        if (tid < 128) {
            int kk = tid >> 3, jf = (tid & 7) << 2;
            *(float4*)&Bs[kk][jf] = *(const float4*)(B + (n0 + kk) * HID + jf);
        }
        __syncthreads();
#pragma unroll
        for (int kk = 0; kk < 16; kk++) {
            float4 av = *(float4*)&As[kk][ty * 4];
            float4 bb = *(float4*)&Bs[kk][tx * 4];
            float a[4] = {av.x, av.y, av.z, av.w};
            float bv[4] = {bb.x, bb.y, bb.z, bb.w};
#pragma unroll
            for (int u = 0; u < 4; u++)
#pragma unroll
                for (int v = 0; v < 4; v++) acc[u][v] += a[u] * bv[v];
        }
        __syncthreads();
    }
#pragma unroll
    for (int u = 0; u < 4; u++) {
        int row = ty * 4 + u;
        if (row < KA)
            *(float4*)&C[(size_t)row * HID + tx * 4] =
                make_float4(acc[u][0], acc[u][1], acc[u][2], acc[u][3]);
    }
}

// ---------------------------------------------------------------------------
// stage-1 pooled softmax, 2 rows per iteration (shares W LDS between rows).
// ---------------------------------------------------------------------------
__global__ __launch_bounds__(256) void pool_softmax1_kernel(
    const float* __restrict__ X, const float* __restrict__ W,
    const float* __restrict__ bias, float* __restrict__ Sout) {
    __shared__ float Ws[HID * KAP];
    __shared__ float bs[KAP];
    int tid = threadIdx.x;
    for (int t = tid; t < HID * KAP; t += 256) {
        int c = t >> 7, k = t & 127;
        Ws[t] = (k < KA) ? W[c * KA + k] : 0.f;
    }
    if (tid < KAP) bs[tid] = (tid < KA) ? bias[tid] : 0.f;
    __syncthreads();
    int lane = tid & 31, warp = tid >> 5;
    int row0 = blockIdx.x * 64 + warp * 8;
    float b0v = bs[lane], b1v = bs[32 + lane], b2v = bs[64 + lane], b3v = bs[96 + lane];
#pragma unroll 1
    for (int r = 0; r < 8; r += 2) {
        int row = row0 + r;
        float xv0 = X[(size_t)row * HID + lane];
        float xv1 = X[(size_t)(row + 1) * HID + lane];
        float a0 = b0v, a1 = b1v, a2 = b2v, a3 = b3v;
        float c0 = b0v, c1 = b1v, c2 = b2v, c3 = b3v;
#pragma unroll
        for (int c = 0; c < HID; c++) {
            float bx0 = __shfl_sync(0xffffffffu, xv0, c);
            float bx1 = __shfl_sync(0xffffffffu, xv1, c);
            const float* wr = Ws + (c << 7) + lane;
            float w0 = wr[0], w1 = wr[32], w2 = wr[64], w3 = wr[96];
            a0 += bx0 * w0; a1 += bx0 * w1; a2 += bx0 * w2; a3 += bx0 * w3;
            c0 += bx1 * w0; c1 += bx1 * w1; c2 += bx1 * w2; c3 += bx1 * w3;
        }
        bool v3 = (96 + lane < KA);
        float e0 = __expf(a0), e1 = __expf(a1), e2 = __expf(a2);
        float e3 = v3 ? __expf(a3) : 0.f;
        float f0 = __expf(c0), f1 = __expf(c1), f2 = __expf(c2);
        float f3 = v3 ? __expf(c3) : 0.f;
        float s0 = (e0 + e1) + (e2 + e3);
        float s1 = (f0 + f1) + (f2 + f3);
#pragma unroll
        for (int o = 16; o; o >>= 1) {
            s0 += __shfl_xor_sync(0xffffffffu, s0, o);
            s1 += __shfl_xor_sync(0xffffffffu, s1, o);
        }
        float i0 = __frcp_rn(s0), i1 = __frcp_rn(s1);
        float* op0 = Sout + (size_t)row * KAP + lane;
        op0[0] = e0 * i0; op0[32] = e1 * i0; op0[64] = e2 * i0; op0[96] = e3 * i0;
        float* op1 = Sout + (size_t)(row + 1) * KAP + lane;
        op1[0] = f0 * i1; op1[32] = f1 * i1; op1[64] = f2 * i1; op1[96] = f3 * i1;
    }
}

// ---------------------------------------------------------------------------
__device__ __forceinline__ float blockReduce128(float v, float* sm) {
    int t = threadIdx.x;
    sm[t] = v;
    __syncthreads();
    for (int s = 64; s > 0; s >>= 1) {
        if (t < s) sm[t] += sm[t + s];
        __syncthreads();
    }
    float r = sm[0];
    __syncthreads();
    return r;
}

__global__ void loss_norm_kernel(const float* __restrict__ raw,
                                 const float* __restrict__ ss,
                                 const float* __restrict__ s,
                                 const float* __restrict__ dflat,
                                 float* __restrict__ adjn,
                                 float* __restrict__ dflat2,
                                 float* __restrict__ lossb,
                                 int k, int n, int ld, int ld_s, int bstride,
                                 int accum) {
    int b = blockIdx.x;
    raw  += (size_t)b * bstride;
    ss   += (size_t)b * bstride;
    s    += (size_t)b * n * ld_s;
    dflat+= (size_t)b * n;
    adjn += (size_t)b * k * k;
    dflat2 += (size_t)b * k;
    __shared__ float sm[128];
    __shared__ float idc[128];
    int tid = threadIdx.x;

    float v = 0.f;
    for (int i = tid; i < k; i += 128) v += raw[i * ld + i];
    float num = blockReduce128(v, sm);

    v = 0.f;
    for (int nn = tid; nn < n; nn += 128) {
        float dv = dflat[nn];
        float acc = 0.f;
        for (int kk = 0; kk < k; kk++) {
            float sv = s[(size_t)nn * ld_s + kk];
            acc += sv * sv;
        }
        v += acc * dv;
    }
    float den = blockReduce128(v, sm);

    v = 0.f;
    for (int i = tid; i < k; i += 128)
        for (int j = 0; j < k; j++) { float t = ss[i * ld + j]; v += t * t; }
    float nrm = sqrtf(blockReduce128(v, sm));

    float invn = 1.0f / nrm;
    float dk = rsqrtf((float)k);
    v = 0.f;
    for (int i = tid; i < k; i += 128)
        for (int j = 0; j < k; j++) {
            float t = ss[i * ld + j] * invn - ((i == j) ? dk : 0.f);
            v += t * t;
        }
    float ortho = sqrtf(blockReduce128(v, sm));

    for (int i = tid; i < k; i += 128) {
        float r = 0.f;
        for (int j = 0; j < k; j++) if (j != i) r += raw[i * ld + j];
        idc[i] = 1.0f / (sqrtf(r) + EPSV);
    }
    __syncthreads();
    for (int idx = tid; idx < k * k; idx += 128) {
        int i = idx / k, j = idx - i * k;
        adjn[idx] = (i == j) ? 0.f : raw[i * ld + j] * idc[i] * idc[j];
    }
    for (int i = tid; i < k; i += 128) {
        float r = 0.f;
        for (int j = 0; j < k; j++) if (j != i) r += raw[i * ld + j] * idc[j];
        dflat2[i] = r * idc[i];
    }
    if (tid == 0) {
        float val = -num / den + ortho;
        if (accum) lossb[b] += val; else lossb[b] = val;
    }
}

// ---------------------------------------------------------------------------
__global__ __launch_bounds__(256) void stage2_conv_kernel(
    const float* __restrict__ adj1, const float* __restrict__ x1,
    const float* __restrict__ relW, const float* __restrict__ relb,
    const float* __restrict__ rootW,
    const float* __restrict__ p2W, const float* __restrict__ p2b,
    float* __restrict__ x2, float* __restrict__ s2) {
    extern __shared__ float sm[];
    float* adj1s = sm;
    float* x1s   = sm + 10000;
    float* relWs = sm + 13200;
    float* rootWs= sm + 14224;
    float* p2Ws  = sm + 15248;
    int b = blockIdx.x, tid = threadIdx.x;
    const float* A = adj1 + (size_t)b * KA * KA;
    const float* X = x1 + (size_t)b * KA * HID;
    for (int i = tid; i < KA * KA; i += 256) adj1s[i] = A[i];
    for (int i = tid; i < KA * HID; i += 256) x1s[i] = X[i];
    for (int i = tid; i < HID * HID; i += 256) { relWs[i] = relW[i]; rootWs[i] = rootW[i]; }
    for (int i = tid; i < HID * KB; i += 256) p2Ws[i] = p2W[i];
    __syncthreads();
    int lane = tid & 31, warp = tid >> 5;
    float rb = relb[lane];
    int kk10 = lane < KB ? lane : 0;
    float p2bv = p2b[kk10];
    for (int i = warp; i < KA; i += 8) {
        float t2 = 0.f;
        const float* ar = adj1s + i * KA;
        for (int m = 0; m < KA; m++) t2 += ar[m] * x1s[(m << 5) + lane];
        float x1v = x1s[(i << 5) + lane];
        float a = rb;
#pragma unroll
        for (int k = 0; k < 32; k++)
            a += __shfl_sync(0xffffffffu, t2, k) * relWs[(k << 5) + lane]
               + __shfl_sync(0xffffffffu, x1v, k) * rootWs[(k << 5) + lane];
        float x2v = fmaxf(a, 0.f);
        x2[((size_t)b * KA + i) * HID + lane] = x2v;
        float zz = p2bv;
#pragma unroll
        for (int c = 0; c < 32; c++)
            zz += __shfl_sync(0xffffffffu, x2v, c) * p2Ws[c * KB + kk10];
        float e = (lane < KB) ? __expf(zz) : 0.f;
        float ssum = e;
#pragma unroll
        for (int o = 16; o; o >>= 1) ssum += __shfl_xor_sync(0xffffffffu, ssum, o);
        if (lane < KB) s2[((size_t)b * KA + i) * KB + lane] = e / ssum;
    }
}

// ---------------------------------------------------------------------------
__global__ __launch_bounds__(256) void stage2b_kernel(
    const float* __restrict__ adj1, const float* __restrict__ s2,
    const float* __restrict__ x2,
    float* __restrict__ adjr2, float* __restrict__ ss2, float* __restrict__ x3) {
    extern __shared__ float sm[];
    float* adj1s = sm;
    float* s2s   = sm + 10000;
    float* x2s   = sm + 11000;
    float* tt2s  = sm + 14200;
    int b = blockIdx.x, tid = threadIdx.x;
    const float* A = adj1 + (size_t)b * KA * KA;
    const float* S2 = s2 + (size_t)b * KA * KB;
    const float* X2 = x2 + (size_t)b * KA * HID;
    for (int i = tid; i < KA * KA; i += 256) adj1s[i] = A[i];
    for (int i = tid; i < KA * KB; i += 256) s2s[i] = S2[i];
    for (int i = tid; i < KA * HID; i += 256) x2s[i] = X2[i];
    __syncthreads();
    for (int t = tid; t < KA * KB; t += 256) {
        int i = t / KB, k = t - i * KB;
        float a = 0.f;
        const float* ar = adj1s + i * KA;
        for (int m = 0; m < KA; m++) a += ar[m] * s2s[m * KB + k];
        tt2s[t] = a;
    }
    __syncthreads();
    for (int t = tid; t < 520; t += 256) {
        if (t < 100) {
            int i = t / 10, j = t - i * 10;
            float a = 0.f;
            for (int n = 0; n < KA; n++) a += s2s[n * KB + i] * tt2s[n * KB + j];
            adjr2[(size_t)b * 100 + t] = a;
        } else if (t < 200) {
            int u = t - 100;
            int i = u / 10, j = u - i * 10;
            float a = 0.f;
            for (int n = 0; n < KA; n++) a += s2s[n * KB + i] * s2s[n * KB + j];
            ss2[(size_t)b * 100 + u] = a;
        } else {
            int u = t - 200;
            int i = u >> 5, c = u & 31;
            float a = 0.f;
            for (int n = 0; n < KA; n++) a += s2s[n * KB + i] * x2s[(n << 5) + c];
            x3[(size_t)b * 320 + u] = a;
        }
    }
}

// ---------------------------------------------------------------------------
__global__ void tail_kernel(const float* __restrict__ adj2, const float* __restrict__ x3,
                            const float* __restrict__ c3rW, const float* __restrict__ c3rb,
                            const float* __restrict__ c3oW,
                            const float* __restrict__ l1W, const float* __restrict__ l1b,
                            const float* __restrict__ l2W, const float* __restrict__ l2b,
                            float* __restrict__ out) {
    int b = blockIdx.x, lane = threadIdx.x;
    const float* A2 = adj2 + (size_t)b * 100;
    const float* X3 = x3 + (size_t)b * 320;
    float x3c[10], t3c[10];
#pragma unroll
    for (int j = 0; j < 10; j++) x3c[j] = X3[j * 32 + lane];
#pragma unroll
    for (int i = 0; i < 10; i++) {
        float a = 0.f;
#pragma unroll
        for (int j = 0; j < 10; j++) a += A2[i * 10 + j] * x3c[j];
        t3c[i] = a;
    }
    float rb = c3rb[lane];
    float g = 0.f;
#pragma unroll
    for (int i = 0; i < 10; i++) {
        float a = rb;
#pragma unroll
        for (int k = 0; k < 32; k++)
            a += __shfl_sync(0xffffffffu, t3c[i], k) * c3rW[k * 32 + lane]
               + __shfl_sync(0xffffffffu, x3c[i], k) * c3oW[k * 32 + lane];
        g += a;
    }
    g *= 0.1f;
    float a1 = l1b[lane];
#pragma unroll
    for (int k = 0; k < 32; k++) a1 += __shfl_sync(0xffffffffu, g, k) * l1W[k * 32 + lane];
    float gg = fmaxf(a1, 0.f);
    int kk = lane < OC ? lane : 0;
    float a2 = l2b[kk];
#pragma unroll
    for (int k = 0; k < 32; k++) a2 += __shfl_sync(0xffffffffu, gg, k) * l2W[k * OC + kk];
    float val = (lane < OC) ? a2 : -INFINITY;
    float m = val;
#pragma unroll
    for (int o = 16; o; o >>= 1) m = fmaxf(m, __shfl_xor_sync(0xffffffffu, m, o));
    float e = (lane < OC) ? __expf(val - m) : 0.f;
    float ssum = e;
#pragma unroll
    for (int o = 16; o; o >>= 1) ssum += __shfl_xor_sync(0xffffffffu, ssum, o);
    if (lane < OC) out[b * OC + lane] = val - m - logf(ssum);
}

__global__ void final_kernel(const float* __restrict__ lossb, float* __restrict__ out,
                             int out_size) {
    __shared__ float sm[128];
    int t = threadIdx.x;
    sm[t] = lossb[t];
    __syncthreads();
    for (int s = 64; s > 0; s >>= 1) {
        if (t < s) sm[t] += sm[t + s];
        __syncthreads();
    }
    if (t == 0 && out_size > BATCH * OC) out[BATCH * OC] = sm[0] / (float)BATCH;
}

// ---------------------------------------------------------------------------
extern "C" void kernel_launch(void* const* d_in, const int* in_sizes, int n_in,
                              void* d_out, int out_size) {
    const float* x    = (const float*)d_in[0];
    const int*   ei   = (const int*)  d_in[1];
    const float* c1W  = (const float*)d_in[3];
    const float* c1b  = (const float*)d_in[4];
    const float* p1W  = (const float*)d_in[5];
    const float* p1b  = (const float*)d_in[6];
    const float* c2rW = (const float*)d_in[7];
    const float* c2rb = (const float*)d_in[8];
    const float* c2oW = (const float*)d_in[9];
    const float* p2W  = (const float*)d_in[10];
    const float* p2b  = (const float*)d_in[11];
    const float* c3rW = (const float*)d_in[12];
    const float* c3rb = (const float*)d_in[13];
    const float* c3oW = (const float*)d_in[14];
    const float* l1W  = (const float*)d_in[15];
    const float* l1b  = (const float*)d_in[16];
    const float* l2W  = (const float*)d_in[17];
    const float* l2b  = (const float*)d_in[18];
    float* out = (float*)d_out;
    int E = in_sizes[1] / 2;
    int eper = E / BATCH;

    void* sp = nullptr;
    cudaGetSymbolAddress(&sp, g_scratch);
    float* S = (float*)sp;
    int *csn, *cdn, *osn, *odn, *lsrc, *ldst;
    cudaGetSymbolAddress((void**)&csn, g_cnt_src);
    cudaGetSymbolAddress((void**)&cdn, g_cnt_dst);
    cudaGetSymbolAddress((void**)&osn, g_off_src);
    cudaGetSymbolAddress((void**)&odn, g_off_dst);
    cudaGetSymbolAddress((void**)&lsrc, g_list_src);
    cudaGetSymbolAddress((void**)&ldst, g_list_dst);

    cudaFuncSetAttribute(stage2_conv_kernel, cudaFuncAttributeMaxDynamicSharedMemorySize, 62272);
    cudaFuncSetAttribute(stage2b_kernel, cudaFuncAttributeMaxDynamicSharedMemorySize, 60800);

    build_csr_kernel<<<BATCH, 512>>>(ei, E, eper, osn, csn, odn, cdn, lsrc, ldst,
                                     S + OFF_DEG, S + OFF_DFLAT);
    xwp_kernel<<<TOT / 8, dim3(32, 8)>>>(x, c1W, S + OFF_DEG, S + OFF_XWP);
    agg_gather_kernel<<<TOT * 32 / 256, 256>>>(odn, cdn, ldst, S + OFF_XWP,
                                               S + OFF_DEG, c1b, S + OFF_H);
    pool_softmax1_kernel<<<TOT / 64, 256>>>(S + OFF_H, p1W, p1b, S + OFF_S1);
    t1_gather_kernel<<<TOT * 32 / 256, 256>>>(osn, csn, lsrc, S + OFF_S1, S + OFF_T1);
    { dim3 g(2, BATCH); gram_mma_kernel<<<g, 256>>>(S + OFF_S1, S + OFF_T1, S + OFF_ADJR1, S + OFF_SS1); }
    atb8_32_kernel<<<BATCH, 256>>>(S + OFF_S1, S + OFF_H, S + OFF_X1);
    loss_norm_kernel<<<BATCH, 128>>>(S + OFF_ADJR1, S + OFF_SS1, S + OFF_S1, S + OFF_DFLAT,
                                     S + OFF_ADJ1, S + OFF_DFLAT2, S + OFF_LOSSB,
                                     KA, NNODE, KAP, KAP, KAP * KAP, 0);
    stage2_conv_kernel<<<BATCH, 256, 62272>>>(S + OFF_ADJ1, S + OFF_X1, c2rW, c2rb, c2oW,
                                              p2W, p2b, S + OFF_X2, S + OFF_S2);
    stage2b_kernel<<<BATCH, 256, 60800>>>(S + OFF_ADJ1, S + OFF_S2, S + OFF_X2,
                                          S + OFF_ADJR2, S + OFF_SS2, S + OFF_X3);
    loss_norm_kernel<<<BATCH, 128>>>(S + OFF_ADJR2, S + OFF_SS2, S + OFF_S2, S + OFF_DFLAT2,
                                     S + OFF_ADJ2, S + OFF_DUMMY, S + OFF_LOSSB,
                                     KB, KA, KB, KB, KB * KB, 1);
    tail_kernel<<<BATCH, 32>>>(S + OFF_ADJ2, S + OFF_X3, c3rW, c3rb, c3oW,
                               l1W, l1b, l2W, l2b, out);
    final_kernel<<<1, 128>>>(S + OFF_LOSSB, out, out_size);
}

// round 10
// speedup vs baseline: 1.0799x; 1.0799x over previous
#include <cuda_runtime.h>
#include <math.h>
#include <stdint.h>

namespace {
constexpr int BATCH = 128, NNODE = 512, INC = 128, HID = 32, KA = 100, KB = 10, OC = 10;
constexpr int KAP = 128;
constexpr int TOT = BATCH * NNODE;
constexpr int MAXE = BATCH * 8192;
constexpr float EPSV = 1e-15f;

constexpr size_t OFF_DEG    = 0;
constexpr size_t OFF_DFLAT  = OFF_DEG + TOT;
constexpr size_t OFF_LOSSB  = OFF_DFLAT + TOT;
constexpr size_t OFF_XWP    = OFF_LOSSB + BATCH;
constexpr size_t OFF_H      = OFF_XWP   + (size_t)TOT * HID;
constexpr size_t OFF_S1     = OFF_H     + (size_t)TOT * HID;
constexpr size_t OFF_T1     = OFF_S1    + (size_t)TOT * KAP;
constexpr size_t OFF_ADJR1  = OFF_T1    + (size_t)TOT * KAP;
constexpr size_t OFF_SS1    = OFF_ADJR1 + (size_t)BATCH * KAP * KAP;
constexpr size_t OFF_X1     = OFF_SS1   + (size_t)BATCH * KAP * KAP;
constexpr size_t OFF_ADJ1   = OFF_X1    + (size_t)BATCH * KA * HID;
constexpr size_t OFF_DFLAT2 = OFF_ADJ1  + (size_t)BATCH * KA * KA;
constexpr size_t OFF_DUMMY  = OFF_DFLAT2+ (size_t)BATCH * KA;
constexpr size_t OFF_X2     = OFF_DUMMY + (size_t)BATCH * KB;
constexpr size_t OFF_S2     = OFF_X2    + (size_t)BATCH * KA * HID;
constexpr size_t OFF_ADJR2  = OFF_S2    + (size_t)BATCH * KA * KB;
constexpr size_t OFF_SS2    = OFF_ADJR2 + (size_t)BATCH * KB * KB;
constexpr size_t OFF_X3     = OFF_SS2   + (size_t)BATCH * KB * KB;
constexpr size_t OFF_ADJ2   = OFF_X3    + (size_t)BATCH * KB * HID;
constexpr size_t SCRATCH_TOTAL = OFF_ADJ2 + (size_t)BATCH * KB * KB;
}  // namespace

__device__ __align__(16) float g_scratch[SCRATCH_TOTAL];
__device__ __align__(16) int g_cnt_src[TOT];
__device__ __align__(16) int g_cnt_dst[TOT];
__device__ __align__(16) int g_off_src[TOT];
__device__ __align__(16) int g_off_dst[TOT];
__device__ __align__(16) int g_list_src[MAXE];
__device__ __align__(16) int g_list_dst[MAXE];

// ---------------------------------------------------------------------------
// Fused CSR build
// ---------------------------------------------------------------------------
__global__ __launch_bounds__(512) void build_csr_kernel(
    const int* __restrict__ ei, int E, int eper,
    int* __restrict__ off_src, int* __restrict__ cnt_src,
    int* __restrict__ off_dst, int* __restrict__ cnt_dst,
    int* __restrict__ list_src, int* __restrict__ list_dst,
    float* __restrict__ deg, float* __restrict__ dflat) {
    __shared__ int sc[512], sd[512], sscan[512];
    __shared__ int csrc[512], cdst[512];
    int b = blockIdx.x, tid = threadIdx.x;
    sc[tid] = 0; sd[tid] = 0;
    __syncthreads();
    const int* se = ei + (size_t)b * eper;
    const int* de = ei + E + (size_t)b * eper;
    for (int e = tid; e < eper; e += 512) {
        atomicAdd(&sc[se[e] & 511], 1);
        atomicAdd(&sd[de[e] & 511], 1);
    }
    __syncthreads();
    int vs = sc[tid], vd = sd[tid];
    int g = (b << 9) + tid;
    int base = b * eper;
    dflat[g] = (float)vs;
    deg[g]   = (float)vd;
    cnt_src[g] = vs;
    cnt_dst[g] = vd;
    sscan[tid] = vs; __syncthreads();
    for (int o = 1; o < 512; o <<= 1) {
        int t = (tid >= o) ? sscan[tid - o] : 0;
        __syncthreads(); sscan[tid] += t; __syncthreads();
    }
    int es = base + sscan[tid] - vs;
    off_src[g] = es; csrc[tid] = es;
    __syncthreads();
    sscan[tid] = vd; __syncthreads();
    for (int o = 1; o < 512; o <<= 1) {
        int t = (tid >= o) ? sscan[tid - o] : 0;
        __syncthreads(); sscan[tid] += t; __syncthreads();
    }
    int ed = base + sscan[tid] - vd;
    off_dst[g] = ed; cdst[tid] = ed;
    __syncthreads();
    for (int e = tid; e < eper; e += 512) {
        int s = se[e] & 511, d = de[e] & 511;
        int p = atomicAdd(&csrc[s], 1);
        list_src[p] = d;
        int q = atomicAdd(&cdst[d], 1);
        list_dst[q] = s;
    }
}

// ---------------------------------------------------------------------------
__global__ __launch_bounds__(256) void xwp_kernel(const float* __restrict__ x,
                                                  const float* __restrict__ W,
                                                  const float* __restrict__ deg,
                                                  float* __restrict__ xwp) {
    __shared__ float Ws[INC * HID];
    __shared__ float xs[8][INC];
    int tid = threadIdx.y * 32 + threadIdx.x;
    for (int t = tid; t < INC * HID; t += 256) Ws[t] = W[t];
    int r0 = blockIdx.x * 8;
    for (int t = tid; t < 8 * INC; t += 256) {
        int r = t >> 7, k = t & 127;
        xs[r][k] = x[(size_t)(r0 + r) * INC + k];
    }
    __syncthreads();
    int c = threadIdx.x, r = threadIdx.y;
    float acc = 0.f;
#pragma unroll 8
    for (int k = 0; k < INC; k++) acc += xs[r][k] * Ws[k * HID + c];
    int g = r0 + r;
    float dis = rsqrtf(deg[g] + 1.0f);
    xwp[(size_t)g * HID + c] = dis * acc;
}

// ---------------------------------------------------------------------------
__global__ __launch_bounds__(256) void agg_gather_kernel(
    const int* __restrict__ off_dst, const int* __restrict__ cnt_dst,
    const int* __restrict__ list_dst,
    const float* __restrict__ xwp, const float* __restrict__ deg,
    const float* __restrict__ bias, float* __restrict__ h) {
    int node = (blockIdx.x * blockDim.x + threadIdx.x) >> 5;
    int lane = threadIdx.x & 31;
    if (node >= TOT) return;
    int b = node >> 9;
    const float* xb = xwp + (((size_t)b << 9) << 5);
    int off = off_dst[node], cnt = cnt_dst[node];
    float acc = 0.f;
    int i = off, end = off + cnt;
    for (; i + 3 < end; i += 4) {
        int s0 = __ldg(&list_dst[i]),   s1 = __ldg(&list_dst[i + 1]);
        int s2 = __ldg(&list_dst[i + 2]), s3 = __ldg(&list_dst[i + 3]);
        acc += xb[(s0 << 5) + lane] + xb[(s1 << 5) + lane]
             + xb[(s2 << 5) + lane] + xb[(s3 << 5) + lane];
    }
    for (; i < end; i++) acc += xb[(__ldg(&list_dst[i]) << 5) + lane];
    float dis = rsqrtf(deg[node] + 1.0f);
    float xv = xwp[((size_t)node << 5) + lane];
    h[((size_t)node << 5) + lane] = fmaxf(dis * (acc + xv) + bias[lane], 0.f);
}

// ---------------------------------------------------------------------------
__global__ __launch_bounds__(256) void t1_gather_kernel(
    const int* __restrict__ off_src, const int* __restrict__ cnt_src,
    const int* __restrict__ list_src,
    const float* __restrict__ s1p, float* __restrict__ T1) {
    int node = (blockIdx.x * blockDim.x + threadIdx.x) >> 5;
    int lane = threadIdx.x & 31;
    if (node >= TOT) return;
    int b = node >> 9;
    const float4* sb = (const float4*)(s1p + (((size_t)b << 9) << 7)) + lane;
    int off = off_src[node], cnt = cnt_src[node];
    float4 acc = make_float4(0, 0, 0, 0);
    int i = off, end = off + cnt;
    for (; i + 3 < end; i += 4) {
        int d0 = __ldg(&list_src[i]),     d1 = __ldg(&list_src[i + 1]);
        int d2 = __ldg(&list_src[i + 2]), d3 = __ldg(&list_src[i + 3]);
        float4 v0 = __ldg(&sb[d0 << 5]);
        float4 v1 = __ldg(&sb[d1 << 5]);
        float4 v2 = __ldg(&sb[d2 << 5]);
        float4 v3 = __ldg(&sb[d3 << 5]);
        acc.x += (v0.x + v1.x) + (v2.x + v3.x);
        acc.y += (v0.y + v1.y) + (v2.y + v3.y);
        acc.z += (v0.z + v1.z) + (v2.z + v3.z);
        acc.w += (v0.w + v1.w) + (v2.w + v3.w);
    }
    for (; i < end; i++) {
        float4 v = __ldg(&sb[__ldg(&list_src[i]) << 5]);
        acc.x += v.x; acc.y += v.y; acc.z += v.z; acc.w += v.w;
    }
    ((float4*)(T1 + ((size_t)node << 7)))[lane] = acc;
}

// ---------------------------------------------------------------------------
// adjr1 = s1^T T1 (sel=0) / ss1 = s1^T s1 (sel=1). Double-buffered, micro 8x8.
// ---------------------------------------------------------------------------
__global__ __launch_bounds__(256) void atb8_128_kernel(const float* __restrict__ s1p,
                                                       const float* __restrict__ T1,
                                                       float* __restrict__ adjr1,
                                                       float* __restrict__ ss1) {
    __shared__ float As[2][16][128];
    __shared__ float Bs[2][16][128];
    int b = blockIdx.y;
    int sel = blockIdx.x;
    const float* A = s1p + ((size_t)b << 9) * KAP;
    const float* B = (sel ? s1p : T1) + ((size_t)b << 9) * KAP;
    float* C = (sel ? ss1 : adjr1) + (size_t)b * KAP * KAP;
    int tid = threadIdx.x;
    int tx = tid & 15, ty = tid >> 4;
    int lk0 = tid >> 5,         lj0 = (tid & 31) << 2;
    int lk1 = (tid + 256) >> 5, lj1 = ((tid + 256) & 31) << 2;

    float4 pa0, pa1, pb0, pb1;
    pa0 = *(const float4*)(A + lk0 * KAP + lj0);
    pa1 = *(const float4*)(A + lk1 * KAP + lj1);
    pb0 = *(const float4*)(B + lk0 * KAP + lj0);
    pb1 = *(const float4*)(B + lk1 * KAP + lj1);
    *(float4*)&As[0][lk0][lj0] = pa0;
    *(float4*)&As[0][lk1][lj1] = pa1;
    *(float4*)&Bs[0][lk0][lj0] = pb0;
    *(float4*)&Bs[0][lk1][lj1] = pb1;
    __syncthreads();

    float acc[8][8] = {};
    int cur = 0;
    for (int n0 = 0; n0 < NNODE; n0 += 16) {
        int nn = n0 + 16;
        if (nn < NNODE) {
            pa0 = *(const float4*)(A + (nn + lk0) * KAP + lj0);
            pa1 = *(const float4*)(A + (nn + lk1) * KAP + lj1);
            pb0 = *(const float4*)(B + (nn + lk0) * KAP + lj0);
            pb1 = *(const float4*)(B + (nn + lk1) * KAP + lj1);
        }
#pragma unroll
        for (int kk = 0; kk < 16; kk++) {
            float4 a0 = *(float4*)&As[cur][kk][ty * 8];
            float4 a1 = *(float4*)&As[cur][kk][ty * 8 + 4];
            float4 b0 = *(float4*)&Bs[cur][kk][tx * 8];
            float4 b1 = *(float4*)&Bs[cur][kk][tx * 8 + 4];
            float a[8] = {a0.x, a0.y, a0.z, a0.w, a1.x, a1.y, a1.z, a1.w};
            float bv[8] = {b0.x, b0.y, b0.z, b0.w, b1.x, b1.y, b1.z, b1.w};
#pragma unroll
            for (int u = 0; u < 8; u++)
#pragma unroll
                for (int v = 0; v < 8; v++) acc[u][v] += a[u] * bv[v];
        }
        if (nn < NNODE) {
            int nx = cur ^ 1;
            *(float4*)&As[nx][lk0][lj0] = pa0;
            *(float4*)&As[nx][lk1][lj1] = pa1;
            *(float4*)&Bs[nx][lk0][lj0] = pb0;
            *(float4*)&Bs[nx][lk1][lj1] = pb1;
            __syncthreads();
            cur = nx;
        }
    }
#pragma unroll
    for (int u = 0; u < 8; u++) {
        int row = ty * 8 + u;
        *(float4*)&C[(size_t)row * KAP + tx * 8] =
            make_float4(acc[u][0], acc[u][1], acc[u][2], acc[u][3]);
        *(float4*)&C[(size_t)row * KAP + tx * 8 + 4] =
            make_float4(acc[u][4], acc[u][5], acc[u][6], acc[u][7]);
    }
}

// ---------------------------------------------------------------------------
__global__ __launch_bounds__(256) void atb8_32_kernel(const float* __restrict__ s1p,
                                                      const float* __restrict__ h,
                                                      float* __restrict__ x1) {
    __shared__ float As[16][128];
    __shared__ float Bs[16][32];
    int b = blockIdx.x;
    const float* A = s1p + ((size_t)b << 9) * KAP;
    const float* B = h + ((size_t)b << 9) * HID;
    float* C = x1 + (size_t)b * KA * HID;
    int tid = threadIdx.x;
    int tx = tid & 7, ty = tid >> 3;
    float acc[4][4] = {};
    for (int n0 = 0; n0 < NNODE; n0 += 16) {
#pragma unroll
        for (int r = 0; r < 2; r++) {
            int t4 = tid + r * 256;
            int kk = t4 >> 5, jf = (t4 & 31) << 2;
            *(float4*)&As[kk][jf] = *(const float4*)(A + (n0 + kk) * KAP + jf);
        }
        if (tid < 128) {
            int kk = tid >> 3, jf = (tid & 7) << 2;
            *(float4*)&Bs[kk][jf] = *(const float4*)(B + (n0 + kk) * HID + jf);
        }
        __syncthreads();
#pragma unroll
        for (int kk = 0; kk < 16; kk++) {
            float4 av = *(float4*)&As[kk][ty * 4];
            float4 bb = *(float4*)&Bs[kk][tx * 4];
            float a[4] = {av.x, av.y, av.z, av.w};
            float bv[4] = {bb.x, bb.y, bb.z, bb.w};
#pragma unroll
            for (int u = 0; u < 4; u++)
#pragma unroll
                for (int v = 0; v < 4; v++) acc[u][v] += a[u] * bv[v];
        }
        __syncthreads();
    }
#pragma unroll
    for (int u = 0; u < 4; u++) {
        int row = ty * 4 + u;
        if (row < KA)
            *(float4*)&C[(size_t)row * HID + tx * 4] =
                make_float4(acc[u][0], acc[u][1], acc[u][2], acc[u][3]);
    }
}

// ---------------------------------------------------------------------------
// stage-1 pooled softmax, 2 rows per iteration (shares W LDS between rows).
// ---------------------------------------------------------------------------
__global__ __launch_bounds__(256) void pool_softmax1_kernel(
    const float* __restrict__ X, const float* __restrict__ W,
    const float* __restrict__ bias, float* __restrict__ Sout) {
    __shared__ float Ws[HID * KAP];
    __shared__ float bs[KAP];
    int tid = threadIdx.x;
    for (int t = tid; t < HID * KAP; t += 256) {
        int c = t >> 7, k = t & 127;
        Ws[t] = (k < KA) ? W[c * KA + k] : 0.f;
    }
    if (tid < KAP) bs[tid] = (tid < KA) ? bias[tid] : 0.f;
    __syncthreads();
    int lane = tid & 31, warp = tid >> 5;
    int row0 = blockIdx.x * 64 + warp * 8;
    float b0v = bs[lane], b1v = bs[32 + lane], b2v = bs[64 + lane], b3v = bs[96 + lane];
#pragma unroll 1
    for (int r = 0; r < 8; r += 2) {
        int row = row0 + r;
        float xv0 = X[(size_t)row * HID + lane];
        float xv1 = X[(size_t)(row + 1) * HID + lane];
        float a0 = b0v, a1 = b1v, a2 = b2v, a3 = b3v;
        float c0 = b0v, c1 = b1v, c2 = b2v, c3 = b3v;
#pragma unroll
        for (int c = 0; c < HID; c++) {
            float bx0 = __shfl_sync(0xffffffffu, xv0, c);
            float bx1 = __shfl_sync(0xffffffffu, xv1, c);
            const float* wr = Ws + (c << 7) + lane;
            float w0 = wr[0], w1 = wr[32], w2 = wr[64], w3 = wr[96];
            a0 += bx0 * w0; a1 += bx0 * w1; a2 += bx0 * w2; a3 += bx0 * w3;
            c0 += bx1 * w0; c1 += bx1 * w1; c2 += bx1 * w2; c3 += bx1 * w3;
        }
        bool v3 = (96 + lane < KA);
        float e0 = __expf(a0), e1 = __expf(a1), e2 = __expf(a2);
        float e3 = v3 ? __expf(a3) : 0.f;
        float f0 = __expf(c0), f1 = __expf(c1), f2 = __expf(c2);
        float f3 = v3 ? __expf(c3) : 0.f;
        float s0 = (e0 + e1) + (e2 + e3);
        float s1 = (f0 + f1) + (f2 + f3);
#pragma unroll
        for (int o = 16; o; o >>= 1) {
            s0 += __shfl_xor_sync(0xffffffffu, s0, o);
            s1 += __shfl_xor_sync(0xffffffffu, s1, o);
        }
        float i0 = __frcp_rn(s0), i1 = __frcp_rn(s1);
        float* op0 = Sout + (size_t)row * KAP + lane;
        op0[0] = e0 * i0; op0[32] = e1 * i0; op0[64] = e2 * i0; op0[96] = e3 * i0;
        float* op1 = Sout + (size_t)(row + 1) * KAP + lane;
        op1[0] = f0 * i1; op1[32] = f1 * i1; op1[64] = f2 * i1; op1[96] = f3 * i1;
    }
}

// ---------------------------------------------------------------------------
__device__ __forceinline__ float blockReduce128(float v, float* sm) {
    int t = threadIdx.x;
    sm[t] = v;
    __syncthreads();
    for (int s = 64; s > 0; s >>= 1) {
        if (t < s) sm[t] += sm[t + s];
        __syncthreads();
    }
    float r = sm[0];
    __syncthreads();
    return r;
}

__global__ void loss_norm_kernel(const float* __restrict__ raw,
                                 const float* __restrict__ ss,
                                 const float* __restrict__ s,
                                 const float* __restrict__ dflat,
                                 float* __restrict__ adjn,
                                 float* __restrict__ dflat2,
                                 float* __restrict__ lossb,
                                 int k, int n, int ld, int ld_s, int bstride,
                                 int accum) {
    int b = blockIdx.x;
    raw  += (size_t)b * bstride;
    ss   += (size_t)b * bstride;
    s    += (size_t)b * n * ld_s;
    dflat+= (size_t)b * n;
    adjn += (size_t)b * k * k;
    dflat2 += (size_t)b * k;
    __shared__ float sm[128];
    __shared__ float idc[128];
    int tid = threadIdx.x;

    float v = 0.f;
    for (int i = tid; i < k; i += 128) v += raw[i * ld + i];
    float num = blockReduce128(v, sm);

    v = 0.f;
    for (int nn = tid; nn < n; nn += 128) {
        float dv = dflat[nn];
        float acc = 0.f;
        for (int kk = 0; kk < k; kk++) {
            float sv = s[(size_t)nn * ld_s + kk];
            acc += sv * sv;
        }
        v += acc * dv;
    }
    float den = blockReduce128(v, sm);

    v = 0.f;
    for (int i = tid; i < k; i += 128)
        for (int j = 0; j < k; j++) { float t = ss[i * ld + j]; v += t * t; }
    float nrm = sqrtf(blockReduce128(v, sm));

    float invn = 1.0f / nrm;
    float dk = rsqrtf((float)k);
    v = 0.f;
    for (int i = tid; i < k; i += 128)
        for (int j = 0; j < k; j++) {
            float t = ss[i * ld + j] * invn - ((i == j) ? dk : 0.f);
            v += t * t;
        }
    float ortho = sqrtf(blockReduce128(v, sm));

    for (int i = tid; i < k; i += 128) {
        float r = 0.f;
        for (int j = 0; j < k; j++) if (j != i) r += raw[i * ld + j];
        idc[i] = 1.0f / (sqrtf(r) + EPSV);
    }
    __syncthreads();
    for (int idx = tid; idx < k * k; idx += 128) {
        int i = idx / k, j = idx - i * k;
        adjn[idx] = (i == j) ? 0.f : raw[i * ld + j] * idc[i] * idc[j];
    }
    for (int i = tid; i < k; i += 128) {
        float r = 0.f;
        for (int j = 0; j < k; j++) if (j != i) r += raw[i * ld + j] * idc[j];
        dflat2[i] = r * idc[i];
    }
    if (tid == 0) {
        float val = -num / den + ortho;
        if (accum) lossb[b] += val; else lossb[b] = val;
    }
}

// ---------------------------------------------------------------------------
__global__ __launch_bounds__(256) void stage2_conv_kernel(
    const float* __restrict__ adj1, const float* __restrict__ x1,
    const float* __restrict__ relW, const float* __restrict__ relb,
    const float* __restrict__ rootW,
    const float* __restrict__ p2W, const float* __restrict__ p2b,
    float* __restrict__ x2, float* __restrict__ s2) {
    extern __shared__ float sm[];
    float* adj1s = sm;
    float* x1s   = sm + 10000;
    float* relWs = sm + 13200;
    float* rootWs= sm + 14224;
    float* p2Ws  = sm + 15248;
    int b = blockIdx.x, tid = threadIdx.x;
    const float* A = adj1 + (size_t)b * KA * KA;
    const float* X = x1 + (size_t)b * KA * HID;
    for (int i = tid; i < KA * KA; i += 256) adj1s[i] = A[i];
    for (int i = tid; i < KA * HID; i += 256) x1s[i] = X[i];
    for (int i = tid; i < HID * HID; i += 256) { relWs[i] = relW[i]; rootWs[i] = rootW[i]; }
    for (int i = tid; i < HID * KB; i += 256) p2Ws[i] = p2W[i];
    __syncthreads();
    int lane = tid & 31, warp = tid >> 5;
    float rb = relb[lane];
    int kk10 = lane < KB ? lane : 0;
    float p2bv = p2b[kk10];
    for (int i = warp; i < KA; i += 8) {
        float t2 = 0.f;
        const float* ar = adj1s + i * KA;
        for (int m = 0; m < KA; m++) t2 += ar[m] * x1s[(m << 5) + lane];
        float x1v = x1s[(i << 5) + lane];
        float a = rb;
#pragma unroll
        for (int k = 0; k < 32; k++)
            a += __shfl_sync(0xffffffffu, t2, k) * relWs[(k << 5) + lane]
               + __shfl_sync(0xffffffffu, x1v, k) * rootWs[(k << 5) + lane];
        float x2v = fmaxf(a, 0.f);
        x2[((size_t)b * KA + i) * HID + lane] = x2v;
        float zz = p2bv;
#pragma unroll
        for (int c = 0; c < 32; c++)
            zz += __shfl_sync(0xffffffffu, x2v, c) * p2Ws[c * KB + kk10];
        float e = (lane < KB) ? __expf(zz) : 0.f;
        float ssum = e;
#pragma unroll
        for (int o = 16; o; o >>= 1) ssum += __shfl_xor_sync(0xffffffffu, ssum, o);
        if (lane < KB) s2[((size_t)b * KA + i) * KB + lane] = e / ssum;
    }
}

// ---------------------------------------------------------------------------
__global__ __launch_bounds__(256) void stage2b_kernel(
    const float* __restrict__ adj1, const float* __restrict__ s2,
    const float* __restrict__ x2,
    float* __restrict__ adjr2, float* __restrict__ ss2, float* __restrict__ x3) {
    extern __shared__ float sm[];
    float* adj1s = sm;
    float* s2s   = sm + 10000;
    float* x2s   = sm + 11000;
    float* tt2s  = sm + 14200;
    int b = blockIdx.x, tid = threadIdx.x;
    const float* A = adj1 + (size_t)b * KA * KA;
    const float* S2 = s2 + (size_t)b * KA * KB;
    const float* X2 = x2 + (size_t)b * KA * HID;
    for (int i = tid; i < KA * KA; i += 256) adj1s[i] = A[i];
    for (int i = tid; i < KA * KB; i += 256) s2s[i] = S2[i];
    for (int i = tid; i < KA * HID; i += 256) x2s[i] = X2[i];
    __syncthreads();
    for (int t = tid; t < KA * KB; t += 256) {
        int i = t / KB, k = t - i * KB;
        float a = 0.f;
        const float* ar = adj1s + i * KA;
        for (int m = 0; m < KA; m++) a += ar[m] * s2s[m * KB + k];
        tt2s[t] = a;
    }
    __syncthreads();
    for (int t = tid; t < 520; t += 256) {
        if (t < 100) {
            int i = t / 10, j = t - i * 10;
            float a = 0.f;
            for (int n = 0; n < KA; n++) a += s2s[n * KB + i] * tt2s[n * KB + j];
            adjr2[(size_t)b * 100 + t] = a;
        } else if (t < 200) {
            int u = t - 100;
            int i = u / 10, j = u - i * 10;
            float a = 0.f;
            for (int n = 0; n < KA; n++) a += s2s[n * KB + i] * s2s[n * KB + j];
            ss2[(size_t)b * 100 + u] = a;
        } else {
            int u = t - 200;
            int i = u >> 5, c = u & 31;
            float a = 0.f;
            for (int n = 0; n < KA; n++) a += s2s[n * KB + i] * x2s[(n << 5) + c];
            x3[(size_t)b * 320 + u] = a;
        }
    }
}

// ---------------------------------------------------------------------------
__global__ void tail_kernel(const float* __restrict__ adj2, const float* __restrict__ x3,
                            const float* __restrict__ c3rW, const float* __restrict__ c3rb,
                            const float* __restrict__ c3oW,
                            const float* __restrict__ l1W, const float* __restrict__ l1b,
                            const float* __restrict__ l2W, const float* __restrict__ l2b,
                            float* __restrict__ out) {
    int b = blockIdx.x, lane = threadIdx.x;
    const float* A2 = adj2 + (size_t)b * 100;
    const float* X3 = x3 + (size_t)b * 320;
    float x3c[10], t3c[10];
#pragma unroll
    for (int j = 0; j < 10; j++) x3c[j] = X3[j * 32 + lane];
#pragma unroll
    for (int i = 0; i < 10; i++) {
        float a = 0.f;
#pragma unroll
        for (int j = 0; j < 10; j++) a += A2[i * 10 + j] * x3c[j];
        t3c[i] = a;
    }
    float rb = c3rb[lane];
    float g = 0.f;
#pragma unroll
    for (int i = 0; i < 10; i++) {
        float a = rb;
#pragma unroll
        for (int k = 0; k < 32; k++)
            a += __shfl_sync(0xffffffffu, t3c[i], k) * c3rW[k * 32 + lane]
               + __shfl_sync(0xffffffffu, x3c[i], k) * c3oW[k * 32 + lane];
        g += a;
    }
    g *= 0.1f;
    float a1 = l1b[lane];
#pragma unroll
    for (int k = 0; k < 32; k++) a1 += __shfl_sync(0xffffffffu, g, k) * l1W[k * 32 + lane];
    float gg = fmaxf(a1, 0.f);
    int kk = lane < OC ? lane : 0;
    float a2 = l2b[kk];
#pragma unroll
    for (int k = 0; k < 32; k++) a2 += __shfl_sync(0xffffffffu, gg, k) * l2W[k * OC + kk];
    float val = (lane < OC) ? a2 : -INFINITY;
    float m = val;
#pragma unroll
    for (int o = 16; o; o >>= 1) m = fmaxf(m, __shfl_xor_sync(0xffffffffu, m, o));
    float e = (lane < OC) ? __expf(val - m) : 0.f;
    float ssum = e;
#pragma unroll
    for (int o = 16; o; o >>= 1) ssum += __shfl_xor_sync(0xffffffffu, ssum, o);
    if (lane < OC) out[b * OC + lane] = val - m - logf(ssum);
}

__global__ void final_kernel(const float* __restrict__ lossb, float* __restrict__ out,
                             int out_size) {
    __shared__ float sm[128];
    int t = threadIdx.x;
    sm[t] = lossb[t];
    __syncthreads();
    for (int s = 64; s > 0; s >>= 1) {
        if (t < s) sm[t] += sm[t + s];
        __syncthreads();
    }
    if (t == 0 && out_size > BATCH * OC) out[BATCH * OC] = sm[0] / (float)BATCH;
}

// ---------------------------------------------------------------------------
extern "C" void kernel_launch(void* const* d_in, const int* in_sizes, int n_in,
                              void* d_out, int out_size) {
    const float* x    = (const float*)d_in[0];
    const int*   ei   = (const int*)  d_in[1];
    const float* c1W  = (const float*)d_in[3];
    const float* c1b  = (const float*)d_in[4];
    const float* p1W  = (const float*)d_in[5];
    const float* p1b  = (const float*)d_in[6];
    const float* c2rW = (const float*)d_in[7];
    const float* c2rb = (const float*)d_in[8];
    const float* c2oW = (const float*)d_in[9];
    const float* p2W  = (const float*)d_in[10];
    const float* p2b  = (const float*)d_in[11];
    const float* c3rW = (const float*)d_in[12];
    const float* c3rb = (const float*)d_in[13];
    const float* c3oW = (const float*)d_in[14];
    const float* l1W  = (const float*)d_in[15];
    const float* l1b  = (const float*)d_in[16];
    const float* l2W  = (const float*)d_in[17];
    const float* l2b  = (const float*)d_in[18];
    float* out = (float*)d_out;
    int E = in_sizes[1] / 2;
    int eper = E / BATCH;

    void* sp = nullptr;
    cudaGetSymbolAddress(&sp, g_scratch);
    float* S = (float*)sp;
    int *csn, *cdn, *osn, *odn, *lsrc, *ldst;
    cudaGetSymbolAddress((void**)&csn, g_cnt_src);
    cudaGetSymbolAddress((void**)&cdn, g_cnt_dst);
    cudaGetSymbolAddress((void**)&osn, g_off_src);
    cudaGetSymbolAddress((void**)&odn, g_off_dst);
    cudaGetSymbolAddress((void**)&lsrc, g_list_src);
    cudaGetSymbolAddress((void**)&ldst, g_list_dst);

    cudaFuncSetAttribute(stage2_conv_kernel, cudaFuncAttributeMaxDynamicSharedMemorySize, 62272);
    cudaFuncSetAttribute(stage2b_kernel, cudaFuncAttributeMaxDynamicSharedMemorySize, 60800);

    build_csr_kernel<<<BATCH, 512>>>(ei, E, eper, osn, csn, odn, cdn, lsrc, ldst,
                                     S + OFF_DEG, S + OFF_DFLAT);
    xwp_kernel<<<TOT / 8, dim3(32, 8)>>>(x, c1W, S + OFF_DEG, S + OFF_XWP);
    agg_gather_kernel<<<TOT * 32 / 256, 256>>>(odn, cdn, ldst, S + OFF_XWP,
                                               S + OFF_DEG, c1b, S + OFF_H);
    pool_softmax1_kernel<<<TOT / 64, 256>>>(S + OFF_H, p1W, p1b, S + OFF_S1);
    t1_gather_kernel<<<TOT * 32 / 256, 256>>>(osn, csn, lsrc, S + OFF_S1, S + OFF_T1);
    { dim3 g(2, BATCH); atb8_128_kernel<<<g, 256>>>(S + OFF_S1, S + OFF_T1, S + OFF_ADJR1, S + OFF_SS1); }
    atb8_32_kernel<<<BATCH, 256>>>(S + OFF_S1, S + OFF_H, S + OFF_X1);
    loss_norm_kernel<<<BATCH, 128>>>(S + OFF_ADJR1, S + OFF_SS1, S + OFF_S1, S + OFF_DFLAT,
                                     S + OFF_ADJ1, S + OFF_DFLAT2, S + OFF_LOSSB,
                                     KA, NNODE, KAP, KAP, KAP * KAP, 0);
    stage2_conv_kernel<<<BATCH, 256, 62272>>>(S + OFF_ADJ1, S + OFF_X1, c2rW, c2rb, c2oW,
                                              p2W, p2b, S + OFF_X2, S + OFF_S2);
    stage2b_kernel<<<BATCH, 256, 60800>>>(S + OFF_ADJ1, S + OFF_S2, S + OFF_X2,
                                          S + OFF_ADJR2, S + OFF_SS2, S + OFF_X3);
    loss_norm_kernel<<<BATCH, 128>>>(S + OFF_ADJR2, S + OFF_SS2, S + OFF_S2, S + OFF_DFLAT2,
                                     S + OFF_ADJ2, S + OFF_DUMMY, S + OFF_LOSSB,
                                     KB, KA, KB, KB, KB * KB, 1);
    tail_kernel<<<BATCH, 32>>>(S + OFF_ADJ2, S + OFF_X3, c3rW, c3rb, c3oW,
                               l1W, l1b, l2W, l2b, out);
    final_kernel<<<1, 128>>>(S + OFF_LOSSB, out, out_size);
}

// round 12
// speedup vs baseline: 1.1629x; 1.0769x over previous
#include <cuda_runtime.h>
#include <math.h>
#include <stdint.h>

namespace {
constexpr int BATCH = 128, NNODE = 512, INC = 128, HID = 32, KA = 100, KB = 10, OC = 10;
constexpr int KAP = 128;
constexpr int TOT = BATCH * NNODE;
constexpr int MAXE = BATCH * 8192;
constexpr float EPSV = 1e-15f;

constexpr size_t OFF_DEG    = 0;
constexpr size_t OFF_DFLAT  = OFF_DEG + TOT;
constexpr size_t OFF_LOSSB  = OFF_DFLAT + TOT;
constexpr size_t OFF_XWP    = OFF_LOSSB + BATCH;
constexpr size_t OFF_H      = OFF_XWP   + (size_t)TOT * HID;
constexpr size_t OFF_S1     = OFF_H     + (size_t)TOT * HID;
constexpr size_t OFF_T1     = OFF_S1    + (size_t)TOT * KAP;
constexpr size_t OFF_ADJR1  = OFF_T1    + (size_t)TOT * KAP;
constexpr size_t OFF_SS1    = OFF_ADJR1 + (size_t)BATCH * KAP * KAP;
constexpr size_t OFF_X1     = OFF_SS1   + (size_t)BATCH * KAP * KAP;
constexpr size_t OFF_ADJ1   = OFF_X1    + (size_t)BATCH * KA * HID;
constexpr size_t OFF_DFLAT2 = OFF_ADJ1  + (size_t)BATCH * KA * KA;
constexpr size_t OFF_DUMMY  = OFF_DFLAT2+ (size_t)BATCH * KA;
constexpr size_t OFF_X2     = OFF_DUMMY + (size_t)BATCH * KB;
constexpr size_t OFF_S2     = OFF_X2    + (size_t)BATCH * KA * HID;
constexpr size_t OFF_ADJR2  = OFF_S2    + (size_t)BATCH * KA * KB;
constexpr size_t OFF_SS2    = OFF_ADJR2 + (size_t)BATCH * KB * KB;
constexpr size_t OFF_X3     = OFF_SS2   + (size_t)BATCH * KB * KB;
constexpr size_t OFF_ADJ2   = OFF_X3    + (size_t)BATCH * KB * HID;
constexpr size_t SCRATCH_TOTAL = OFF_ADJ2 + (size_t)BATCH * KB * KB;
}  // namespace

__device__ __align__(16) float g_scratch[SCRATCH_TOTAL];
__device__ __align__(16) int g_cnt_src[TOT];
__device__ __align__(16) int g_cnt_dst[TOT];
__device__ __align__(16) int g_off_src[TOT];
__device__ __align__(16) int g_off_dst[TOT];
__device__ __align__(16) int g_list_src[MAXE];
__device__ __align__(16) int g_list_dst[MAXE];

// ---------------------------------------------------------------------------
// Fused CSR build
// ---------------------------------------------------------------------------
__global__ __launch_bounds__(512) void build_csr_kernel(
    const int* __restrict__ ei, int E, int eper,
    int* __restrict__ off_src, int* __restrict__ cnt_src,
    int* __restrict__ off_dst, int* __restrict__ cnt_dst,
    int* __restrict__ list_src, int* __restrict__ list_dst,
    float* __restrict__ deg, float* __restrict__ dflat) {
    __shared__ int sc[512], sd[512], sscan[512];
    __shared__ int csrc[512], cdst[512];
    int b = blockIdx.x, tid = threadIdx.x;
    sc[tid] = 0; sd[tid] = 0;
    __syncthreads();
    const int* se = ei + (size_t)b * eper;
    const int* de = ei + E + (size_t)b * eper;
    for (int e = tid; e < eper; e += 512) {
        atomicAdd(&sc[se[e] & 511], 1);
        atomicAdd(&sd[de[e] & 511], 1);
    }
    __syncthreads();
    int vs = sc[tid], vd = sd[tid];
    int g = (b << 9) + tid;
    int base = b * eper;
    dflat[g] = (float)vs;
    deg[g]   = (float)vd;
    cnt_src[g] = vs;
    cnt_dst[g] = vd;
    sscan[tid] = vs; __syncthreads();
    for (int o = 1; o < 512; o <<= 1) {
        int t = (tid >= o) ? sscan[tid - o] : 0;
        __syncthreads(); sscan[tid] += t; __syncthreads();
    }
    int es = base + sscan[tid] - vs;
    off_src[g] = es; csrc[tid] = es;
    __syncthreads();
    sscan[tid] = vd; __syncthreads();
    for (int o = 1; o < 512; o <<= 1) {
        int t = (tid >= o) ? sscan[tid - o] : 0;
        __syncthreads(); sscan[tid] += t; __syncthreads();
    }
    int ed = base + sscan[tid] - vd;
    off_dst[g] = ed; cdst[tid] = ed;
    __syncthreads();
    for (int e = tid; e < eper; e += 512) {
        int s = se[e] & 511, d = de[e] & 511;
        int p = atomicAdd(&csrc[s], 1);
        list_src[p] = d;
        int q = atomicAdd(&cdst[d], 1);
        list_dst[q] = s;
    }
}

// ---------------------------------------------------------------------------
__global__ __launch_bounds__(256) void xwp_kernel(const float* __restrict__ x,
                                                  const float* __restrict__ W,
                                                  const float* __restrict__ deg,
                                                  float* __restrict__ xwp) {
    __shared__ float Ws[INC * HID];
    __shared__ float xs[8][INC];
    int tid = threadIdx.y * 32 + threadIdx.x;
    for (int t = tid; t < INC * HID; t += 256) Ws[t] = W[t];
    int r0 = blockIdx.x * 8;
    for (int t = tid; t < 8 * INC; t += 256) {
        int r = t >> 7, k = t & 127;
        xs[r][k] = x[(size_t)(r0 + r) * INC + k];
    }
    __syncthreads();
    int c = threadIdx.x, r = threadIdx.y;
    float acc = 0.f;
#pragma unroll 8
    for (int k = 0; k < INC; k++) acc += xs[r][k] * Ws[k * HID + c];
    int g = r0 + r;
    float dis = rsqrtf(deg[g] + 1.0f);
    xwp[(size_t)g * HID + c] = dis * acc;
}

// ---------------------------------------------------------------------------
__global__ __launch_bounds__(256) void agg_gather_kernel(
    const int* __restrict__ off_dst, const int* __restrict__ cnt_dst,
    const int* __restrict__ list_dst,
    const float* __restrict__ xwp, const float* __restrict__ deg,
    const float* __restrict__ bias, float* __restrict__ h) {
    int node = (blockIdx.x * blockDim.x + threadIdx.x) >> 5;
    int lane = threadIdx.x & 31;
    if (node >= TOT) return;
    int b = node >> 9;
    const float* xb = xwp + (((size_t)b << 9) << 5);
    int off = off_dst[node], cnt = cnt_dst[node];
    float acc = 0.f;
    int i = off, end = off + cnt;
    for (; i + 3 < end; i += 4) {
        int s0 = __ldg(&list_dst[i]),   s1 = __ldg(&list_dst[i + 1]);
        int s2 = __ldg(&list_dst[i + 2]), s3 = __ldg(&list_dst[i + 3]);
        acc += xb[(s0 << 5) + lane] + xb[(s1 << 5) + lane]
             + xb[(s2 << 5) + lane] + xb[(s3 << 5) + lane];
    }
    for (; i < end; i++) acc += xb[(__ldg(&list_dst[i]) << 5) + lane];
    float dis = rsqrtf(deg[node] + 1.0f);
    float xv = xwp[((size_t)node << 5) + lane];
    h[((size_t)node << 5) + lane] = fmaxf(dis * (acc + xv) + bias[lane], 0.f);
}

// ---------------------------------------------------------------------------
__global__ __launch_bounds__(256) void t1_gather_kernel(
    const int* __restrict__ off_src, const int* __restrict__ cnt_src,
    const int* __restrict__ list_src,
    const float* __restrict__ s1p, float* __restrict__ T1) {
    int node = (blockIdx.x * blockDim.x + threadIdx.x) >> 5;
    int lane = threadIdx.x & 31;
    if (node >= TOT) return;
    int b = node >> 9;
    const float4* sb = (const float4*)(s1p + (((size_t)b << 9) << 7)) + lane;
    int off = off_src[node], cnt = cnt_src[node];
    float4 acc = make_float4(0, 0, 0, 0);
    int i = off, end = off + cnt;
    for (; i + 3 < end; i += 4) {
        int d0 = __ldg(&list_src[i]),     d1 = __ldg(&list_src[i + 1]);
        int d2 = __ldg(&list_src[i + 2]), d3 = __ldg(&list_src[i + 3]);
        float4 v0 = __ldg(&sb[d0 << 5]);
        float4 v1 = __ldg(&sb[d1 << 5]);
        float4 v2 = __ldg(&sb[d2 << 5]);
        float4 v3 = __ldg(&sb[d3 << 5]);
        acc.x += (v0.x + v1.x) + (v2.x + v3.x);
        acc.y += (v0.y + v1.y) + (v2.y + v3.y);
        acc.z += (v0.z + v1.z) + (v2.z + v3.z);
        acc.w += (v0.w + v1.w) + (v2.w + v3.w);
    }
    for (; i < end; i++) {
        float4 v = __ldg(&sb[__ldg(&list_src[i]) << 5]);
        acc.x += v.x; acc.y += v.y; acc.z += v.z; acc.w += v.w;
    }
    ((float4*)(T1 + ((size_t)node << 7)))[lane] = acc;
}

// ---------------------------------------------------------------------------
// Fused Gram kernel: one block per graph, 288 threads.
//   threads 0..168   : adjr1 = s1^T T1, 13x13 grid of 8x8 micro-blocks (KA=100<=104)
//   threads 169..259 : ss1 = s1^T s1 upper triangle (91 blocks), mirrored on write
//   threads 260..287 : idle (sync only)
// ---------------------------------------------------------------------------
__global__ __launch_bounds__(288) void gram_fused_kernel(
    const float* __restrict__ s1p, const float* __restrict__ T1,
    float* __restrict__ adjr1, float* __restrict__ ss1) {
    __shared__ float As[2][16][128];
    __shared__ float Bs[2][16][128];
    int b = blockIdx.x;
    const float* A = s1p + ((size_t)b << 16);
    const float* B = T1 + ((size_t)b << 16);
    int tid = threadIdx.x;

    // micro-block mapping
    int sel, r, c;
    if (tid < 169) {
        sel = 0; r = tid / 13; c = tid - r * 13;
    } else if (tid < 260) {
        int u = tid - 169;
        // row boundaries of the upper triangle are FIXED: 13, 25, 36, 46, ...
        // accumulate nb unconditionally; advance (rr, base) when u passes.
        int rr = 0, base = 0, nb = 13;
#pragma unroll
        for (int q = 0; q < 12; q++) {
            if (u >= nb) { rr = q + 1; base = nb; }
            nb += 12 - q;
        }
        sel = 1; r = rr; c = rr + (u - base);
    } else {
        sel = 2; r = 0; c = 0;
    }

    bool loader = tid < 256;
    int lk0 = tid >> 5,         lj0 = (tid & 31) << 2;
    int lk1 = (tid + 256) >> 5, lj1 = ((tid + 256) & 31) << 2;

    float4 pa0, pa1, pb0, pb1;
    if (loader) {
        pa0 = *(const float4*)(A + lk0 * KAP + lj0);
        pa1 = *(const float4*)(A + lk1 * KAP + lj1);
        pb0 = *(const float4*)(B + lk0 * KAP + lj0);
        pb1 = *(const float4*)(B + lk1 * KAP + lj1);
        *(float4*)&As[0][lk0][lj0] = pa0;
        *(float4*)&As[0][lk1][lj1] = pa1;
        *(float4*)&Bs[0][lk0][lj0] = pb0;
        *(float4*)&Bs[0][lk1][lj1] = pb1;
    }
    __syncthreads();

    float acc[8][8] = {};
    int cur = 0;
    for (int n0 = 0; n0 < NNODE; n0 += 16) {
        int nn = n0 + 16;
        if (loader && nn < NNODE) {
            pa0 = *(const float4*)(A + (nn + lk0) * KAP + lj0);
            pa1 = *(const float4*)(A + (nn + lk1) * KAP + lj1);
            pb0 = *(const float4*)(B + (nn + lk0) * KAP + lj0);
            pb1 = *(const float4*)(B + (nn + lk1) * KAP + lj1);
        }
        if (sel != 2) {
            const float (*pA)[128] = As[cur];
            const float (*pB)[128] = (sel == 1) ? As[cur] : Bs[cur];
#pragma unroll
            for (int kk = 0; kk < 16; kk++) {
                float4 a0 = *(const float4*)&pA[kk][r * 8];
                float4 a1 = *(const float4*)&pA[kk][r * 8 + 4];
                float4 b0 = *(const float4*)&pB[kk][c * 8];
                float4 b1 = *(const float4*)&pB[kk][c * 8 + 4];
                float a[8] = {a0.x, a0.y, a0.z, a0.w, a1.x, a1.y, a1.z, a1.w};
                float bv[8] = {b0.x, b0.y, b0.z, b0.w, b1.x, b1.y, b1.z, b1.w};
#pragma unroll
                for (int u = 0; u < 8; u++)
#pragma unroll
                    for (int v = 0; v < 8; v++) acc[u][v] += a[u] * bv[v];
            }
        }
        if (nn < NNODE) {
            int nx = cur ^ 1;
            if (loader) {
                *(float4*)&As[nx][lk0][lj0] = pa0;
                *(float4*)&As[nx][lk1][lj1] = pa1;
                *(float4*)&Bs[nx][lk0][lj0] = pb0;
                *(float4*)&Bs[nx][lk1][lj1] = pb1;
            }
            __syncthreads();
            cur = nx;
        }
    }

    if (sel == 0) {
        float* C = adjr1 + ((size_t)b << 14);
#pragma unroll
        for (int u = 0; u < 8; u++) {
            *(float4*)&C[(size_t)(r * 8 + u) * KAP + c * 8] =
                make_float4(acc[u][0], acc[u][1], acc[u][2], acc[u][3]);
            *(float4*)&C[(size_t)(r * 8 + u) * KAP + c * 8 + 4] =
                make_float4(acc[u][4], acc[u][5], acc[u][6], acc[u][7]);
        }
    } else if (sel == 1) {
        float* C = ss1 + ((size_t)b << 14);
#pragma unroll
        for (int u = 0; u < 8; u++) {
            *(float4*)&C[(size_t)(r * 8 + u) * KAP + c * 8] =
                make_float4(acc[u][0], acc[u][1], acc[u][2], acc[u][3]);
            *(float4*)&C[(size_t)(r * 8 + u) * KAP + c * 8 + 4] =
                make_float4(acc[u][4], acc[u][5], acc[u][6], acc[u][7]);
        }
        if (r != c) {
#pragma unroll
            for (int v = 0; v < 8; v++)
#pragma unroll
                for (int u = 0; u < 8; u++)
                    C[(size_t)(c * 8 + v) * KAP + r * 8 + u] = acc[u][v];
        }
    }
}

// ---------------------------------------------------------------------------
__global__ __launch_bounds__(256) void atb8_32_kernel(const float* __restrict__ s1p,
                                                      const float* __restrict__ h,
                                                      float* __restrict__ x1) {
    __shared__ float As[16][128];
    __shared__ float Bs[16][32];
    int b = blockIdx.x;
    const float* A = s1p + ((size_t)b << 9) * KAP;
    const float* B = h + ((size_t)b << 9) * HID;
    float* C = x1 + (size_t)b * KA * HID;
    int tid = threadIdx.x;
    int tx = tid & 7, ty = tid >> 3;
    float acc[4][4] = {};
    for (int n0 = 0; n0 < NNODE; n0 += 16) {
#pragma unroll
        for (int r = 0; r < 2; r++) {
            int t4 = tid + r * 256;
            int kk = t4 >> 5, jf = (t4 & 31) << 2;
            *(float4*)&As[kk][jf] = *(const float4*)(A + (n0 + kk) * KAP + jf);
        }
        if (tid < 128) {
            int kk = tid >> 3, jf = (tid & 7) << 2;
            *(float4*)&Bs[kk][jf] = *(const float4*)(B + (n0 + kk) * HID + jf);
        }
        __syncthreads();
#pragma unroll
        for (int kk = 0; kk < 16; kk++) {
            float4 av = *(float4*)&As[kk][ty * 4];
            float4 bb = *(float4*)&Bs[kk][tx * 4];
            float a[4] = {av.x, av.y, av.z, av.w};
            float bv[4] = {bb.x, bb.y, bb.z, bb.w};
#pragma unroll
            for (int u = 0; u < 4; u++)
#pragma unroll
                for (int v = 0; v < 4; v++) acc[u][v] += a[u] * bv[v];
        }
        __syncthreads();
    }
#pragma unroll
    for (int u = 0; u < 4; u++) {
        int row = ty * 4 + u;
        if (row < KA)
            *(float4*)&C[(size_t)row * HID + tx * 4] =
                make_float4(acc[u][0], acc[u][1], acc[u][2], acc[u][3]);
    }
}

// ---------------------------------------------------------------------------
// stage-1 pooled softmax, 2 rows per iteration (shares W LDS between rows).
// ---------------------------------------------------------------------------
__global__ __launch_bounds__(256) void pool_softmax1_kernel(
    const float* __restrict__ X, const float* __restrict__ W,
    const float* __restrict__ bias, float* __restrict__ Sout) {
    __shared__ float Ws[HID * KAP];
    __shared__ float bs[KAP];
    int tid = threadIdx.x;
    for (int t = tid; t < HID * KAP; t += 256) {
        int c = t >> 7, k = t & 127;
        Ws[t] = (k < KA) ? W[c * KA + k] : 0.f;
    }
    if (tid < KAP) bs[tid] = (tid < KA) ? bias[tid] : 0.f;
    __syncthreads();
    int lane = tid & 31, warp = tid >> 5;
    int row0 = blockIdx.x * 64 + warp * 8;
    float b0v = bs[lane], b1v = bs[32 + lane], b2v = bs[64 + lane], b3v = bs[96 + lane];
#pragma unroll 1
    for (int r = 0; r < 8; r += 2) {
        int row = row0 + r;
        float xv0 = X[(size_t)row * HID + lane];
        float xv1 = X[(size_t)(row + 1) * HID + lane];
        float a0 = b0v, a1 = b1v, a2 = b2v, a3 = b3v;
        float c0 = b0v, c1 = b1v, c2 = b2v, c3 = b3v;
#pragma unroll
        for (int c = 0; c < HID; c++) {
            float bx0 = __shfl_sync(0xffffffffu, xv0, c);
            float bx1 = __shfl_sync(0xffffffffu, xv1, c);
            const float* wr = Ws + (c << 7) + lane;
            float w0 = wr[0], w1 = wr[32], w2 = wr[64], w3 = wr[96];
            a0 += bx0 * w0; a1 += bx0 * w1; a2 += bx0 * w2; a3 += bx0 * w3;
            c0 += bx1 * w0; c1 += bx1 * w1; c2 += bx1 * w2; c3 += bx1 * w3;
        }
        bool v3 = (96 + lane < KA);
        float e0 = __expf(a0), e1 = __expf(a1), e2 = __expf(a2);
        float e3 = v3 ? __expf(a3) : 0.f;
        float f0 = __expf(c0), f1 = __expf(c1), f2 = __expf(c2);
        float f3 = v3 ? __expf(c3) : 0.f;
        float s0 = (e0 + e1) + (e2 + e3);
        float s1 = (f0 + f1) + (f2 + f3);
#pragma unroll
        for (int o = 16; o; o >>= 1) {
            s0 += __shfl_xor_sync(0xffffffffu, s0, o);
            s1 += __shfl_xor_sync(0xffffffffu, s1, o);
        }
        float i0 = __frcp_rn(s0), i1 = __frcp_rn(s1);
        float* op0 = Sout + (size_t)row * KAP + lane;
        op0[0] = e0 * i0; op0[32] = e1 * i0; op0[64] = e2 * i0; op0[96] = e3 * i0;
        float* op1 = Sout + (size_t)(row + 1) * KAP + lane;
        op1[0] = f0 * i1; op1[32] = f1 * i1; op1[64] = f2 * i1; op1[96] = f3 * i1;
    }
}

// ---------------------------------------------------------------------------
__device__ __forceinline__ float blockReduce128(float v, float* sm) {
    int t = threadIdx.x;
    sm[t] = v;
    __syncthreads();
    for (int s = 64; s > 0; s >>= 1) {
        if (t < s) sm[t] += sm[t + s];
        __syncthreads();
    }
    float r = sm[0];
    __syncthreads();
    return r;
}

__global__ void loss_norm_kernel(const float* __restrict__ raw,
                                 const float* __restrict__ ss,
                                 const float* __restrict__ s,
                                 const float* __restrict__ dflat,
                                 float* __restrict__ adjn,
                                 float* __restrict__ dflat2,
                                 float* __restrict__ lossb,
                                 int k, int n, int ld, int ld_s, int bstride,
                                 int accum) {
    int b = blockIdx.x;
    raw  += (size_t)b * bstride;
    ss   += (size_t)b * bstride;
    s    += (size_t)b * n * ld_s;
    dflat+= (size_t)b * n;
    adjn += (size_t)b * k * k;
    dflat2 += (size_t)b * k;
    __shared__ float sm[128];
    __shared__ float idc[128];
    int tid = threadIdx.x;

    float v = 0.f;
    for (int i = tid; i < k; i += 128) v += raw[i * ld + i];
    float num = blockReduce128(v, sm);

    v = 0.f;
    for (int nn = tid; nn < n; nn += 128) {
        float dv = dflat[nn];
        float acc = 0.f;
        for (int kk = 0; kk < k; kk++) {
            float sv = s[(size_t)nn * ld_s + kk];
            acc += sv * sv;
        }
        v += acc * dv;
    }
    float den = blockReduce128(v, sm);

    v = 0.f;
    for (int i = tid; i < k; i += 128)
        for (int j = 0; j < k; j++) { float t = ss[i * ld + j]; v += t * t; }
    float nrm = sqrtf(blockReduce128(v, sm));

    float invn = 1.0f / nrm;
    float dk = rsqrtf((float)k);
    v = 0.f;
    for (int i = tid; i < k; i += 128)
        for (int j = 0; j < k; j++) {
            float t = ss[i * ld + j] * invn - ((i == j) ? dk : 0.f);
            v += t * t;
        }
    float ortho = sqrtf(blockReduce128(v, sm));

    for (int i = tid; i < k; i += 128) {
        float r = 0.f;
        for (int j = 0; j < k; j++) if (j != i) r += raw[i * ld + j];
        idc[i] = 1.0f / (sqrtf(r) + EPSV);
    }
    __syncthreads();
    for (int idx = tid; idx < k * k; idx += 128) {
        int i = idx / k, j = idx - i * k;
        adjn[idx] = (i == j) ? 0.f : raw[i * ld + j] * idc[i] * idc[j];
    }
    for (int i = tid; i < k; i += 128) {
        float r = 0.f;
        for (int j = 0; j < k; j++) if (j != i) r += raw[i * ld + j] * idc[j];
        dflat2[i] = r * idc[i];
    }
    if (tid == 0) {
        float val = -num / den + ortho;
        if (accum) lossb[b] += val; else lossb[b] = val;
    }
}

// ---------------------------------------------------------------------------
__global__ __launch_bounds__(256) void stage2_conv_kernel(
    const float* __restrict__ adj1, const float* __restrict__ x1,
    const float* __restrict__ relW, const float* __restrict__ relb,
    const float* __restrict__ rootW,
    const float* __restrict__ p2W, const float* __restrict__ p2b,
    float* __restrict__ x2, float* __restrict__ s2) {
    extern __shared__ float sm[];
    float* adj1s = sm;
    float* x1s   = sm + 10000;
    float* relWs = sm + 13200;
    float* rootWs= sm + 14224;
    float* p2Ws  = sm + 15248;
    int b = blockIdx.x, tid = threadIdx.x;
    const float* A = adj1 + (size_t)b * KA * KA;
    const float* X = x1 + (size_t)b * KA * HID;
    for (int i = tid; i < KA * KA; i += 256) adj1s[i] = A[i];
    for (int i = tid; i < KA * HID; i += 256) x1s[i] = X[i];
    for (int i = tid; i < HID * HID; i += 256) { relWs[i] = relW[i]; rootWs[i] = rootW[i]; }
    for (int i = tid; i < HID * KB; i += 256) p2Ws[i] = p2W[i];
    __syncthreads();
    int lane = tid & 31, warp = tid >> 5;
    float rb = relb[lane];
    int kk10 = lane < KB ? lane : 0;
    float p2bv = p2b[kk10];
    for (int i = warp; i < KA; i += 8) {
        float t2 = 0.f;
        const float* ar = adj1s + i * KA;
        for (int m = 0; m < KA; m++) t2 += ar[m] * x1s[(m << 5) + lane];
        float x1v = x1s[(i << 5) + lane];
        float a = rb;
#pragma unroll
        for (int k = 0; k < 32; k++)
            a += __shfl_sync(0xffffffffu, t2, k) * relWs[(k << 5) + lane]
               + __shfl_sync(0xffffffffu, x1v, k) * rootWs[(k << 5) + lane];
        float x2v = fmaxf(a, 0.f);
        x2[((size_t)b * KA + i) * HID + lane] = x2v;
        float zz = p2bv;
#pragma unroll
        for (int c = 0; c < 32; c++)
            zz += __shfl_sync(0xffffffffu, x2v, c) * p2Ws[c * KB + kk10];
        float e = (lane < KB) ? __expf(zz) : 0.f;
        float ssum = e;
#pragma unroll
        for (int o = 16; o; o >>= 1) ssum += __shfl_xor_sync(0xffffffffu, ssum, o);
        if (lane < KB) s2[((size_t)b * KA + i) * KB + lane] = e / ssum;
    }
}

// ---------------------------------------------------------------------------
__global__ __launch_bounds__(256) void stage2b_kernel(
    const float* __restrict__ adj1, const float* __restrict__ s2,
    const float* __restrict__ x2,
    float* __restrict__ adjr2, float* __restrict__ ss2, float* __restrict__ x3) {
    extern __shared__ float sm[];
    float* adj1s = sm;
    float* s2s   = sm + 10000;
    float* x2s   = sm + 11000;
    float* tt2s  = sm + 14200;
    int b = blockIdx.x, tid = threadIdx.x;
    const float* A = adj1 + (size_t)b * KA * KA;
    const float* S2 = s2 + (size_t)b * KA * KB;
    const float* X2 = x2 + (size_t)b * KA * HID;
    for (int i = tid; i < KA * KA; i += 256) adj1s[i] = A[i];
    for (int i = tid; i < KA * KB; i += 256) s2s[i] = S2[i];
    for (int i = tid; i < KA * HID; i += 256) x2s[i] = X2[i];
    __syncthreads();
    for (int t = tid; t < KA * KB; t += 256) {
        int i = t / KB, k = t - i * KB;
        float a = 0.f;
        const float* ar = adj1s + i * KA;
        for (int m = 0; m < KA; m++) a += ar[m] * s2s[m * KB + k];
        tt2s[t] = a;
    }
    __syncthreads();
    for (int t = tid; t < 520; t += 256) {
        if (t < 100) {
            int i = t / 10, j = t - i * 10;
            float a = 0.f;
            for (int n = 0; n < KA; n++) a += s2s[n * KB + i] * tt2s[n * KB + j];
            adjr2[(size_t)b * 100 + t] = a;
        } else if (t < 200) {
            int u = t - 100;
            int i = u / 10, j = u - i * 10;
            float a = 0.f;
            for (int n = 0; n < KA; n++) a += s2s[n * KB + i] * s2s[n * KB + j];
            ss2[(size_t)b * 100 + u] = a;
        } else {
            int u = t - 200;
            int i = u >> 5, c = u & 31;
            float a = 0.f;
            for (int n = 0; n < KA; n++) a += s2s[n * KB + i] * x2s[(n << 5) + c];
            x3[(size_t)b * 320 + u] = a;
        }
    }
}

// ---------------------------------------------------------------------------
__global__ void tail_kernel(const float* __restrict__ adj2, const float* __restrict__ x3,
                            const float* __restrict__ c3rW, const float* __restrict__ c3rb,
                            const float* __restrict__ c3oW,
                            const float* __restrict__ l1W, const float* __restrict__ l1b,
                            const float* __restrict__ l2W, const float* __restrict__ l2b,
                            float* __restrict__ out) {
    int b = blockIdx.x, lane = threadIdx.x;
    const float* A2 = adj2 + (size_t)b * 100;
    const float* X3 = x3 + (size_t)b * 320;
    float x3c[10], t3c[10];
#pragma unroll
    for (int j = 0; j < 10; j++) x3c[j] = X3[j * 32 + lane];
#pragma unroll
    for (int i = 0; i < 10; i++) {
        float a = 0.f;
#pragma unroll
        for (int j = 0; j < 10; j++) a += A2[i * 10 + j] * x3c[j];
        t3c[i] = a;
    }
    float rb = c3rb[lane];
    float g = 0.f;
#pragma unroll
    for (int i = 0; i < 10; i++) {
        float a = rb;
#pragma unroll
        for (int k = 0; k < 32; k++)
            a += __shfl_sync(0xffffffffu, t3c[i], k) * c3rW[k * 32 + lane]
               + __shfl_sync(0xffffffffu, x3c[i], k) * c3oW[k * 32 + lane];
        g += a;
    }
    g *= 0.1f;
    float a1 = l1b[lane];
#pragma unroll
    for (int k = 0; k < 32; k++) a1 += __shfl_sync(0xffffffffu, g, k) * l1W[k * 32 + lane];
    float gg = fmaxf(a1, 0.f);
    int kk = lane < OC ? lane : 0;
    float a2 = l2b[kk];
#pragma unroll
    for (int k = 0; k < 32; k++) a2 += __shfl_sync(0xffffffffu, gg, k) * l2W[k * OC + kk];
    float val = (lane < OC) ? a2 : -INFINITY;
    float m = val;
#pragma unroll
    for (int o = 16; o; o >>= 1) m = fmaxf(m, __shfl_xor_sync(0xffffffffu, m, o));
    float e = (lane < OC) ? __expf(val - m) : 0.f;
    float ssum = e;
#pragma unroll
    for (int o = 16; o; o >>= 1) ssum += __shfl_xor_sync(0xffffffffu, ssum, o);
    if (lane < OC) out[b * OC + lane] = val - m - logf(ssum);
}

__global__ void final_kernel(const float* __restrict__ lossb, float* __restrict__ out,
                             int out_size) {
    __shared__ float sm[128];
    int t = threadIdx.x;
    sm[t] = lossb[t];
    __syncthreads();
    for (int s = 64; s > 0; s >>= 1) {
        if (t < s) sm[t] += sm[t + s];
        __syncthreads();
    }
    if (t == 0 && out_size > BATCH * OC) out[BATCH * OC] = sm[0] / (float)BATCH;
}

// ---------------------------------------------------------------------------
extern "C" void kernel_launch(void* const* d_in, const int* in_sizes, int n_in,
                              void* d_out, int out_size) {
    const float* x    = (const float*)d_in[0];
    const int*   ei   = (const int*)  d_in[1];
    const float* c1W  = (const float*)d_in[3];
    const float* c1b  = (const float*)d_in[4];
    const float* p1W  = (const float*)d_in[5];
    const float* p1b  = (const float*)d_in[6];
    const float* c2rW = (const float*)d_in[7];
    const float* c2rb = (const float*)d_in[8];
    const float* c2oW = (const float*)d_in[9];
    const float* p2W  = (const float*)d_in[10];
    const float* p2b  = (const float*)d_in[11];
    const float* c3rW = (const float*)d_in[12];
    const float* c3rb = (const float*)d_in[13];
    const float* c3oW = (const float*)d_in[14];
    const float* l1W  = (const float*)d_in[15];
    const float* l1b  = (const float*)d_in[16];
    const float* l2W  = (const float*)d_in[17];
    const float* l2b  = (const float*)d_in[18];
    float* out = (float*)d_out;
    int E = in_sizes[1] / 2;
    int eper = E / BATCH;

    void* sp = nullptr;
    cudaGetSymbolAddress(&sp, g_scratch);
    float* S = (float*)sp;
    int *csn, *cdn, *osn, *odn, *lsrc, *ldst;
    cudaGetSymbolAddress((void**)&csn, g_cnt_src);
    cudaGetSymbolAddress((void**)&cdn, g_cnt_dst);
    cudaGetSymbolAddress((void**)&osn, g_off_src);
    cudaGetSymbolAddress((void**)&odn, g_off_dst);
    cudaGetSymbolAddress((void**)&lsrc, g_list_src);
    cudaGetSymbolAddress((void**)&ldst, g_list_dst);

    cudaFuncSetAttribute(stage2_conv_kernel, cudaFuncAttributeMaxDynamicSharedMemorySize, 62272);
    cudaFuncSetAttribute(stage2b_kernel, cudaFuncAttributeMaxDynamicSharedMemorySize, 60800);

    build_csr_kernel<<<BATCH, 512>>>(ei, E, eper, osn, csn, odn, cdn, lsrc, ldst,
                                     S + OFF_DEG, S + OFF_DFLAT);
    xwp_kernel<<<TOT / 8, dim3(32, 8)>>>(x, c1W, S + OFF_DEG, S + OFF_XWP);
    agg_gather_kernel<<<TOT * 32 / 256, 256>>>(odn, cdn, ldst, S + OFF_XWP,
                                               S + OFF_DEG, c1b, S + OFF_H);
    pool_softmax1_kernel<<<TOT / 64, 256>>>(S + OFF_H, p1W, p1b, S + OFF_S1);
    t1_gather_kernel<<<TOT * 32 / 256, 256>>>(osn, csn, lsrc, S + OFF_S1, S + OFF_T1);
    gram_fused_kernel<<<BATCH, 288>>>(S + OFF_S1, S + OFF_T1, S + OFF_ADJR1, S + OFF_SS1);
    atb8_32_kernel<<<BATCH, 256>>>(S + OFF_S1, S + OFF_H, S + OFF_X1);
    loss_norm_kernel<<<BATCH, 128>>>(S + OFF_ADJR1, S + OFF_SS1, S + OFF_S1, S + OFF_DFLAT,
                                     S + OFF_ADJ1, S + OFF_DFLAT2, S + OFF_LOSSB,
                                     KA, NNODE, KAP, KAP, KAP * KAP, 0);
    stage2_conv_kernel<<<BATCH, 256, 62272>>>(S + OFF_ADJ1, S + OFF_X1, c2rW, c2rb, c2oW,
                                              p2W, p2b, S + OFF_X2, S + OFF_S2);
    stage2b_kernel<<<BATCH, 256, 60800>>>(S + OFF_ADJ1, S + OFF_S2, S + OFF_X2,
                                          S + OFF_ADJR2, S + OFF_SS2, S + OFF_X3);
    loss_norm_kernel<<<BATCH, 128>>>(S + OFF_ADJR2, S + OFF_SS2, S + OFF_S2, S + OFF_DFLAT2,
                                     S + OFF_ADJ2, S + OFF_DUMMY, S + OFF_LOSSB,
                                     KB, KA, KB, KB, KB * KB, 1);
    tail_kernel<<<BATCH, 32>>>(S + OFF_ADJ2, S + OFF_X3, c3rW, c3rb, c3oW,
                               l1W, l1b, l2W, l2b, out);
    final_kernel<<<1, 128>>>(S + OFF_LOSSB, out, out_size);
}

// round 13
// speedup vs baseline: 1.1990x; 1.0310x over previous
#include <cuda_runtime.h>
#include <math.h>
#include <stdint.h>

namespace {
constexpr int BATCH = 128, NNODE = 512, INC = 128, HID = 32, KA = 100, KB = 10, OC = 10;
constexpr int KAP = 128;
constexpr int TOT = BATCH * NNODE;
constexpr int MAXE = BATCH * 8192;
constexpr float EPSV = 1e-15f;

constexpr size_t OFF_DEG    = 0;
constexpr size_t OFF_DFLAT  = OFF_DEG + TOT;
constexpr size_t OFF_LOSSB  = OFF_DFLAT + TOT;
constexpr size_t OFF_XWP    = OFF_LOSSB + BATCH;
constexpr size_t OFF_H      = OFF_XWP   + (size_t)TOT * HID;
constexpr size_t OFF_S1     = OFF_H     + (size_t)TOT * HID;
constexpr size_t OFF_T1     = OFF_S1    + (size_t)TOT * KAP;
constexpr size_t OFF_ADJR1  = OFF_T1    + (size_t)TOT * KAP;
constexpr size_t OFF_SS1    = OFF_ADJR1 + (size_t)BATCH * KAP * KAP;
constexpr size_t OFF_X1     = OFF_SS1   + (size_t)BATCH * KAP * KAP;
constexpr size_t OFF_ADJ1   = OFF_X1    + (size_t)BATCH * KA * HID;
constexpr size_t OFF_DFLAT2 = OFF_ADJ1  + (size_t)BATCH * KA * KA;
constexpr size_t OFF_DUMMY  = OFF_DFLAT2+ (size_t)BATCH * KA;
constexpr size_t OFF_S2     = OFF_DUMMY + (size_t)BATCH * KB;
constexpr size_t OFF_ADJR2  = OFF_S2    + (size_t)BATCH * KA * KB;
constexpr size_t OFF_SS2    = OFF_ADJR2 + (size_t)BATCH * KB * KB;
constexpr size_t OFF_X3     = OFF_SS2   + (size_t)BATCH * KB * KB;
constexpr size_t OFF_ADJ2   = OFF_X3    + (size_t)BATCH * KB * HID;
constexpr size_t SCRATCH_TOTAL = OFF_ADJ2 + (size_t)BATCH * KB * KB;
}  // namespace

__device__ __align__(16) float g_scratch[SCRATCH_TOTAL];
__device__ __align__(16) int g_cnt_src[TOT];
__device__ __align__(16) int g_cnt_dst[TOT];
__device__ __align__(16) int g_off_src[TOT];
__device__ __align__(16) int g_off_dst[TOT];
__device__ __align__(16) int g_list_src[MAXE];
__device__ __align__(16) int g_list_dst[MAXE];

// ---------------------------------------------------------------------------
// Fused CSR build
// ---------------------------------------------------------------------------
__global__ __launch_bounds__(512) void build_csr_kernel(
    const int* __restrict__ ei, int E, int eper,
    int* __restrict__ off_src, int* __restrict__ cnt_src,
    int* __restrict__ off_dst, int* __restrict__ cnt_dst,
    int* __restrict__ list_src, int* __restrict__ list_dst,
    float* __restrict__ deg, float* __restrict__ dflat) {
    __shared__ int sc[512], sd[512], sscan[512];
    __shared__ int csrc[512], cdst[512];
    int b = blockIdx.x, tid = threadIdx.x;
    sc[tid] = 0; sd[tid] = 0;
    __syncthreads();
    const int* se = ei + (size_t)b * eper;
    const int* de = ei + E + (size_t)b * eper;
    for (int e = tid; e < eper; e += 512) {
        atomicAdd(&sc[se[e] & 511], 1);
        atomicAdd(&sd[de[e] & 511], 1);
    }
    __syncthreads();
    int vs = sc[tid], vd = sd[tid];
    int g = (b << 9) + tid;
    int base = b * eper;
    dflat[g] = (float)vs;
    deg[g]   = (float)vd;
    cnt_src[g] = vs;
    cnt_dst[g] = vd;
    sscan[tid] = vs; __syncthreads();
    for (int o = 1; o < 512; o <<= 1) {
        int t = (tid >= o) ? sscan[tid - o] : 0;
        __syncthreads(); sscan[tid] += t; __syncthreads();
    }
    int es = base + sscan[tid] - vs;
    off_src[g] = es; csrc[tid] = es;
    __syncthreads();
    sscan[tid] = vd; __syncthreads();
    for (int o = 1; o < 512; o <<= 1) {
        int t = (tid >= o) ? sscan[tid - o] : 0;
        __syncthreads(); sscan[tid] += t; __syncthreads();
    }
    int ed = base + sscan[tid] - vd;
    off_dst[g] = ed; cdst[tid] = ed;
    __syncthreads();
    for (int e = tid; e < eper; e += 512) {
        int s = se[e] & 511, d = de[e] & 511;
        int p = atomicAdd(&csrc[s], 1);
        list_src[p] = d;
        int q = atomicAdd(&cdst[d], 1);
        list_dst[q] = s;
    }
}

// ---------------------------------------------------------------------------
__global__ __launch_bounds__(256) void xwp_kernel(const float* __restrict__ x,
                                                  const float* __restrict__ W,
                                                  const float* __restrict__ deg,
                                                  float* __restrict__ xwp) {
    __shared__ float Ws[INC * HID];
    __shared__ float xs[8][INC];
    int tid = threadIdx.y * 32 + threadIdx.x;
    for (int t = tid; t < INC * HID; t += 256) Ws[t] = W[t];
    int r0 = blockIdx.x * 8;
    for (int t = tid; t < 8 * INC; t += 256) {
        int r = t >> 7, k = t & 127;
        xs[r][k] = x[(size_t)(r0 + r) * INC + k];
    }
    __syncthreads();
    int c = threadIdx.x, r = threadIdx.y;
    float acc = 0.f;
#pragma unroll 8
    for (int k = 0; k < INC; k++) acc += xs[r][k] * Ws[k * HID + c];
    int g = r0 + r;
    float dis = rsqrtf(deg[g] + 1.0f);
    xwp[(size_t)g * HID + c] = dis * acc;
}

// ---------------------------------------------------------------------------
__global__ __launch_bounds__(256) void agg_gather_kernel(
    const int* __restrict__ off_dst, const int* __restrict__ cnt_dst,
    const int* __restrict__ list_dst,
    const float* __restrict__ xwp, const float* __restrict__ deg,
    const float* __restrict__ bias, float* __restrict__ h) {
    int node = (blockIdx.x * blockDim.x + threadIdx.x) >> 5;
    int lane = threadIdx.x & 31;
    if (node >= TOT) return;
    int b = node >> 9;
    const float* xb = xwp + (((size_t)b << 9) << 5);
    int off = off_dst[node], cnt = cnt_dst[node];
    float acc = 0.f;
    int i = off, end = off + cnt;
    for (; i + 3 < end; i += 4) {
        int s0 = __ldg(&list_dst[i]),   s1 = __ldg(&list_dst[i + 1]);
        int s2 = __ldg(&list_dst[i + 2]), s3 = __ldg(&list_dst[i + 3]);
        acc += xb[(s0 << 5) + lane] + xb[(s1 << 5) + lane]
             + xb[(s2 << 5) + lane] + xb[(s3 << 5) + lane];
    }
    for (; i < end; i++) acc += xb[(__ldg(&list_dst[i]) << 5) + lane];
    float dis = rsqrtf(deg[node] + 1.0f);
    float xv = xwp[((size_t)node << 5) + lane];
    h[((size_t)node << 5) + lane] = fmaxf(dis * (acc + xv) + bias[lane], 0.f);
}

// ---------------------------------------------------------------------------
__global__ __launch_bounds__(256) void t1_gather_kernel(
    const int* __restrict__ off_src, const int* __restrict__ cnt_src,
    const int* __restrict__ list_src,
    const float* __restrict__ s1p, float* __restrict__ T1) {
    int node = (blockIdx.x * blockDim.x + threadIdx.x) >> 5;
    int lane = threadIdx.x & 31;
    if (node >= TOT) return;
    int b = node >> 9;
    const float4* sb = (const float4*)(s1p + (((size_t)b << 9) << 7)) + lane;
    int off = off_src[node], cnt = cnt_src[node];
    float4 acc = make_float4(0, 0, 0, 0);
    int i = off, end = off + cnt;
    for (; i + 3 < end; i += 4) {
        int d0 = __ldg(&list_src[i]),     d1 = __ldg(&list_src[i + 1]);
        int d2 = __ldg(&list_src[i + 2]), d3 = __ldg(&list_src[i + 3]);
        float4 v0 = __ldg(&sb[d0 << 5]);
        float4 v1 = __ldg(&sb[d1 << 5]);
        float4 v2 = __ldg(&sb[d2 << 5]);
        float4 v3 = __ldg(&sb[d3 << 5]);
        acc.x += (v0.x + v1.x) + (v2.x + v3.x);
        acc.y += (v0.y + v1.y) + (v2.y + v3.y);
        acc.z += (v0.z + v1.z) + (v2.z + v3.z);
        acc.w += (v0.w + v1.w) + (v2.w + v3.w);
    }
    for (; i < end; i++) {
        float4 v = __ldg(&sb[__ldg(&list_src[i]) << 5]);
        acc.x += v.x; acc.y += v.y; acc.z += v.z; acc.w += v.w;
    }
    ((float4*)(T1 + ((size_t)node << 7)))[lane] = acc;
}

// ---------------------------------------------------------------------------
// Fused Gram kernel (validated R12): one block per graph, 288 threads.
// ---------------------------------------------------------------------------
__global__ __launch_bounds__(288) void gram_fused_kernel(
    const float* __restrict__ s1p, const float* __restrict__ T1,
    float* __restrict__ adjr1, float* __restrict__ ss1) {
    __shared__ float As[2][16][128];
    __shared__ float Bs[2][16][128];
    int b = blockIdx.x;
    const float* A = s1p + ((size_t)b << 16);
    const float* B = T1 + ((size_t)b << 16);
    int tid = threadIdx.x;

    int sel, r, c;
    if (tid < 169) {
        sel = 0; r = tid / 13; c = tid - r * 13;
    } else if (tid < 260) {
        int u = tid - 169;
        int rr = 0, base = 0, nb = 13;
#pragma unroll
        for (int q = 0; q < 12; q++) {
            if (u >= nb) { rr = q + 1; base = nb; }
            nb += 12 - q;
        }
        sel = 1; r = rr; c = rr + (u - base);
    } else {
        sel = 2; r = 0; c = 0;
    }

    bool loader = tid < 256;
    int lk0 = tid >> 5,         lj0 = (tid & 31) << 2;
    int lk1 = (tid + 256) >> 5, lj1 = ((tid + 256) & 31) << 2;

    float4 pa0, pa1, pb0, pb1;
    if (loader) {
        pa0 = *(const float4*)(A + lk0 * KAP + lj0);
        pa1 = *(const float4*)(A + lk1 * KAP + lj1);
        pb0 = *(const float4*)(B + lk0 * KAP + lj0);
        pb1 = *(const float4*)(B + lk1 * KAP + lj1);
        *(float4*)&As[0][lk0][lj0] = pa0;
        *(float4*)&As[0][lk1][lj1] = pa1;
        *(float4*)&Bs[0][lk0][lj0] = pb0;
        *(float4*)&Bs[0][lk1][lj1] = pb1;
    }
    __syncthreads();

    float acc[8][8] = {};
    int cur = 0;
    for (int n0 = 0; n0 < NNODE; n0 += 16) {
        int nn = n0 + 16;
        if (loader && nn < NNODE) {
            pa0 = *(const float4*)(A + (nn + lk0) * KAP + lj0);
            pa1 = *(const float4*)(A + (nn + lk1) * KAP + lj1);
            pb0 = *(const float4*)(B + (nn + lk0) * KAP + lj0);
            pb1 = *(const float4*)(B + (nn + lk1) * KAP + lj1);
        }
        if (sel != 2) {
            const float (*pA)[128] = As[cur];
            const float (*pB)[128] = (sel == 1) ? As[cur] : Bs[cur];
#pragma unroll
            for (int kk = 0; kk < 16; kk++) {
                float4 a0 = *(const float4*)&pA[kk][r * 8];
                float4 a1 = *(const float4*)&pA[kk][r * 8 + 4];
                float4 b0 = *(const float4*)&pB[kk][c * 8];
                float4 b1 = *(const float4*)&pB[kk][c * 8 + 4];
                float a[8] = {a0.x, a0.y, a0.z, a0.w, a1.x, a1.y, a1.z, a1.w};
                float bv[8] = {b0.x, b0.y, b0.z, b0.w, b1.x, b1.y, b1.z, b1.w};
#pragma unroll
                for (int u = 0; u < 8; u++)
#pragma unroll
                    for (int v = 0; v < 8; v++) acc[u][v] += a[u] * bv[v];
            }
        }
        if (nn < NNODE) {
            int nx = cur ^ 1;
            if (loader) {
                *(float4*)&As[nx][lk0][lj0] = pa0;
                *(float4*)&As[nx][lk1][lj1] = pa1;
                *(float4*)&Bs[nx][lk0][lj0] = pb0;
                *(float4*)&Bs[nx][lk1][lj1] = pb1;
            }
            __syncthreads();
            cur = nx;
        }
    }

    if (sel == 0) {
        float* C = adjr1 + ((size_t)b << 14);
#pragma unroll
        for (int u = 0; u < 8; u++) {
            *(float4*)&C[(size_t)(r * 8 + u) * KAP + c * 8] =
                make_float4(acc[u][0], acc[u][1], acc[u][2], acc[u][3]);
            *(float4*)&C[(size_t)(r * 8 + u) * KAP + c * 8 + 4] =
                make_float4(acc[u][4], acc[u][5], acc[u][6], acc[u][7]);
        }
    } else if (sel == 1) {
        float* C = ss1 + ((size_t)b << 14);
#pragma unroll
        for (int u = 0; u < 8; u++) {
            *(float4*)&C[(size_t)(r * 8 + u) * KAP + c * 8] =
                make_float4(acc[u][0], acc[u][1], acc[u][2], acc[u][3]);
            *(float4*)&C[(size_t)(r * 8 + u) * KAP + c * 8 + 4] =
                make_float4(acc[u][4], acc[u][5], acc[u][6], acc[u][7]);
        }
        if (r != c) {
#pragma unroll
            for (int v = 0; v < 8; v++)
#pragma unroll
                for (int u = 0; u < 8; u++)
                    C[(size_t)(c * 8 + v) * KAP + r * 8 + u] = acc[u][v];
        }
    }
}

// ---------------------------------------------------------------------------
__global__ __launch_bounds__(256) void atb8_32_kernel(const float* __restrict__ s1p,
                                                      const float* __restrict__ h,
                                                      float* __restrict__ x1) {
    __shared__ float As[16][128];
    __shared__ float Bs[16][32];
    int b = blockIdx.x;
    const float* A = s1p + ((size_t)b << 9) * KAP;
    const float* B = h + ((size_t)b << 9) * HID;
    float* C = x1 + (size_t)b * KA * HID;
    int tid = threadIdx.x;
    int tx = tid & 7, ty = tid >> 3;
    float acc[4][4] = {};
    for (int n0 = 0; n0 < NNODE; n0 += 16) {
#pragma unroll
        for (int r = 0; r < 2; r++) {
            int t4 = tid + r * 256;
            int kk = t4 >> 5, jf = (t4 & 31) << 2;
            *(float4*)&As[kk][jf] = *(const float4*)(A + (n0 + kk) * KAP + jf);
        }
        if (tid < 128) {
            int kk = tid >> 3, jf = (tid & 7) << 2;
            *(float4*)&Bs[kk][jf] = *(const float4*)(B + (n0 + kk) * HID + jf);
        }
        __syncthreads();
#pragma unroll
        for (int kk = 0; kk < 16; kk++) {
            float4 av = *(float4*)&As[kk][ty * 4];
            float4 bb = *(float4*)&Bs[kk][tx * 4];
            float a[4] = {av.x, av.y, av.z, av.w};
            float bv[4] = {bb.x, bb.y, bb.z, bb.w};
#pragma unroll
            for (int u = 0; u < 4; u++)
#pragma unroll
                for (int v = 0; v < 4; v++) acc[u][v] += a[u] * bv[v];
        }
        __syncthreads();
    }
#pragma unroll
    for (int u = 0; u < 4; u++) {
        int row = ty * 4 + u;
        if (row < KA)
            *(float4*)&C[(size_t)row * HID + tx * 4] =
                make_float4(acc[u][0], acc[u][1], acc[u][2], acc[u][3]);
    }
}

// ---------------------------------------------------------------------------
// stage-1 pooled softmax, 4 rows per iteration (shares W LDS among 4 rows).
// Per-row arithmetic order identical to before (bit-exact outputs).
// ---------------------------------------------------------------------------
__global__ __launch_bounds__(256) void pool_softmax1_kernel(
    const float* __restrict__ X, const float* __restrict__ W,
    const float* __restrict__ bias, float* __restrict__ Sout) {
    __shared__ float Ws[HID * KAP];
    __shared__ float bs[KAP];
    int tid = threadIdx.x;
    for (int t = tid; t < HID * KAP; t += 256) {
        int c = t >> 7, k = t & 127;
        Ws[t] = (k < KA) ? W[c * KA + k] : 0.f;
    }
    if (tid < KAP) bs[tid] = (tid < KA) ? bias[tid] : 0.f;
    __syncthreads();
    int lane = tid & 31, warp = tid >> 5;
    int row0 = blockIdx.x * 64 + warp * 8;
    float b0v = bs[lane], b1v = bs[32 + lane], b2v = bs[64 + lane], b3v = bs[96 + lane];
#pragma unroll 1
    for (int r = 0; r < 8; r += 4) {
        int row = row0 + r;
        float xv0 = X[(size_t)row * HID + lane];
        float xv1 = X[(size_t)(row + 1) * HID + lane];
        float xv2 = X[(size_t)(row + 2) * HID + lane];
        float xv3 = X[(size_t)(row + 3) * HID + lane];
        float a0 = b0v, a1 = b1v, a2 = b2v, a3 = b3v;
        float c0 = b0v, c1 = b1v, c2 = b2v, c3 = b3v;
        float d0 = b0v, d1 = b1v, d2 = b2v, d3 = b3v;
        float g0 = b0v, g1 = b1v, g2 = b2v, g3 = b3v;
#pragma unroll
        for (int c = 0; c < HID; c++) {
            float bx0 = __shfl_sync(0xffffffffu, xv0, c);
            float bx1 = __shfl_sync(0xffffffffu, xv1, c);
            float bx2 = __shfl_sync(0xffffffffu, xv2, c);
            float bx3 = __shfl_sync(0xffffffffu, xv3, c);
            const float* wr = Ws + (c << 7) + lane;
            float w0 = wr[0], w1 = wr[32], w2 = wr[64], w3 = wr[96];
            a0 += bx0 * w0; a1 += bx0 * w1; a2 += bx0 * w2; a3 += bx0 * w3;
            c0 += bx1 * w0; c1 += bx1 * w1; c2 += bx1 * w2; c3 += bx1 * w3;
            d0 += bx2 * w0; d1 += bx2 * w1; d2 += bx2 * w2; d3 += bx2 * w3;
            g0 += bx3 * w0; g1 += bx3 * w1; g2 += bx3 * w2; g3 += bx3 * w3;
        }
        bool v3 = (96 + lane < KA);
        float e0 = __expf(a0), e1 = __expf(a1), e2 = __expf(a2);
        float e3 = v3 ? __expf(a3) : 0.f;
        float f0 = __expf(c0), f1 = __expf(c1), f2 = __expf(c2);
        float f3 = v3 ? __expf(c3) : 0.f;
        float h0 = __expf(d0), h1 = __expf(d1), h2 = __expf(d2);
        float h3 = v3 ? __expf(d3) : 0.f;
        float k0 = __expf(g0), k1 = __expf(g1), k2 = __expf(g2);
        float k3 = v3 ? __expf(g3) : 0.f;
        float s0 = (e0 + e1) + (e2 + e3);
        float s1 = (f0 + f1) + (f2 + f3);
        float s2 = (h0 + h1) + (h2 + h3);
        float s3 = (k0 + k1) + (k2 + k3);
#pragma unroll
        for (int o = 16; o; o >>= 1) {
            s0 += __shfl_xor_sync(0xffffffffu, s0, o);
            s1 += __shfl_xor_sync(0xffffffffu, s1, o);
            s2 += __shfl_xor_sync(0xffffffffu, s2, o);
            s3 += __shfl_xor_sync(0xffffffffu, s3, o);
        }
        float i0 = __frcp_rn(s0), i1 = __frcp_rn(s1);
        float i2 = __frcp_rn(s2), i3 = __frcp_rn(s3);
        float* op0 = Sout + (size_t)row * KAP + lane;
        op0[0] = e0 * i0; op0[32] = e1 * i0; op0[64] = e2 * i0; op0[96] = e3 * i0;
        float* op1 = Sout + (size_t)(row + 1) * KAP + lane;
        op1[0] = f0 * i1; op1[32] = f1 * i1; op1[64] = f2 * i1; op1[96] = f3 * i1;
        float* op2 = Sout + (size_t)(row + 2) * KAP + lane;
        op2[0] = h0 * i2; op2[32] = h1 * i2; op2[64] = h2 * i2; op2[96] = h3 * i2;
        float* op3 = Sout + (size_t)(row + 3) * KAP + lane;
        op3[0] = k0 * i3; op3[32] = k1 * i3; op3[64] = k2 * i3; op3[96] = k3 * i3;
    }
}

// ---------------------------------------------------------------------------
__device__ __forceinline__ float blockReduce128(float v, float* sm) {
    int t = threadIdx.x;
    sm[t] = v;
    __syncthreads();
    for (int s = 64; s > 0; s >>= 1) {
        if (t < s) sm[t] += sm[t + s];
        __syncthreads();
    }
    float r = sm[0];
    __syncthreads();
    return r;
}

__global__ void loss_norm_kernel(const float* __restrict__ raw,
                                 const float* __restrict__ ss,
                                 const float* __restrict__ s,
                                 const float* __restrict__ dflat,
                                 float* __restrict__ adjn,
                                 float* __restrict__ dflat2,
                                 float* __restrict__ lossb,
                                 int k, int n, int ld, int ld_s, int bstride,
                                 int accum) {
    int b = blockIdx.x;
    raw  += (size_t)b * bstride;
    ss   += (size_t)b * bstride;
    s    += (size_t)b * n * ld_s;
    dflat+= (size_t)b * n;
    adjn += (size_t)b * k * k;
    dflat2 += (size_t)b * k;
    __shared__ float sm[128];
    __shared__ float idc[128];
    int tid = threadIdx.x;

    float v = 0.f;
    for (int i = tid; i < k; i += 128) v += raw[i * ld + i];
    float num = blockReduce128(v, sm);

    v = 0.f;
    for (int nn = tid; nn < n; nn += 128) {
        float dv = dflat[nn];
        float acc = 0.f;
        for (int kk = 0; kk < k; kk++) {
            float sv = s[(size_t)nn * ld_s + kk];
            acc += sv * sv;
        }
        v += acc * dv;
    }
    float den = blockReduce128(v, sm);

    v = 0.f;
    for (int i = tid; i < k; i += 128)
        for (int j = 0; j < k; j++) { float t = ss[i * ld + j]; v += t * t; }
    float nrm = sqrtf(blockReduce128(v, sm));

    float invn = 1.0f / nrm;
    float dk = rsqrtf((float)k);
    v = 0.f;
    for (int i = tid; i < k; i += 128)
        for (int j = 0; j < k; j++) {
            float t = ss[i * ld + j] * invn - ((i == j) ? dk : 0.f);
            v += t * t;
        }
    float ortho = sqrtf(blockReduce128(v, sm));

    for (int i = tid; i < k; i += 128) {
        float r = 0.f;
        for (int j = 0; j < k; j++) if (j != i) r += raw[i * ld + j];
        idc[i] = 1.0f / (sqrtf(r) + EPSV);
    }
    __syncthreads();
    for (int idx = tid; idx < k * k; idx += 128) {
        int i = idx / k, j = idx - i * k;
        adjn[idx] = (i == j) ? 0.f : raw[i * ld + j] * idc[i] * idc[j];
    }
    for (int i = tid; i < k; i += 128) {
        float r = 0.f;
        for (int j = 0; j < k; j++) if (j != i) r += raw[i * ld + j] * idc[j];
        dflat2[i] = r * idc[i];
    }
    if (tid == 0) {
        float val = -num / den + ortho;
        if (accum) lossb[b] += val; else lossb[b] = val;
    }
}

// ---------------------------------------------------------------------------
// Fused stage-2: conv2+relu, softmax2, TT2, adjr2/ss2/x3 in one kernel.
// x2 lives only in smem; s2 written to global for loss_norm2.
// smem layout (floats): adj1s 10000 | x1s 3200 | relWs 1024 | rootWs 1024 |
//                       p2Ws 320 | x2s 3200 | s2s 1000 | tt2s 1000  = 20768
// ---------------------------------------------------------------------------
__global__ __launch_bounds__(256) void stage2_fused_kernel(
    const float* __restrict__ adj1, const float* __restrict__ x1,
    const float* __restrict__ relW, const float* __restrict__ relb,
    const float* __restrict__ rootW,
    const float* __restrict__ p2W, const float* __restrict__ p2b,
    float* __restrict__ s2out,
    float* __restrict__ adjr2, float* __restrict__ ss2, float* __restrict__ x3) {
    extern __shared__ float sm[];
    float* adj1s = sm;
    float* x1s   = sm + 10000;
    float* relWs = sm + 13200;
    float* rootWs= sm + 14224;
    float* p2Ws  = sm + 15248;
    float* x2s   = sm + 15568;
    float* s2s   = sm + 18768;
    float* tt2s  = sm + 19768;
    int b = blockIdx.x, tid = threadIdx.x;
    const float* A = adj1 + (size_t)b * KA * KA;
    const float* X = x1 + (size_t)b * KA * HID;
    for (int i = tid; i < KA * KA; i += 256) adj1s[i] = A[i];
    for (int i = tid; i < KA * HID; i += 256) x1s[i] = X[i];
    for (int i = tid; i < HID * HID; i += 256) { relWs[i] = relW[i]; rootWs[i] = rootW[i]; }
    for (int i = tid; i < HID * KB; i += 256) p2Ws[i] = p2W[i];
    __syncthreads();
    int lane = tid & 31, warp = tid >> 5;
    float rb = relb[lane];
    int kk10 = lane < KB ? lane : 0;
    float p2bv = p2b[kk10];
    for (int i = warp; i < KA; i += 8) {
        float t2 = 0.f;
        const float* ar = adj1s + i * KA;
        for (int m = 0; m < KA; m++) t2 += ar[m] * x1s[(m << 5) + lane];
        float x1v = x1s[(i << 5) + lane];
        float a = rb;
#pragma unroll
        for (int k = 0; k < 32; k++)
            a += __shfl_sync(0xffffffffu, t2, k) * relWs[(k << 5) + lane]
               + __shfl_sync(0xffffffffu, x1v, k) * rootWs[(k << 5) + lane];
        float x2v = fmaxf(a, 0.f);
        x2s[(i << 5) + lane] = x2v;
        float zz = p2bv;
#pragma unroll
        for (int c = 0; c < 32; c++)
            zz += __shfl_sync(0xffffffffu, x2v, c) * p2Ws[c * KB + kk10];
        float e = (lane < KB) ? __expf(zz) : 0.f;
        float ssum = e;
#pragma unroll
        for (int o = 16; o; o >>= 1) ssum += __shfl_xor_sync(0xffffffffu, ssum, o);
        if (lane < KB) {
            float sv = e / ssum;
            s2s[i * KB + lane] = sv;
            s2out[((size_t)b * KA + i) * KB + lane] = sv;
        }
    }
    __syncthreads();
    for (int t = tid; t < KA * KB; t += 256) {
        int i = t / KB, k = t - i * KB;
        float a = 0.f;
        const float* ar = adj1s + i * KA;
        for (int m = 0; m < KA; m++) a += ar[m] * s2s[m * KB + k];
        tt2s[t] = a;
    }
    __syncthreads();
    for (int t = tid; t < 520; t += 256) {
        if (t < 100) {
            int i = t / 10, j = t - i * 10;
            float a = 0.f;
            for (int n = 0; n < KA; n++) a += s2s[n * KB + i] * tt2s[n * KB + j];
            adjr2[(size_t)b * 100 + t] = a;
        } else if (t < 200) {
            int u = t - 100;
            int i = u / 10, j = u - i * 10;
            float a = 0.f;
            for (int n = 0; n < KA; n++) a += s2s[n * KB + i] * s2s[n * KB + j];
            ss2[(size_t)b * 100 + u] = a;
        } else {
            int u = t - 200;
            int i = u >> 5, c = u & 31;
            float a = 0.f;
            for (int n = 0; n < KA; n++) a += s2s[n * KB + i] * x2s[(n << 5) + c];
            x3[(size_t)b * 320 + u] = a;
        }
    }
}

// ---------------------------------------------------------------------------
__global__ void tail_kernel(const float* __restrict__ adj2, const float* __restrict__ x3,
                            const float* __restrict__ c3rW, const float* __restrict__ c3rb,
                            const float* __restrict__ c3oW,
                            const float* __restrict__ l1W, const float* __restrict__ l1b,
                            const float* __restrict__ l2W, const float* __restrict__ l2b,
                            float* __restrict__ out) {
    int b = blockIdx.x, lane = threadIdx.x;
    const float* A2 = adj2 + (size_t)b * 100;
    const float* X3 = x3 + (size_t)b * 320;
    float x3c[10], t3c[10];
#pragma unroll
    for (int j = 0; j < 10; j++) x3c[j] = X3[j * 32 + lane];
#pragma unroll
    for (int i = 0; i < 10; i++) {
        float a = 0.f;
#pragma unroll
        for (int j = 0; j < 10; j++) a += A2[i * 10 + j] * x3c[j];
        t3c[i] = a;
    }
    float rb = c3rb[lane];
    float g = 0.f;
#pragma unroll
    for (int i = 0; i < 10; i++) {
        float a = rb;
#pragma unroll
        for (int k = 0; k < 32; k++)
            a += __shfl_sync(0xffffffffu, t3c[i], k) * c3rW[k * 32 + lane]
               + __shfl_sync(0xffffffffu, x3c[i], k) * c3oW[k * 32 + lane];
        g += a;
    }
    g *= 0.1f;
    float a1 = l1b[lane];
#pragma unroll
    for (int k = 0; k < 32; k++) a1 += __shfl_sync(0xffffffffu, g, k) * l1W[k * 32 + lane];
    float gg = fmaxf(a1, 0.f);
    int kk = lane < OC ? lane : 0;
    float a2 = l2b[kk];
#pragma unroll
    for (int k = 0; k < 32; k++) a2 += __shfl_sync(0xffffffffu, gg, k) * l2W[k * OC + kk];
    float val = (lane < OC) ? a2 : -INFINITY;
    float m = val;
#pragma unroll
    for (int o = 16; o; o >>= 1) m = fmaxf(m, __shfl_xor_sync(0xffffffffu, m, o));
    float e = (lane < OC) ? __expf(val - m) : 0.f;
    float ssum = e;
#pragma unroll
    for (int o = 16; o; o >>= 1) ssum += __shfl_xor_sync(0xffffffffu, ssum, o);
    if (lane < OC) out[b * OC + lane] = val - m - logf(ssum);
}

__global__ void final_kernel(const float* __restrict__ lossb, float* __restrict__ out,
                             int out_size) {
    __shared__ float sm[128];
    int t = threadIdx.x;
    sm[t] = lossb[t];
    __syncthreads();
    for (int s = 64; s > 0; s >>= 1) {
        if (t < s) sm[t] += sm[t + s];
        __syncthreads();
    }
    if (t == 0 && out_size > BATCH * OC) out[BATCH * OC] = sm[0] / (float)BATCH;
}

// ---------------------------------------------------------------------------
extern "C" void kernel_launch(void* const* d_in, const int* in_sizes, int n_in,
                              void* d_out, int out_size) {
    const float* x    = (const float*)d_in[0];
    const int*   ei   = (const int*)  d_in[1];
    const float* c1W  = (const float*)d_in[3];
    const float* c1b  = (const float*)d_in[4];
    const float* p1W  = (const float*)d_in[5];
    const float* p1b  = (const float*)d_in[6];
    const float* c2rW = (const float*)d_in[7];
    const float* c2rb = (const float*)d_in[8];
    const float* c2oW = (const float*)d_in[9];
    const float* p2W  = (const float*)d_in[10];
    const float* p2b  = (const float*)d_in[11];
    const float* c3rW = (const float*)d_in[12];
    const float* c3rb = (const float*)d_in[13];
    const float* c3oW = (const float*)d_in[14];
    const float* l1W  = (const float*)d_in[15];
    const float* l1b  = (const float*)d_in[16];
    const float* l2W  = (const float*)d_in[17];
    const float* l2b  = (const float*)d_in[18];
    float* out = (float*)d_out;
    int E = in_sizes[1] / 2;
    int eper = E / BATCH;

    void* sp = nullptr;
    cudaGetSymbolAddress(&sp, g_scratch);
    float* S = (float*)sp;
    int *csn, *cdn, *osn, *odn, *lsrc, *ldst;
    cudaGetSymbolAddress((void**)&csn, g_cnt_src);
    cudaGetSymbolAddress((void**)&cdn, g_cnt_dst);
    cudaGetSymbolAddress((void**)&osn, g_off_src);
    cudaGetSymbolAddress((void**)&odn, g_off_dst);
    cudaGetSymbolAddress((void**)&lsrc, g_list_src);
    cudaGetSymbolAddress((void**)&ldst, g_list_dst);

    cudaFuncSetAttribute(stage2_fused_kernel, cudaFuncAttributeMaxDynamicSharedMemorySize, 83072);

    build_csr_kernel<<<BATCH, 512>>>(ei, E, eper, osn, csn, odn, cdn, lsrc, ldst,
                                     S + OFF_DEG, S + OFF_DFLAT);
    xwp_kernel<<<TOT / 8, dim3(32, 8)>>>(x, c1W, S + OFF_DEG, S + OFF_XWP);
    agg_gather_kernel<<<TOT * 32 / 256, 256>>>(odn, cdn, ldst, S + OFF_XWP,
                                               S + OFF_DEG, c1b, S + OFF_H);
    pool_softmax1_kernel<<<TOT / 64, 256>>>(S + OFF_H, p1W, p1b, S + OFF_S1);
    t1_gather_kernel<<<TOT * 32 / 256, 256>>>(osn, csn, lsrc, S + OFF_S1, S + OFF_T1);
    gram_fused_kernel<<<BATCH, 288>>>(S + OFF_S1, S + OFF_T1, S + OFF_ADJR1, S + OFF_SS1);
    atb8_32_kernel<<<BATCH, 256>>>(S + OFF_S1, S + OFF_H, S + OFF_X1);
    loss_norm_kernel<<<BATCH, 128>>>(S + OFF_ADJR1, S + OFF_SS1, S + OFF_S1, S + OFF_DFLAT,
                                     S + OFF_ADJ1, S + OFF_DFLAT2, S + OFF_LOSSB,
                                     KA, NNODE, KAP, KAP, KAP * KAP, 0);
    stage2_fused_kernel<<<BATCH, 256, 83072>>>(S + OFF_ADJ1, S + OFF_X1, c2rW, c2rb, c2oW,
                                               p2W, p2b, S + OFF_S2,
                                               S + OFF_ADJR2, S + OFF_SS2, S + OFF_X3);
    loss_norm_kernel<<<BATCH, 128>>>(S + OFF_ADJR2, S + OFF_SS2, S + OFF_S2, S + OFF_DFLAT2,
                                     S + OFF_ADJ2, S + OFF_DUMMY, S + OFF_LOSSB,
                                     KB, KA, KB, KB, KB * KB, 1);
    tail_kernel<<<BATCH, 32>>>(S + OFF_ADJ2, S + OFF_X3, c3rW, c3rb, c3oW,
                               l1W, l1b, l2W, l2b, out);
    final_kernel<<<1, 128>>>(S + OFF_LOSSB, out, out_size);
}

// round 14
// speedup vs baseline: 1.3046x; 1.0881x over previous
#include <cuda_runtime.h>
#include <math.h>
#include <stdint.h>

namespace {
constexpr int BATCH = 128, NNODE = 512, INC = 128, HID = 32, KA = 100, KB = 10, OC = 10;
constexpr int KAP = 128;
constexpr int TOT = BATCH * NNODE;
constexpr int MAXE = BATCH * 8192;
constexpr float EPSV = 1e-15f;

constexpr size_t OFF_DEG    = 0;
constexpr size_t OFF_DFLAT  = OFF_DEG + TOT;
constexpr size_t OFF_LOSSB  = OFF_DFLAT + TOT;
constexpr size_t OFF_XWP    = OFF_LOSSB + BATCH;
constexpr size_t OFF_H      = OFF_XWP   + (size_t)TOT * HID;
constexpr size_t OFF_S1     = OFF_H     + (size_t)TOT * HID;
constexpr size_t OFF_T1     = OFF_S1    + (size_t)TOT * KAP;
constexpr size_t OFF_ADJR1  = OFF_T1    + (size_t)TOT * KAP;
constexpr size_t OFF_SS1    = OFF_ADJR1 + (size_t)BATCH * KAP * KAP;
constexpr size_t OFF_X1     = OFF_SS1   + (size_t)BATCH * KAP * KAP;
constexpr size_t OFF_ADJ1   = OFF_X1    + (size_t)BATCH * KA * HID;
constexpr size_t OFF_DFLAT2 = OFF_ADJ1  + (size_t)BATCH * KA * KA;
constexpr size_t SCRATCH_TOTAL = OFF_DFLAT2 + (size_t)BATCH * KA;
}  // namespace

__device__ __align__(16) float g_scratch[SCRATCH_TOTAL];
__device__ __align__(16) int g_cnt_src[TOT];
__device__ __align__(16) int g_cnt_dst[TOT];
__device__ __align__(16) int g_off_src[TOT];
__device__ __align__(16) int g_off_dst[TOT];
__device__ __align__(16) int g_list_src[MAXE];
__device__ __align__(16) int g_list_dst[MAXE];

// ---------------------------------------------------------------------------
// Fused CSR build
// ---------------------------------------------------------------------------
__global__ __launch_bounds__(512) void build_csr_kernel(
    const int* __restrict__ ei, int E, int eper,
    int* __restrict__ off_src, int* __restrict__ cnt_src,
    int* __restrict__ off_dst, int* __restrict__ cnt_dst,
    int* __restrict__ list_src, int* __restrict__ list_dst,
    float* __restrict__ deg, float* __restrict__ dflat) {
    __shared__ int sc[512], sd[512], sscan[512];
    __shared__ int csrc[512], cdst[512];
    int b = blockIdx.x, tid = threadIdx.x;
    sc[tid] = 0; sd[tid] = 0;
    __syncthreads();
    const int* se = ei + (size_t)b * eper;
    const int* de = ei + E + (size_t)b * eper;
    for (int e = tid; e < eper; e += 512) {
        atomicAdd(&sc[se[e] & 511], 1);
        atomicAdd(&sd[de[e] & 511], 1);
    }
    __syncthreads();
    int vs = sc[tid], vd = sd[tid];
    int g = (b << 9) + tid;
    int base = b * eper;
    dflat[g] = (float)vs;
    deg[g]   = (float)vd;
    cnt_src[g] = vs;
    cnt_dst[g] = vd;
    sscan[tid] = vs; __syncthreads();
    for (int o = 1; o < 512; o <<= 1) {
        int t = (tid >= o) ? sscan[tid - o] : 0;
        __syncthreads(); sscan[tid] += t; __syncthreads();
    }
    int es = base + sscan[tid] - vs;
    off_src[g] = es; csrc[tid] = es;
    __syncthreads();
    sscan[tid] = vd; __syncthreads();
    for (int o = 1; o < 512; o <<= 1) {
        int t = (tid >= o) ? sscan[tid - o] : 0;
        __syncthreads(); sscan[tid] += t; __syncthreads();
    }
    int ed = base + sscan[tid] - vd;
    off_dst[g] = ed; cdst[tid] = ed;
    __syncthreads();
    for (int e = tid; e < eper; e += 512) {
        int s = se[e] & 511, d = de[e] & 511;
        int p = atomicAdd(&csrc[s], 1);
        list_src[p] = d;
        int q = atomicAdd(&cdst[d], 1);
        list_dst[q] = s;
    }
}

// ---------------------------------------------------------------------------
__global__ __launch_bounds__(256) void xwp_kernel(const float* __restrict__ x,
                                                  const float* __restrict__ W,
                                                  const float* __restrict__ deg,
                                                  float* __restrict__ xwp) {
    __shared__ float Ws[INC * HID];
    __shared__ float xs[8][INC];
    int tid = threadIdx.y * 32 + threadIdx.x;
    for (int t = tid; t < INC * HID; t += 256) Ws[t] = W[t];
    int r0 = blockIdx.x * 8;
    for (int t = tid; t < 8 * INC; t += 256) {
        int r = t >> 7, k = t & 127;
        xs[r][k] = x[(size_t)(r0 + r) * INC + k];
    }
    __syncthreads();
    int c = threadIdx.x, r = threadIdx.y;
    float acc = 0.f;
#pragma unroll 8
    for (int k = 0; k < INC; k++) acc += xs[r][k] * Ws[k * HID + c];
    int g = r0 + r;
    float dis = rsqrtf(deg[g] + 1.0f);
    xwp[(size_t)g * HID + c] = dis * acc;
}

// ---------------------------------------------------------------------------
__global__ __launch_bounds__(256) void agg_gather_kernel(
    const int* __restrict__ off_dst, const int* __restrict__ cnt_dst,
    const int* __restrict__ list_dst,
    const float* __restrict__ xwp, const float* __restrict__ deg,
    const float* __restrict__ bias, float* __restrict__ h) {
    int node = (blockIdx.x * blockDim.x + threadIdx.x) >> 5;
    int lane = threadIdx.x & 31;
    if (node >= TOT) return;
    int b = node >> 9;
    const float* xb = xwp + (((size_t)b << 9) << 5);
    int off = off_dst[node], cnt = cnt_dst[node];
    float acc = 0.f;
    int i = off, end = off + cnt;
    for (; i + 3 < end; i += 4) {
        int s0 = __ldg(&list_dst[i]),   s1 = __ldg(&list_dst[i + 1]);
        int s2 = __ldg(&list_dst[i + 2]), s3 = __ldg(&list_dst[i + 3]);
        acc += xb[(s0 << 5) + lane] + xb[(s1 << 5) + lane]
             + xb[(s2 << 5) + lane] + xb[(s3 << 5) + lane];
    }
    for (; i < end; i++) acc += xb[(__ldg(&list_dst[i]) << 5) + lane];
    float dis = rsqrtf(deg[node] + 1.0f);
    float xv = xwp[((size_t)node << 5) + lane];
    h[((size_t)node << 5) + lane] = fmaxf(dis * (acc + xv) + bias[lane], 0.f);
}

// ---------------------------------------------------------------------------
__global__ __launch_bounds__(256) void t1_gather_kernel(
    const int* __restrict__ off_src, const int* __restrict__ cnt_src,
    const int* __restrict__ list_src,
    const float* __restrict__ s1p, float* __restrict__ T1) {
    int node = (blockIdx.x * blockDim.x + threadIdx.x) >> 5;
    int lane = threadIdx.x & 31;
    if (node >= TOT) return;
    int b = node >> 9;
    const float4* sb = (const float4*)(s1p + (((size_t)b << 9) << 7)) + lane;
    int off = off_src[node], cnt = cnt_src[node];
    float4 acc = make_float4(0, 0, 0, 0);
    int i = off, end = off + cnt;
    for (; i + 3 < end; i += 4) {
        int d0 = __ldg(&list_src[i]),     d1 = __ldg(&list_src[i + 1]);
        int d2 = __ldg(&list_src[i + 2]), d3 = __ldg(&list_src[i + 3]);
        float4 v0 = __ldg(&sb[d0 << 5]);
        float4 v1 = __ldg(&sb[d1 << 5]);
        float4 v2 = __ldg(&sb[d2 << 5]);
        float4 v3 = __ldg(&sb[d3 << 5]);
        acc.x += (v0.x + v1.x) + (v2.x + v3.x);
        acc.y += (v0.y + v1.y) + (v2.y + v3.y);
        acc.z += (v0.z + v1.z) + (v2.z + v3.z);
        acc.w += (v0.w + v1.w) + (v2.w + v3.w);
    }
    for (; i < end; i++) {
        float4 v = __ldg(&sb[__ldg(&list_src[i]) << 5]);
        acc.x += v.x; acc.y += v.y; acc.z += v.z; acc.w += v.w;
    }
    ((float4*)(T1 + ((size_t)node << 7)))[lane] = acc;
}

// ---------------------------------------------------------------------------
// Fused Gram + x1 kernel: one block per graph, 320 threads.
//   t 0..168   : adjr1 = s1^T T1  (13x13 8x8 micro-blocks)
//   t 169..259 : ss1 = s1^T s1 upper triangle (91 blocks, mirrored)
//   t 260..311 : x1 = s1^T h     (13x4 blocks, cols 0..31)
//   t 312..319 : idle compute (results discarded)
// Uniform inner loop via per-thread B-operand smem pointer (no divergence).
// ---------------------------------------------------------------------------
__global__ __launch_bounds__(320) void gram_fused_kernel(
    const float* __restrict__ s1p, const float* __restrict__ T1,
    const float* __restrict__ h,
    float* __restrict__ adjr1, float* __restrict__ ss1, float* __restrict__ x1) {
    __shared__ float As[2][16][128];
    __shared__ float Bs[2][16][128];
    __shared__ float Hs[2][16][128];   // only cols 0..31 loaded/used
    int b = blockIdx.x;
    const float* A = s1p + ((size_t)b << 16);
    const float* B = T1 + ((size_t)b << 16);
    const float* H = h + ((size_t)b << 14);
    int tid = threadIdx.x;

    int sel, r, c;
    if (tid < 169) {
        sel = 0; r = tid / 13; c = tid - r * 13;
    } else if (tid < 260) {
        int u = tid - 169;
        int rr = 0, base = 0, nb = 13;
#pragma unroll
        for (int q = 0; q < 12; q++) {
            if (u >= nb) { rr = q + 1; base = nb; }
            nb += 12 - q;
        }
        sel = 1; r = rr; c = rr + (u - base);
    } else if (tid < 312) {
        int u = tid - 260;
        sel = 3; r = u >> 2; c = u & 3;
    } else {
        sel = 2; r = 0; c = 0;
    }

    // per-thread B-operand base pointers (uniform compute loop)
    const float* pBbuf0;
    const float* pBbuf1;
    if (sel == 1)      { pBbuf0 = &As[0][0][0]; pBbuf1 = &As[1][0][0]; }
    else if (sel == 3) { pBbuf0 = &Hs[0][0][0]; pBbuf1 = &Hs[1][0][0]; }
    else               { pBbuf0 = &Bs[0][0][0]; pBbuf1 = &Bs[1][0][0]; }
    int aoff = r * 8, boff = c * 8;

    bool loadAB = tid < 256;
    int lk0 = tid >> 5,         lj0 = (tid & 31) << 2;
    int lk1 = (tid + 256) >> 5, lj1 = ((tid + 256) & 31) << 2;
    bool loadH = tid >= 256;
    int ht = tid - 256;                       // 0..63
    int hk0 = ht >> 3,        hj0 = (ht & 7) << 2;
    int hk1 = (ht + 64) >> 3, hj1 = ((ht + 64) & 7) << 2;

    float4 pa0, pa1, pb0, pb1, ph0, ph1;
    if (loadAB) {
        pa0 = *(const float4*)(A + lk0 * KAP + lj0);
        pa1 = *(const float4*)(A + lk1 * KAP + lj1);
        pb0 = *(const float4*)(B + lk0 * KAP + lj0);
        pb1 = *(const float4*)(B + lk1 * KAP + lj1);
        *(float4*)&As[0][lk0][lj0] = pa0;
        *(float4*)&As[0][lk1][lj1] = pa1;
        *(float4*)&Bs[0][lk0][lj0] = pb0;
        *(float4*)&Bs[0][lk1][lj1] = pb1;
    }
    if (loadH) {
        ph0 = *(const float4*)(H + hk0 * HID + hj0);
        ph1 = *(const float4*)(H + hk1 * HID + hj1);
        *(float4*)&Hs[0][hk0][hj0] = ph0;
        *(float4*)&Hs[0][hk1][hj1] = ph1;
    }
    __syncthreads();

    float acc[8][8] = {};
    int cur = 0;
    for (int n0 = 0; n0 < NNODE; n0 += 16) {
        int nn = n0 + 16;
        if (nn < NNODE) {
            if (loadAB) {
                pa0 = *(const float4*)(A + (nn + lk0) * KAP + lj0);
                pa1 = *(const float4*)(A + (nn + lk1) * KAP + lj1);
                pb0 = *(const float4*)(B + (nn + lk0) * KAP + lj0);
                pb1 = *(const float4*)(B + (nn + lk1) * KAP + lj1);
            }
            if (loadH) {
                ph0 = *(const float4*)(H + (nn + hk0) * HID + hj0);
                ph1 = *(const float4*)(H + (nn + hk1) * HID + hj1);
            }
        }
        {
            const float* pA = &As[cur][0][0];
            const float* pB = cur ? pBbuf1 : pBbuf0;
#pragma unroll
            for (int kk = 0; kk < 16; kk++) {
                float4 a0 = *(const float4*)(pA + kk * 128 + aoff);
                float4 a1 = *(const float4*)(pA + kk * 128 + aoff + 4);
                float4 b0 = *(const float4*)(pB + kk * 128 + boff);
                float4 b1 = *(const float4*)(pB + kk * 128 + boff + 4);
                float a[8] = {a0.x, a0.y, a0.z, a0.w, a1.x, a1.y, a1.z, a1.w};
                float bv[8] = {b0.x, b0.y, b0.z, b0.w, b1.x, b1.y, b1.z, b1.w};
#pragma unroll
                for (int u = 0; u < 8; u++)
#pragma unroll
                    for (int v = 0; v < 8; v++) acc[u][v] += a[u] * bv[v];
            }
        }
        if (nn < NNODE) {
            int nx = cur ^ 1;
            if (loadAB) {
                *(float4*)&As[nx][lk0][lj0] = pa0;
                *(float4*)&As[nx][lk1][lj1] = pa1;
                *(float4*)&Bs[nx][lk0][lj0] = pb0;
                *(float4*)&Bs[nx][lk1][lj1] = pb1;
            }
            if (loadH) {
                *(float4*)&Hs[nx][hk0][hj0] = ph0;
                *(float4*)&Hs[nx][hk1][hj1] = ph1;
            }
            __syncthreads();
            cur = nx;
        }
    }

    if (sel == 0) {
        float* C = adjr1 + ((size_t)b << 14);
#pragma unroll
        for (int u = 0; u < 8; u++) {
            *(float4*)&C[(size_t)(r * 8 + u) * KAP + c * 8] =
                make_float4(acc[u][0], acc[u][1], acc[u][2], acc[u][3]);
            *(float4*)&C[(size_t)(r * 8 + u) * KAP + c * 8 + 4] =
                make_float4(acc[u][4], acc[u][5], acc[u][6], acc[u][7]);
        }
    } else if (sel == 1) {
        float* C = ss1 + ((size_t)b << 14);
#pragma unroll
        for (int u = 0; u < 8; u++) {
            *(float4*)&C[(size_t)(r * 8 + u) * KAP + c * 8] =
                make_float4(acc[u][0], acc[u][1], acc[u][2], acc[u][3]);
            *(float4*)&C[(size_t)(r * 8 + u) * KAP + c * 8 + 4] =
                make_float4(acc[u][4], acc[u][5], acc[u][6], acc[u][7]);
        }
        if (r != c) {
#pragma unroll
            for (int v = 0; v < 8; v++)
#pragma unroll
                for (int u = 0; u < 8; u++)
                    C[(size_t)(c * 8 + v) * KAP + r * 8 + u] = acc[u][v];
        }
    } else if (sel == 3) {
        float* C = x1 + (size_t)b * KA * HID;
#pragma unroll
        for (int u = 0; u < 8; u++) {
            int row = r * 8 + u;
            if (row < KA) {
                *(float4*)&C[(size_t)row * HID + c * 8] =
                    make_float4(acc[u][0], acc[u][1], acc[u][2], acc[u][3]);
                *(float4*)&C[(size_t)row * HID + c * 8 + 4] =
                    make_float4(acc[u][4], acc[u][5], acc[u][6], acc[u][7]);
            }
        }
    }
}

// ---------------------------------------------------------------------------
// stage-1 pooled softmax, 4 rows per iteration (validated R13).
// ---------------------------------------------------------------------------
__global__ __launch_bounds__(256) void pool_softmax1_kernel(
    const float* __restrict__ X, const float* __restrict__ W,
    const float* __restrict__ bias, float* __restrict__ Sout) {
    __shared__ float Ws[HID * KAP];
    __shared__ float bs[KAP];
    int tid = threadIdx.x;
    for (int t = tid; t < HID * KAP; t += 256) {
        int c = t >> 7, k = t & 127;
        Ws[t] = (k < KA) ? W[c * KA + k] : 0.f;
    }
    if (tid < KAP) bs[tid] = (tid < KA) ? bias[tid] : 0.f;
    __syncthreads();
    int lane = tid & 31, warp = tid >> 5;
    int row0 = blockIdx.x * 64 + warp * 8;
    float b0v = bs[lane], b1v = bs[32 + lane], b2v = bs[64 + lane], b3v = bs[96 + lane];
#pragma unroll 1
    for (int r = 0; r < 8; r += 4) {
        int row = row0 + r;
        float xv0 = X[(size_t)row * HID + lane];
        float xv1 = X[(size_t)(row + 1) * HID + lane];
        float xv2 = X[(size_t)(row + 2) * HID + lane];
        float xv3 = X[(size_t)(row + 3) * HID + lane];
        float a0 = b0v, a1 = b1v, a2 = b2v, a3 = b3v;
        float c0 = b0v, c1 = b1v, c2 = b2v, c3 = b3v;
        float d0 = b0v, d1 = b1v, d2 = b2v, d3 = b3v;
        float g0 = b0v, g1 = b1v, g2 = b2v, g3 = b3v;
#pragma unroll
        for (int c = 0; c < HID; c++) {
            float bx0 = __shfl_sync(0xffffffffu, xv0, c);
            float bx1 = __shfl_sync(0xffffffffu, xv1, c);
            float bx2 = __shfl_sync(0xffffffffu, xv2, c);
            float bx3 = __shfl_sync(0xffffffffu, xv3, c);
            const float* wr = Ws + (c << 7) + lane;
            float w0 = wr[0], w1 = wr[32], w2 = wr[64], w3 = wr[96];
            a0 += bx0 * w0; a1 += bx0 * w1; a2 += bx0 * w2; a3 += bx0 * w3;
            c0 += bx1 * w0; c1 += bx1 * w1; c2 += bx1 * w2; c3 += bx1 * w3;
            d0 += bx2 * w0; d1 += bx2 * w1; d2 += bx2 * w2; d3 += bx2 * w3;
            g0 += bx3 * w0; g1 += bx3 * w1; g2 += bx3 * w2; g3 += bx3 * w3;
        }
        bool v3 = (96 + lane < KA);
        float e0 = __expf(a0), e1 = __expf(a1), e2 = __expf(a2);
        float e3 = v3 ? __expf(a3) : 0.f;
        float f0 = __expf(c0), f1 = __expf(c1), f2 = __expf(c2);
        float f3 = v3 ? __expf(c3) : 0.f;
        float h0 = __expf(d0), h1 = __expf(d1), h2 = __expf(d2);
        float h3 = v3 ? __expf(d3) : 0.f;
        float k0 = __expf(g0), k1 = __expf(g1), k2 = __expf(g2);
        float k3 = v3 ? __expf(g3) : 0.f;
        float s0 = (e0 + e1) + (e2 + e3);
        float s1 = (f0 + f1) + (f2 + f3);
        float s2 = (h0 + h1) + (h2 + h3);
        float s3 = (k0 + k1) + (k2 + k3);
#pragma unroll
        for (int o = 16; o; o >>= 1) {
            s0 += __shfl_xor_sync(0xffffffffu, s0, o);
            s1 += __shfl_xor_sync(0xffffffffu, s1, o);
            s2 += __shfl_xor_sync(0xffffffffu, s2, o);
            s3 += __shfl_xor_sync(0xffffffffu, s3, o);
        }
        float i0 = __frcp_rn(s0), i1 = __frcp_rn(s1);
        float i2 = __frcp_rn(s2), i3 = __frcp_rn(s3);
        float* op0 = Sout + (size_t)row * KAP + lane;
        op0[0] = e0 * i0; op0[32] = e1 * i0; op0[64] = e2 * i0; op0[96] = e3 * i0;
        float* op1 = Sout + (size_t)(row + 1) * KAP + lane;
        op1[0] = f0 * i1; op1[32] = f1 * i1; op1[64] = f2 * i1; op1[96] = f3 * i1;
        float* op2 = Sout + (size_t)(row + 2) * KAP + lane;
        op2[0] = h0 * i2; op2[32] = h1 * i2; op2[64] = h2 * i2; op2[96] = h3 * i2;
        float* op3 = Sout + (size_t)(row + 3) * KAP + lane;
        op3[0] = k0 * i3; op3[32] = k1 * i3; op3[64] = k2 * i3; op3[96] = k3 * i3;
    }
}

// ---------------------------------------------------------------------------
__device__ __forceinline__ float blockReduce128(float v, float* sm) {
    int t = threadIdx.x;
    sm[t] = v;
    __syncthreads();
    for (int s = 64; s > 0; s >>= 1) {
        if (t < s) sm[t] += sm[t + s];
        __syncthreads();
    }
    float r = sm[0];
    __syncthreads();
    return r;
}

// level-1 loss + normalization (unchanged)
__global__ void loss_norm_kernel(const float* __restrict__ raw,
                                 const float* __restrict__ ss,
                                 const float* __restrict__ s,
                                 const float* __restrict__ dflat,
                                 float* __restrict__ adjn,
                                 float* __restrict__ dflat2,
                                 float* __restrict__ lossb,
                                 int k, int n, int ld, int ld_s, int bstride,
                                 int accum) {
    int b = blockIdx.x;
    raw  += (size_t)b * bstride;
    ss   += (size_t)b * bstride;
    s    += (size_t)b * n * ld_s;
    dflat+= (size_t)b * n;
    adjn += (size_t)b * k * k;
    dflat2 += (size_t)b * k;
    __shared__ float sm[128];
    __shared__ float idc[128];
    int tid = threadIdx.x;

    float v = 0.f;
    for (int i = tid; i < k; i += 128) v += raw[i * ld + i];
    float num = blockReduce128(v, sm);

    v = 0.f;
    for (int nn = tid; nn < n; nn += 128) {
        float dv = dflat[nn];
        float acc = 0.f;
        for (int kk = 0; kk < k; kk++) {
            float sv = s[(size_t)nn * ld_s + kk];
            acc += sv * sv;
        }
        v += acc * dv;
    }
    float den = blockReduce128(v, sm);

    v = 0.f;
    for (int i = tid; i < k; i += 128)
        for (int j = 0; j < k; j++) { float t = ss[i * ld + j]; v += t * t; }
    float nrm = sqrtf(blockReduce128(v, sm));

    float invn = 1.0f / nrm;
    float dk = rsqrtf((float)k);
    v = 0.f;
    for (int i = tid; i < k; i += 128)
        for (int j = 0; j < k; j++) {
            float t = ss[i * ld + j] * invn - ((i == j) ? dk : 0.f);
            v += t * t;
        }
    float ortho = sqrtf(blockReduce128(v, sm));

    for (int i = tid; i < k; i += 128) {
        float r = 0.f;
        for (int j = 0; j < k; j++) if (j != i) r += raw[i * ld + j];
        idc[i] = 1.0f / (sqrtf(r) + EPSV);
    }
    __syncthreads();
    for (int idx = tid; idx < k * k; idx += 128) {
        int i = idx / k, j = idx - i * k;
        adjn[idx] = (i == j) ? 0.f : raw[i * ld + j] * idc[i] * idc[j];
    }
    for (int i = tid; i < k; i += 128) {
        float r = 0.f;
        for (int j = 0; j < k; j++) if (j != i) r += raw[i * ld + j] * idc[j];
        dflat2[i] = r * idc[i];
    }
    if (tid == 0) {
        float val = -num / den + ortho;
        if (accum) lossb[b] += val; else lossb[b] = val;
    }
}

// ---------------------------------------------------------------------------
// Stage-2 mega kernel: conv2+relu, softmax2, TT2, adjr2/ss2/x3 (smem),
// then level-2 loss + pooled-adjacency normalize + conv3 + head, all in one.
// ---------------------------------------------------------------------------
__global__ __launch_bounds__(256) void stage2_mega_kernel(
    const float* __restrict__ adj1, const float* __restrict__ x1,
    const float* __restrict__ relW, const float* __restrict__ relb,
    const float* __restrict__ rootW,
    const float* __restrict__ p2W, const float* __restrict__ p2b,
    const float* __restrict__ dflat2g, float* __restrict__ lossb,
    const float* __restrict__ c3rW, const float* __restrict__ c3rb,
    const float* __restrict__ c3oW,
    const float* __restrict__ l1W, const float* __restrict__ l1b,
    const float* __restrict__ l2W, const float* __restrict__ l2b,
    float* __restrict__ out) {
    extern __shared__ float sm[];
    float* adj1s = sm;             // 10000
    float* x1s   = sm + 10000;     // 3200
    float* relWs = sm + 13200;     // 1024
    float* rootWs= sm + 14224;     // 1024
    float* p2Ws  = sm + 15248;     // 320
    float* x2s   = sm + 15568;     // 3200
    float* s2s   = sm + 18768;     // 1000
    float* tt2s  = sm + 19768;     // 1000
    float* adjr2s= sm + 20768;     // 100
    float* ss2s  = sm + 20868;     // 100
    float* adj2s = sm + 20968;     // 100
    float* idcs  = sm + 21068;     // 16
    float* x3s   = sm + 21084;     // 320  -> total 21404 floats
    int b = blockIdx.x, tid = threadIdx.x;
    const float* A = adj1 + (size_t)b * KA * KA;
    const float* X = x1 + (size_t)b * KA * HID;
    for (int i = tid; i < KA * KA; i += 256) adj1s[i] = A[i];
    for (int i = tid; i < KA * HID; i += 256) x1s[i] = X[i];
    for (int i = tid; i < HID * HID; i += 256) { relWs[i] = relW[i]; rootWs[i] = rootW[i]; }
    for (int i = tid; i < HID * KB; i += 256) p2Ws[i] = p2W[i];
    __syncthreads();
    int lane = tid & 31, warp = tid >> 5;
    float rb = relb[lane];
    int kk10 = lane < KB ? lane : 0;
    float p2bv = p2b[kk10];
    for (int i = warp; i < KA; i += 8) {
        float t2 = 0.f;
        const float* ar = adj1s + i * KA;
        for (int m = 0; m < KA; m++) t2 += ar[m] * x1s[(m << 5) + lane];
        float x1v = x1s[(i << 5) + lane];
        float a = rb;
#pragma unroll
        for (int k = 0; k < 32; k++)
            a += __shfl_sync(0xffffffffu, t2, k) * relWs[(k << 5) + lane]
               + __shfl_sync(0xffffffffu, x1v, k) * rootWs[(k << 5) + lane];
        float x2v = fmaxf(a, 0.f);
        x2s[(i << 5) + lane] = x2v;
        float zz = p2bv;
#pragma unroll
        for (int c = 0; c < 32; c++)
            zz += __shfl_sync(0xffffffffu, x2v, c) * p2Ws[c * KB + kk10];
        float e = (lane < KB) ? __expf(zz) : 0.f;
        float ssum = e;
#pragma unroll
        for (int o = 16; o; o >>= 1) ssum += __shfl_xor_sync(0xffffffffu, ssum, o);
        if (lane < KB) s2s[i * KB + lane] = e / ssum;
    }
    __syncthreads();
    for (int t = tid; t < KA * KB; t += 256) {
        int i = t / KB, k = t - i * KB;
        float a = 0.f;
        const float* ar = adj1s + i * KA;
        for (int m = 0; m < KA; m++) a += ar[m] * s2s[m * KB + k];
        tt2s[t] = a;
    }
    __syncthreads();
    for (int t = tid; t < 520; t += 256) {
        if (t < 100) {
            int i = t / 10, j = t - i * 10;
            float a = 0.f;
            for (int n = 0; n < KA; n++) a += s2s[n * KB + i] * tt2s[n * KB + j];
            adjr2s[t] = a;
        } else if (t < 200) {
            int u = t - 100;
            int i = u / 10, j = u - i * 10;
            float a = 0.f;
            for (int n = 0; n < KA; n++) a += s2s[n * KB + i] * s2s[n * KB + j];
            ss2s[u] = a;
        } else {
            int u = t - 200;
            int i = u >> 5, c = u & 31;
            float a = 0.f;
            for (int n = 0; n < KA; n++) a += s2s[n * KB + i] * x2s[(n << 5) + c];
            x3s[u] = a;
        }
    }
    __syncthreads();

    if (tid < 32) {
        const float* df = dflat2g + (size_t)b * KA;
        // mincut num = trace(adjr2)
        float v = (lane < KB) ? adjr2s[lane * KB + lane] : 0.f;
#pragma unroll
        for (int o = 16; o; o >>= 1) v += __shfl_xor_sync(0xffffffffu, v, o);
        float num = v;
        // den = sum_n dflat2[n] * sum_k s2[n][k]^2
        v = 0.f;
        for (int n = lane; n < KA; n += 32) {
            float acc = 0.f;
#pragma unroll
            for (int k = 0; k < KB; k++) { float sv = s2s[n * KB + k]; acc += sv * sv; }
            v += acc * df[n];
        }
#pragma unroll
        for (int o = 16; o; o >>= 1) v += __shfl_xor_sync(0xffffffffu, v, o);
        float den = v;
        // ||ss2||_F
        v = 0.f;
        for (int t = lane; t < 100; t += 32) { float q = ss2s[t]; v += q * q; }
#pragma unroll
        for (int o = 16; o; o >>= 1) v += __shfl_xor_sync(0xffffffffu, v, o);
        float nrm = sqrtf(v);
        float invn = 1.0f / nrm;
        float dk = rsqrtf((float)KB);
        v = 0.f;
        for (int t = lane; t < 100; t += 32) {
            int i = t / 10, j = t - i * 10;
            float q = ss2s[t] * invn - ((i == j) ? dk : 0.f);
            v += q * q;
        }
#pragma unroll
        for (int o = 16; o; o >>= 1) v += __shfl_xor_sync(0xffffffffu, v, o);
        float ortho = sqrtf(v);
        // idc + adj2
        if (lane < KB) {
            float rsum = 0.f;
            for (int j = 0; j < KB; j++) if (j != lane) rsum += adjr2s[lane * KB + j];
            idcs[lane] = 1.0f / (sqrtf(rsum) + EPSV);
        }
        __syncwarp();
        for (int t = lane; t < 100; t += 32) {
            int i = t / 10, j = t - i * 10;
            adj2s[t] = (i == j) ? 0.f : adjr2s[t] * idcs[i] * idcs[j];
        }
        if (lane == 0) lossb[b] += -num / den + ortho;
        __syncwarp();

        // ---- tail: conv3 + mean + lin1 relu + lin2 + log_softmax ----
        float x3c[10], t3c[10];
#pragma unroll
        for (int j = 0; j < 10; j++) x3c[j] = x3s[j * 32 + lane];
#pragma unroll
        for (int i = 0; i < 10; i++) {
            float a = 0.f;
#pragma unroll
            for (int j = 0; j < 10; j++) a += adj2s[i * 10 + j] * x3c[j];
            t3c[i] = a;
        }
        float rb3 = c3rb[lane];
        float g = 0.f;
#pragma unroll
        for (int i = 0; i < 10; i++) {
            float a = rb3;
#pragma unroll
            for (int k = 0; k < 32; k++)
                a += __shfl_sync(0xffffffffu, t3c[i], k) * c3rW[k * 32 + lane]
                   + __shfl_sync(0xffffffffu, x3c[i], k) * c3oW[k * 32 + lane];
            g += a;
        }
        g *= 0.1f;
        float a1 = l1b[lane];
#pragma unroll
        for (int k = 0; k < 32; k++) a1 += __shfl_sync(0xffffffffu, g, k) * l1W[k * 32 + lane];
        float gg = fmaxf(a1, 0.f);
        float a2 = l2b[kk10];
#pragma unroll
        for (int k = 0; k < 32; k++) a2 += __shfl_sync(0xffffffffu, gg, k) * l2W[k * OC + kk10];
        float val = (lane < OC) ? a2 : -INFINITY;
        float m = val;
#pragma unroll
        for (int o = 16; o; o >>= 1) m = fmaxf(m, __shfl_xor_sync(0xffffffffu, m, o));
        float e = (lane < OC) ? __expf(val - m) : 0.f;
        float ssum = e;
#pragma unroll
        for (int o = 16; o; o >>= 1) ssum += __shfl_xor_sync(0xffffffffu, ssum, o);
        if (lane < OC) out[b * OC + lane] = val - m - logf(ssum);
    }
}

__global__ void final_kernel(const float* __restrict__ lossb, float* __restrict__ out,
                             int out_size) {
    __shared__ float sm[128];
    int t = threadIdx.x;
    sm[t] = lossb[t];
    __syncthreads();
    for (int s = 64; s > 0; s >>= 1) {
        if (t < s) sm[t] += sm[t + s];
        __syncthreads();
    }
    if (t == 0 && out_size > BATCH * OC) out[BATCH * OC] = sm[0] / (float)BATCH;
}

// ---------------------------------------------------------------------------
extern "C" void kernel_launch(void* const* d_in, const int* in_sizes, int n_in,
                              void* d_out, int out_size) {
    const float* x    = (const float*)d_in[0];
    const int*   ei   = (const int*)  d_in[1];
    const float* c1W  = (const float*)d_in[3];
    const float* c1b  = (const float*)d_in[4];
    const float* p1W  = (const float*)d_in[5];
    const float* p1b  = (const float*)d_in[6];
    const float* c2rW = (const float*)d_in[7];
    const float* c2rb = (const float*)d_in[8];
    const float* c2oW = (const float*)d_in[9];
    const float* p2W  = (const float*)d_in[10];
    const float* p2b  = (const float*)d_in[11];
    const float* c3rW = (const float*)d_in[12];
    const float* c3rb = (const float*)d_in[13];
    const float* c3oW = (const float*)d_in[14];
    const float* l1W  = (const float*)d_in[15];
    const float* l1b  = (const float*)d_in[16];
    const float* l2W  = (const float*)d_in[17];
    const float* l2b  = (const float*)d_in[18];
    float* out = (float*)d_out;
    int E = in_sizes[1] / 2;
    int eper = E / BATCH;

    void* sp = nullptr;
    cudaGetSymbolAddress(&sp, g_scratch);
    float* S = (float*)sp;
    int *csn, *cdn, *osn, *odn, *lsrc, *ldst;
    cudaGetSymbolAddress((void**)&csn, g_cnt_src);
    cudaGetSymbolAddress((void**)&cdn, g_cnt_dst);
    cudaGetSymbolAddress((void**)&osn, g_off_src);
    cudaGetSymbolAddress((void**)&odn, g_off_dst);
    cudaGetSymbolAddress((void**)&lsrc, g_list_src);
    cudaGetSymbolAddress((void**)&ldst, g_list_dst);

    cudaFuncSetAttribute(stage2_mega_kernel, cudaFuncAttributeMaxDynamicSharedMemorySize, 85632);

    build_csr_kernel<<<BATCH, 512>>>(ei, E, eper, osn, csn, odn, cdn, lsrc, ldst,
                                     S + OFF_DEG, S + OFF_DFLAT);
    xwp_kernel<<<TOT / 8, dim3(32, 8)>>>(x, c1W, S + OFF_DEG, S + OFF_XWP);
    agg_gather_kernel<<<TOT * 32 / 256, 256>>>(odn, cdn, ldst, S + OFF_XWP,
                                               S + OFF_DEG, c1b, S + OFF_H);
    pool_softmax1_kernel<<<TOT / 64, 256>>>(S + OFF_H, p1W, p1b, S + OFF_S1);
    t1_gather_kernel<<<TOT * 32 / 256, 256>>>(osn, csn, lsrc, S + OFF_S1, S + OFF_T1);
    gram_fused_kernel<<<BATCH, 320>>>(S + OFF_S1, S + OFF_T1, S + OFF_H,
                                      S + OFF_ADJR1, S + OFF_SS1, S + OFF_X1);
    loss_norm_kernel<<<BATCH, 128>>>(S + OFF_ADJR1, S + OFF_SS1, S + OFF_S1, S + OFF_DFLAT,
                                     S + OFF_ADJ1, S + OFF_DFLAT2, S + OFF_LOSSB,
                                     KA, NNODE, KAP, KAP, KAP * KAP, 0);
    stage2_mega_kernel<<<BATCH, 256, 85632>>>(S + OFF_ADJ1, S + OFF_X1, c2rW, c2rb, c2oW,
                                              p2W, p2b, S + OFF_DFLAT2, S + OFF_LOSSB,
                                              c3rW, c3rb, c3oW, l1W, l1b, l2W, l2b, out);
    final_kernel<<<1, 128>>>(S + OFF_LOSSB, out, out_size);
}

// round 15
// speedup vs baseline: 1.4095x; 1.0804x over previous
#include <cuda_runtime.h>
#include <math.h>
#include <stdint.h>

namespace {
constexpr int BATCH = 128, NNODE = 512, INC = 128, HID = 32, KA = 100, KB = 10, OC = 10;
constexpr int KAP = 128;
constexpr int TOT = BATCH * NNODE;
constexpr int MAXE = BATCH * 8192;
constexpr float EPSV = 1e-15f;

constexpr size_t OFF_DEG    = 0;
constexpr size_t OFF_DFLAT  = OFF_DEG + TOT;
constexpr size_t OFF_LOSSB  = OFF_DFLAT + TOT;
constexpr size_t OFF_XWP    = OFF_LOSSB + BATCH;
constexpr size_t OFF_H      = OFF_XWP   + (size_t)TOT * HID;
constexpr size_t OFF_S1     = OFF_H     + (size_t)TOT * HID;
constexpr size_t OFF_T1     = OFF_S1    + (size_t)TOT * KAP;
constexpr size_t OFF_X1     = OFF_T1    + (size_t)TOT * KAP;
constexpr size_t OFF_ADJ1   = OFF_X1    + (size_t)BATCH * KA * HID;
constexpr size_t OFF_DFLAT2 = OFF_ADJ1  + (size_t)BATCH * KA * KA;
constexpr size_t SCRATCH_TOTAL = OFF_DFLAT2 + (size_t)BATCH * KA;
}  // namespace

__device__ __align__(16) float g_scratch[SCRATCH_TOTAL];
__device__ __align__(16) int g_cnt_src[TOT];
__device__ __align__(16) int g_cnt_dst[TOT];
__device__ __align__(16) int g_off_src[TOT];
__device__ __align__(16) int g_off_dst[TOT];
__device__ __align__(16) int g_list_src[MAXE];
__device__ __align__(16) int g_list_dst[MAXE];

// ---------------------------------------------------------------------------
// Fused CSR build
// ---------------------------------------------------------------------------
__global__ __launch_bounds__(512) void build_csr_kernel(
    const int* __restrict__ ei, int E, int eper,
    int* __restrict__ off_src, int* __restrict__ cnt_src,
    int* __restrict__ off_dst, int* __restrict__ cnt_dst,
    int* __restrict__ list_src, int* __restrict__ list_dst,
    float* __restrict__ deg, float* __restrict__ dflat) {
    __shared__ int sc[512], sd[512], sscan[512];
    __shared__ int csrc[512], cdst[512];
    int b = blockIdx.x, tid = threadIdx.x;
    sc[tid] = 0; sd[tid] = 0;
    __syncthreads();
    const int* se = ei + (size_t)b * eper;
    const int* de = ei + E + (size_t)b * eper;
    for (int e = tid; e < eper; e += 512) {
        atomicAdd(&sc[se[e] & 511], 1);
        atomicAdd(&sd[de[e] & 511], 1);
    }
    __syncthreads();
    int vs = sc[tid], vd = sd[tid];
    int g = (b << 9) + tid;
    int base = b * eper;
    dflat[g] = (float)vs;
    deg[g]   = (float)vd;
    cnt_src[g] = vs;
    cnt_dst[g] = vd;
    sscan[tid] = vs; __syncthreads();
    for (int o = 1; o < 512; o <<= 1) {
        int t = (tid >= o) ? sscan[tid - o] : 0;
        __syncthreads(); sscan[tid] += t; __syncthreads();
    }
    int es = base + sscan[tid] - vs;
    off_src[g] = es; csrc[tid] = es;
    __syncthreads();
    sscan[tid] = vd; __syncthreads();
    for (int o = 1; o < 512; o <<= 1) {
        int t = (tid >= o) ? sscan[tid - o] : 0;
        __syncthreads(); sscan[tid] += t; __syncthreads();
    }
    int ed = base + sscan[tid] - vd;
    off_dst[g] = ed; cdst[tid] = ed;
    __syncthreads();
    for (int e = tid; e < eper; e += 512) {
        int s = se[e] & 511, d = de[e] & 511;
        int p = atomicAdd(&csrc[s], 1);
        list_src[p] = d;
        int q = atomicAdd(&cdst[d], 1);
        list_dst[q] = s;
    }
}

// ---------------------------------------------------------------------------
__global__ __launch_bounds__(256) void xwp_kernel(const float* __restrict__ x,
                                                  const float* __restrict__ W,
                                                  const float* __restrict__ deg,
                                                  float* __restrict__ xwp) {
    __shared__ float Ws[INC * HID];
    __shared__ float xs[8][INC];
    int tid = threadIdx.y * 32 + threadIdx.x;
    for (int t = tid; t < INC * HID; t += 256) Ws[t] = W[t];
    int r0 = blockIdx.x * 8;
    for (int t = tid; t < 8 * INC; t += 256) {
        int r = t >> 7, k = t & 127;
        xs[r][k] = x[(size_t)(r0 + r) * INC + k];
    }
    __syncthreads();
    int c = threadIdx.x, r = threadIdx.y;
    float acc = 0.f;
#pragma unroll 8
    for (int k = 0; k < INC; k++) acc += xs[r][k] * Ws[k * HID + c];
    int g = r0 + r;
    float dis = rsqrtf(deg[g] + 1.0f);
    xwp[(size_t)g * HID + c] = dis * acc;
}

// ---------------------------------------------------------------------------
// Fused GCN aggregate + stage-1 pooled softmax.
// Grid 1024; block = 64 rows (one graph). Per 4 rows: gather h (written to
// global, bit-identical to the old agg kernel), then the validated 4-row
// softmax on the register-resident h values.
// ---------------------------------------------------------------------------
__global__ __launch_bounds__(256) void agg_softmax_kernel(
    const int* __restrict__ off_dst, const int* __restrict__ cnt_dst,
    const int* __restrict__ list_dst,
    const float* __restrict__ xwp, const float* __restrict__ deg,
    const float* __restrict__ c1b,
    const float* __restrict__ W, const float* __restrict__ bias,
    float* __restrict__ h, float* __restrict__ Sout) {
    __shared__ float Ws[HID * KAP];
    __shared__ float bs[KAP];
    int tid = threadIdx.x;
    for (int t = tid; t < HID * KAP; t += 256) {
        int c = t >> 7, k = t & 127;
        Ws[t] = (k < KA) ? W[c * KA + k] : 0.f;
    }
    if (tid < KAP) bs[tid] = (tid < KA) ? bias[tid] : 0.f;
    __syncthreads();
    int lane = tid & 31, warp = tid >> 5;
    int row0 = blockIdx.x * 64 + warp * 8;
    int b = blockIdx.x >> 3;
    const float* xb = xwp + ((size_t)b << 14);
    float c1bv = c1b[lane];
    float b0v = bs[lane], b1v = bs[32 + lane], b2v = bs[64 + lane], b3v = bs[96 + lane];
#pragma unroll 1
    for (int r = 0; r < 8; r += 4) {
        float hv[4];
#pragma unroll 1
        for (int q = 0; q < 4; q++) {
            int node = row0 + r + q;
            int off = off_dst[node], cnt = cnt_dst[node];
            float acc = 0.f;
            int i = off, end = off + cnt;
            for (; i + 3 < end; i += 4) {
                int s0 = __ldg(&list_dst[i]),     s1 = __ldg(&list_dst[i + 1]);
                int s2 = __ldg(&list_dst[i + 2]), s3 = __ldg(&list_dst[i + 3]);
                acc += xb[(s0 << 5) + lane] + xb[(s1 << 5) + lane]
                     + xb[(s2 << 5) + lane] + xb[(s3 << 5) + lane];
            }
            for (; i < end; i++) acc += xb[(__ldg(&list_dst[i]) << 5) + lane];
            float dis = rsqrtf(deg[node] + 1.0f);
            float xv = xwp[((size_t)node << 5) + lane];
            float v = fmaxf(dis * (acc + xv) + c1bv, 0.f);
            hv[q] = v;
            h[((size_t)node << 5) + lane] = v;
        }
        int row = row0 + r;
        float xv0 = hv[0], xv1 = hv[1], xv2 = hv[2], xv3 = hv[3];
        float a0 = b0v, a1 = b1v, a2 = b2v, a3 = b3v;
        float c0 = b0v, c1 = b1v, c2 = b2v, c3 = b3v;
        float d0 = b0v, d1 = b1v, d2 = b2v, d3 = b3v;
        float g0 = b0v, g1 = b1v, g2 = b2v, g3 = b3v;
#pragma unroll
        for (int c = 0; c < HID; c++) {
            float bx0 = __shfl_sync(0xffffffffu, xv0, c);
            float bx1 = __shfl_sync(0xffffffffu, xv1, c);
            float bx2 = __shfl_sync(0xffffffffu, xv2, c);
            float bx3 = __shfl_sync(0xffffffffu, xv3, c);
            const float* wr = Ws + (c << 7) + lane;
            float w0 = wr[0], w1 = wr[32], w2 = wr[64], w3 = wr[96];
            a0 += bx0 * w0; a1 += bx0 * w1; a2 += bx0 * w2; a3 += bx0 * w3;
            c0 += bx1 * w0; c1 += bx1 * w1; c2 += bx1 * w2; c3 += bx1 * w3;
            d0 += bx2 * w0; d1 += bx2 * w1; d2 += bx2 * w2; d3 += bx2 * w3;
            g0 += bx3 * w0; g1 += bx3 * w1; g2 += bx3 * w2; g3 += bx3 * w3;
        }
        bool v3 = (96 + lane < KA);
        float e0 = __expf(a0), e1 = __expf(a1), e2 = __expf(a2);
        float e3 = v3 ? __expf(a3) : 0.f;
        float f0 = __expf(c0), f1 = __expf(c1), f2 = __expf(c2);
        float f3 = v3 ? __expf(c3) : 0.f;
        float h0 = __expf(d0), h1 = __expf(d1), h2 = __expf(d2);
        float h3 = v3 ? __expf(d3) : 0.f;
        float k0 = __expf(g0), k1 = __expf(g1), k2 = __expf(g2);
        float k3 = v3 ? __expf(g3) : 0.f;
        float s0 = (e0 + e1) + (e2 + e3);
        float s1 = (f0 + f1) + (f2 + f3);
        float s2 = (h0 + h1) + (h2 + h3);
        float s3 = (k0 + k1) + (k2 + k3);
#pragma unroll
        for (int o = 16; o; o >>= 1) {
            s0 += __shfl_xor_sync(0xffffffffu, s0, o);
            s1 += __shfl_xor_sync(0xffffffffu, s1, o);
            s2 += __shfl_xor_sync(0xffffffffu, s2, o);
            s3 += __shfl_xor_sync(0xffffffffu, s3, o);
        }
        float i0 = __frcp_rn(s0), i1 = __frcp_rn(s1);
        float i2 = __frcp_rn(s2), i3 = __frcp_rn(s3);
        float* op0 = Sout + (size_t)row * KAP + lane;
        op0[0] = e0 * i0; op0[32] = e1 * i0; op0[64] = e2 * i0; op0[96] = e3 * i0;
        float* op1 = Sout + (size_t)(row + 1) * KAP + lane;
        op1[0] = f0 * i1; op1[32] = f1 * i1; op1[64] = f2 * i1; op1[96] = f3 * i1;
        float* op2 = Sout + (size_t)(row + 2) * KAP + lane;
        op2[0] = h0 * i2; op2[32] = h1 * i2; op2[64] = h2 * i2; op2[96] = h3 * i2;
        float* op3 = Sout + (size_t)(row + 3) * KAP + lane;
        op3[0] = k0 * i3; op3[32] = k1 * i3; op3[64] = k2 * i3; op3[96] = k3 * i3;
    }
}

// ---------------------------------------------------------------------------
__global__ __launch_bounds__(256) void t1_gather_kernel(
    const int* __restrict__ off_src, const int* __restrict__ cnt_src,
    const int* __restrict__ list_src,
    const float* __restrict__ s1p, float* __restrict__ T1) {
    int node = (blockIdx.x * blockDim.x + threadIdx.x) >> 5;
    int lane = threadIdx.x & 31;
    if (node >= TOT) return;
    int b = node >> 9;
    const float4* sb = (const float4*)(s1p + (((size_t)b << 9) << 7)) + lane;
    int off = off_src[node], cnt = cnt_src[node];
    float4 acc = make_float4(0, 0, 0, 0);
    int i = off, end = off + cnt;
    for (; i + 3 < end; i += 4) {
        int d0 = __ldg(&list_src[i]),     d1 = __ldg(&list_src[i + 1]);
        int d2 = __ldg(&list_src[i + 2]), d3 = __ldg(&list_src[i + 3]);
        float4 v0 = __ldg(&sb[d0 << 5]);
        float4 v1 = __ldg(&sb[d1 << 5]);
        float4 v2 = __ldg(&sb[d2 << 5]);
        float4 v3 = __ldg(&sb[d3 << 5]);
        acc.x += (v0.x + v1.x) + (v2.x + v3.x);
        acc.y += (v0.y + v1.y) + (v2.y + v3.y);
        acc.z += (v0.z + v1.z) + (v2.z + v3.z);
        acc.w += (v0.w + v1.w) + (v2.w + v3.w);
    }
    for (; i < end; i++) {
        float4 v = __ldg(&sb[__ldg(&list_src[i]) << 5]);
        acc.x += v.x; acc.y += v.y; acc.z += v.z; acc.w += v.w;
    }
    ((float4*)(T1 + ((size_t)node << 7)))[lane] = acc;
}

// ---------------------------------------------------------------------------
// Fused Gram + x1 + level-1 loss/normalize kernel. One block per graph,
// 320 threads, 48 KB dynamic smem (tiles aliased for post-phase scratch).
//   t 0..168   : adjr1 blocks    t 169..259 : ss1 upper triangle
//   t 260..311 : x1 blocks       t 312..319 : idle compute
// Post phase: deterministic staged reductions -> mincut+ortho loss,
// normalized adj1 (100x100), dflat2. adjr1/ss1 never hit global memory.
// ---------------------------------------------------------------------------
__global__ __launch_bounds__(320) void gram_fused_kernel(
    const float* __restrict__ s1p, const float* __restrict__ T1,
    const float* __restrict__ h, const float* __restrict__ dflat,
    float* __restrict__ adj1, float* __restrict__ x1,
    float* __restrict__ dflat2, float* __restrict__ lossb) {
    extern __shared__ float dyn[];
    float* AsD = dyn;           // 2*16*128
    float* BsD = dyn + 4096;
    float* HsD = dyn + 8192;
    // post-phase aliases (valid after tiles are dead)
    float* psum  = dyn;          // 104*13
    float* diagv = dyn + 1360;   // 104
    float* idcs  = dyn + 1472;   // 104
    float* stat  = dyn + 1584;   // 91*2 (fro, tr)
    float* denp  = dyn + 1776;   // 128
    float* redv  = dyn + 1920;   // 4

    int b = blockIdx.x;
    const float* A = s1p + ((size_t)b << 16);
    const float* B = T1 + ((size_t)b << 16);
    const float* H = h + ((size_t)b << 14);
    int tid = threadIdx.x;

    int sel, r, c;
    if (tid < 169) {
        sel = 0; r = tid / 13; c = tid - r * 13;
    } else if (tid < 260) {
        int u = tid - 169;
        int rr = 0, base = 0, nb = 13;
#pragma unroll
        for (int q = 0; q < 12; q++) {
            if (u >= nb) { rr = q + 1; base = nb; }
            nb += 12 - q;
        }
        sel = 1; r = rr; c = rr + (u - base);
    } else if (tid < 312) {
        int u = tid - 260;
        sel = 3; r = u >> 2; c = u & 3;
    } else {
        sel = 2; r = 0; c = 0;
    }

    const float* pBbuf0;
    const float* pBbuf1;
    if (sel == 1)      { pBbuf0 = AsD; pBbuf1 = AsD + 2048; }
    else if (sel == 3) { pBbuf0 = HsD; pBbuf1 = HsD + 2048; }
    else               { pBbuf0 = BsD; pBbuf1 = BsD + 2048; }
    int aoff = r * 8, boff = c * 8;

    bool loadAB = tid < 256;
    int lk0 = tid >> 5,         lj0 = (tid & 31) << 2;
    int lk1 = (tid + 256) >> 5, lj1 = ((tid + 256) & 31) << 2;
    bool loadH = tid >= 256;
    int ht = tid - 256;
    int hk0 = ht >> 3,        hj0 = (ht & 7) << 2;
    int hk1 = (ht + 64) >> 3, hj1 = ((ht + 64) & 7) << 2;

    float4 pa0, pa1, pb0, pb1, ph0, ph1;
    if (loadAB) {
        pa0 = *(const float4*)(A + lk0 * KAP + lj0);
        pa1 = *(const float4*)(A + lk1 * KAP + lj1);
        pb0 = *(const float4*)(B + lk0 * KAP + lj0);
        pb1 = *(const float4*)(B + lk1 * KAP + lj1);
        *(float4*)&AsD[lk0 * 128 + lj0] = pa0;
        *(float4*)&AsD[lk1 * 128 + lj1] = pa1;
        *(float4*)&BsD[lk0 * 128 + lj0] = pb0;
        *(float4*)&BsD[lk1 * 128 + lj1] = pb1;
    }
    if (loadH) {
        ph0 = *(const float4*)(H + hk0 * HID + hj0);
        ph1 = *(const float4*)(H + hk1 * HID + hj1);
        *(float4*)&HsD[hk0 * 128 + hj0] = ph0;
        *(float4*)&HsD[hk1 * 128 + hj1] = ph1;
    }
    __syncthreads();

    float acc[8][8] = {};
    int cur = 0;
    for (int n0 = 0; n0 < NNODE; n0 += 16) {
        int nn = n0 + 16;
        if (nn < NNODE) {
            if (loadAB) {
                pa0 = *(const float4*)(A + (nn + lk0) * KAP + lj0);
                pa1 = *(const float4*)(A + (nn + lk1) * KAP + lj1);
                pb0 = *(const float4*)(B + (nn + lk0) * KAP + lj0);
                pb1 = *(const float4*)(B + (nn + lk1) * KAP + lj1);
            }
            if (loadH) {
                ph0 = *(const float4*)(H + (nn + hk0) * HID + hj0);
                ph1 = *(const float4*)(H + (nn + hk1) * HID + hj1);
            }
        }
        {
            const float* pA = AsD + cur * 2048;
            const float* pB = cur ? pBbuf1 : pBbuf0;
#pragma unroll
            for (int kk = 0; kk < 16; kk++) {
                float4 a0 = *(const float4*)(pA + kk * 128 + aoff);
                float4 a1 = *(const float4*)(pA + kk * 128 + aoff + 4);
                float4 b0 = *(const float4*)(pB + kk * 128 + boff);
                float4 b1 = *(const float4*)(pB + kk * 128 + boff + 4);
                float a[8] = {a0.x, a0.y, a0.z, a0.w, a1.x, a1.y, a1.z, a1.w};
                float bv[8] = {b0.x, b0.y, b0.z, b0.w, b1.x, b1.y, b1.z, b1.w};
#pragma unroll
                for (int u = 0; u < 8; u++)
#pragma unroll
                    for (int v = 0; v < 8; v++) acc[u][v] += a[u] * bv[v];
            }
        }
        if (nn < NNODE) {
            int nx = cur ^ 1;
            if (loadAB) {
                *(float4*)&AsD[nx * 2048 + lk0 * 128 + lj0] = pa0;
                *(float4*)&AsD[nx * 2048 + lk1 * 128 + lj1] = pa1;
                *(float4*)&BsD[nx * 2048 + lk0 * 128 + lj0] = pb0;
                *(float4*)&BsD[nx * 2048 + lk1 * 128 + lj1] = pb1;
            }
            if (loadH) {
                *(float4*)&HsD[nx * 2048 + hk0 * 128 + hj0] = ph0;
                *(float4*)&HsD[nx * 2048 + hk1 * 128 + hj1] = ph1;
            }
            __syncthreads();
            cur = nx;
        }
    }
    __syncthreads();   // tiles dead; smem now post-phase scratch

    // x1 output (unchanged, bit-exact)
    if (sel == 3) {
        float* C = x1 + (size_t)b * KA * HID;
#pragma unroll
        for (int u = 0; u < 8; u++) {
            int row = r * 8 + u;
            if (row < KA) {
                *(float4*)&C[(size_t)row * HID + c * 8] =
                    make_float4(acc[u][0], acc[u][1], acc[u][2], acc[u][3]);
                *(float4*)&C[(size_t)row * HID + c * 8 + 4] =
                    make_float4(acc[u][4], acc[u][5], acc[u][6], acc[u][7]);
            }
        }
    }
    // Phase A: adjr1 row partials + diagonal
    if (sel == 0) {
#pragma unroll
        for (int u = 0; u < 8; u++) {
            float s = 0.f;
#pragma unroll
            for (int v = 0; v < 8; v++) s += acc[u][v];
            psum[(r * 8 + u) * 13 + c] = s;
        }
        if (r == c) {
#pragma unroll
            for (int u = 0; u < 8; u++) diagv[r * 8 + u] = acc[u][u];
        }
    }
    // Phase C: ss1 stats (Frobenius^2 partial, trace partial)
    if (sel == 1) {
        float fro = 0.f;
#pragma unroll
        for (int u = 0; u < 8; u++)
#pragma unroll
            for (int v = 0; v < 8; v++) fro += acc[u][v] * acc[u][v];
        if (r != c) fro *= 2.f;
        float tr = 0.f;
        if (r == c) {
#pragma unroll
            for (int u = 0; u < 8; u++) tr += acc[u][u];
        }
        int idx = tid - 169;
        stat[2 * idx] = fro;
        stat[2 * idx + 1] = tr;
    }
    // Phase D: den partials (re-read s1 from L2)
    if (tid < 128) {
        const float* df = dflat + ((size_t)b << 9);
        float v = 0.f;
        for (int n = tid; n < NNODE; n += 128) {
            const float* srow = A + (size_t)n * KAP;
            float a2 = 0.f;
            for (int k = 0; k < KAP; k++) { float sv = srow[k]; a2 += sv * sv; }
            v += a2 * df[n];
        }
        denp[tid] = v;
    }
    __syncthreads();

    // Phase B: per-row idc
    if (tid < 104) {
        float rf = 0.f;
#pragma unroll
        for (int cc = 0; cc < 13; cc++) rf += psum[tid * 13 + cc];
        float rdl = rf - diagv[tid];
        idcs[tid] = 1.0f / (sqrtf(rdl) + EPSV);
    } else if (tid == 104) {
        float num = 0.f;
        for (int i = 0; i < KA; i++) num += diagv[i];
        redv[0] = num;
    } else if (tid == 105) {
        float fro = 0.f, tr = 0.f;
        for (int i = 0; i < 91; i++) { fro += stat[2 * i]; tr += stat[2 * i + 1]; }
        redv[1] = fro;
        redv[2] = tr;
    } else if (tid == 106) {
        // placeholder; den reduced below by tid==0 path after this sync
    }
    if (tid == 107) {
        float den = 0.f;
        for (int i = 0; i < 128; i++) den += denp[i];
        redv[3] = den;
    }
    __syncthreads();

    if (tid == 0) {
        float num = redv[0], fro = redv[1], tr = redv[2], den = redv[3];
        float nrm = sqrtf(fro);
        float orth2 = 2.f - 2.f * tr / (nrm * 10.0f);   // sqrt(KA)=10
        float ortho = sqrtf(fmaxf(orth2, 0.f));
        lossb[b] = -num / den + ortho;
    }
    // Phase F: normalized adj1 write + dflat2 partials
    if (sel == 0) {
        float* C = adj1 + (size_t)b * KA * KA;
#pragma unroll
        for (int u = 0; u < 8; u++) {
            int i = r * 8 + u;
            if (i >= KA) continue;
            float idci = idcs[i];
            float ps = 0.f;
#pragma unroll
            for (int v = 0; v < 8; v++) {
                int j = c * 8 + v;
                if (j >= KA) continue;
                if (j == i) {
                    C[(size_t)i * KA + j] = 0.f;
                } else {
                    float val = acc[u][v] * idci * idcs[j];
                    C[(size_t)i * KA + j] = val;
                    ps += acc[u][v] * idcs[j];
                }
            }
            psum[i * 13 + c] = ps;
        }
    }
    __syncthreads();
    if (tid < KA) {
        float s = 0.f;
#pragma unroll
        for (int cc = 0; cc < 13; cc++) s += psum[tid * 13 + cc];
        dflat2[(size_t)b * KA + tid] = s * idcs[tid];
    }
}

// ---------------------------------------------------------------------------
// Stage-2 mega kernel (validated R14).
// ---------------------------------------------------------------------------
__global__ __launch_bounds__(256) void stage2_mega_kernel(
    const float* __restrict__ adj1, const float* __restrict__ x1,
    const float* __restrict__ relW, const float* __restrict__ relb,
    const float* __restrict__ rootW,
    const float* __restrict__ p2W, const float* __restrict__ p2b,
    const float* __restrict__ dflat2g, float* __restrict__ lossb,
    const float* __restrict__ c3rW, const float* __restrict__ c3rb,
    const float* __restrict__ c3oW,
    const float* __restrict__ l1W, const float* __restrict__ l1b,
    const float* __restrict__ l2W, const float* __restrict__ l2b,
    float* __restrict__ out) {
    extern __shared__ float sm[];
    float* adj1s = sm;
    float* x1s   = sm + 10000;
    float* relWs = sm + 13200;
    float* rootWs= sm + 14224;
    float* p2Ws  = sm + 15248;
    float* x2s   = sm + 15568;
    float* s2s   = sm + 18768;
    float* tt2s  = sm + 19768;
    float* adjr2s= sm + 20768;
    float* ss2s  = sm + 20868;
    float* adj2s = sm + 20968;
    float* idcs  = sm + 21068;
    float* x3s   = sm + 21084;
    int b = blockIdx.x, tid = threadIdx.x;
    const float* A = adj1 + (size_t)b * KA * KA;
    const float* X = x1 + (size_t)b * KA * HID;
    for (int i = tid; i < KA * KA; i += 256) adj1s[i] = A[i];
    for (int i = tid; i < KA * HID; i += 256) x1s[i] = X[i];
    for (int i = tid; i < HID * HID; i += 256) { relWs[i] = relW[i]; rootWs[i] = rootW[i]; }
    for (int i = tid; i < HID * KB; i += 256) p2Ws[i] = p2W[i];
    __syncthreads();
    int lane = tid & 31, warp = tid >> 5;
    float rb = relb[lane];
    int kk10 = lane < KB ? lane : 0;
    float p2bv = p2b[kk10];
    for (int i = warp; i < KA; i += 8) {
        float t2 = 0.f;
        const float* ar = adj1s + i * KA;
        for (int m = 0; m < KA; m++) t2 += ar[m] * x1s[(m << 5) + lane];
        float x1v = x1s[(i << 5) + lane];
        float a = rb;
#pragma unroll
        for (int k = 0; k < 32; k++)
            a += __shfl_sync(0xffffffffu, t2, k) * relWs[(k << 5) + lane]
               + __shfl_sync(0xffffffffu, x1v, k) * rootWs[(k << 5) + lane];
        float x2v = fmaxf(a, 0.f);
        x2s[(i << 5) + lane] = x2v;
        float zz = p2bv;
#pragma unroll
        for (int c = 0; c < 32; c++)
            zz += __shfl_sync(0xffffffffu, x2v, c) * p2Ws[c * KB + kk10];
        float e = (lane < KB) ? __expf(zz) : 0.f;
        float ssum = e;
#pragma unroll
        for (int o = 16; o; o >>= 1) ssum += __shfl_xor_sync(0xffffffffu, ssum, o);
        if (lane < KB) s2s[i * KB + lane] = e / ssum;
    }
    __syncthreads();
    for (int t = tid; t < KA * KB; t += 256) {
        int i = t / KB, k = t - i * KB;
        float a = 0.f;
        const float* ar = adj1s + i * KA;
        for (int m = 0; m < KA; m++) a += ar[m] * s2s[m * KB + k];
        tt2s[t] = a;
    }
    __syncthreads();
    for (int t = tid; t < 520; t += 256) {
        if (t < 100) {
            int i = t / 10, j = t - i * 10;
            float a = 0.f;
            for (int n = 0; n < KA; n++) a += s2s[n * KB + i] * tt2s[n * KB + j];
            adjr2s[t] = a;
        } else if (t < 200) {
            int u = t - 100;
            int i = u / 10, j = u - i * 10;
            float a = 0.f;
            for (int n = 0; n < KA; n++) a += s2s[n * KB + i] * s2s[n * KB + j];
            ss2s[u] = a;
        } else {
            int u = t - 200;
            int i = u >> 5, c = u & 31;
            float a = 0.f;
            for (int n = 0; n < KA; n++) a += s2s[n * KB + i] * x2s[(n << 5) + c];
            x3s[u] = a;
        }
    }
    __syncthreads();

    if (tid < 32) {
        const float* df = dflat2g + (size_t)b * KA;
        float v = (lane < KB) ? adjr2s[lane * KB + lane] : 0.f;
#pragma unroll
        for (int o = 16; o; o >>= 1) v += __shfl_xor_sync(0xffffffffu, v, o);
        float num = v;
        v = 0.f;
        for (int n = lane; n < KA; n += 32) {
            float acc = 0.f;
#pragma unroll
            for (int k = 0; k < KB; k++) { float sv = s2s[n * KB + k]; acc += sv * sv; }
            v += acc * df[n];
        }
#pragma unroll
        for (int o = 16; o; o >>= 1) v += __shfl_xor_sync(0xffffffffu, v, o);
        float den = v;
        v = 0.f;
        for (int t = lane; t < 100; t += 32) { float q = ss2s[t]; v += q * q; }
#pragma unroll
        for (int o = 16; o; o >>= 1) v += __shfl_xor_sync(0xffffffffu, v, o);
        float nrm = sqrtf(v);
        float invn = 1.0f / nrm;
        float dk = rsqrtf((float)KB);
        v = 0.f;
        for (int t = lane; t < 100; t += 32) {
            int i = t / 10, j = t - i * 10;
            float q = ss2s[t] * invn - ((i == j) ? dk : 0.f);
            v += q * q;
        }
#pragma unroll
        for (int o = 16; o; o >>= 1) v += __shfl_xor_sync(0xffffffffu, v, o);
        float ortho = sqrtf(v);
        if (lane < KB) {
            float rsum = 0.f;
            for (int j = 0; j < KB; j++) if (j != lane) rsum += adjr2s[lane * KB + j];
            idcs[lane] = 1.0f / (sqrtf(rsum) + EPSV);
        }
        __syncwarp();
        for (int t = lane; t < 100; t += 32) {
            int i = t / 10, j = t - i * 10;
            adj2s[t] = (i == j) ? 0.f : adjr2s[t] * idcs[i] * idcs[j];
        }
        if (lane == 0) lossb[b] += -num / den + ortho;
        __syncwarp();

        float x3c[10], t3c[10];
#pragma unroll
        for (int j = 0; j < 10; j++) x3c[j] = x3s[j * 32 + lane];
#pragma unroll
        for (int i = 0; i < 10; i++) {
            float a = 0.f;
#pragma unroll
            for (int j = 0; j < 10; j++) a += adj2s[i * 10 + j] * x3c[j];
            t3c[i] = a;
        }
        float rb3 = c3rb[lane];
        float g = 0.f;
#pragma unroll
        for (int i = 0; i < 10; i++) {
            float a = rb3;
#pragma unroll
            for (int k = 0; k < 32; k++)
                a += __shfl_sync(0xffffffffu, t3c[i], k) * c3rW[k * 32 + lane]
                   + __shfl_sync(0xffffffffu, x3c[i], k) * c3oW[k * 32 + lane];
            g += a;
        }
        g *= 0.1f;
        float a1 = l1b[lane];
#pragma unroll
        for (int k = 0; k < 32; k++) a1 += __shfl_sync(0xffffffffu, g, k) * l1W[k * 32 + lane];
        float gg = fmaxf(a1, 0.f);
        float a2 = l2b[kk10];
#pragma unroll
        for (int k = 0; k < 32; k++) a2 += __shfl_sync(0xffffffffu, gg, k) * l2W[k * OC + kk10];
        float val = (lane < OC) ? a2 : -INFINITY;
        float m = val;
#pragma unroll
        for (int o = 16; o; o >>= 1) m = fmaxf(m, __shfl_xor_sync(0xffffffffu, m, o));
        float e = (lane < OC) ? __expf(val - m) : 0.f;
        float ssum = e;
#pragma unroll
        for (int o = 16; o; o >>= 1) ssum += __shfl_xor_sync(0xffffffffu, ssum, o);
        if (lane < OC) out[b * OC + lane] = val - m - logf(ssum);
    }
}

__global__ void final_kernel(const float* __restrict__ lossb, float* __restrict__ out,
                             int out_size) {
    __shared__ float sm[128];
    int t = threadIdx.x;
    sm[t] = lossb[t];
    __syncthreads();
    for (int s = 64; s > 0; s >>= 1) {
        if (t < s) sm[t] += sm[t + s];
        __syncthreads();
    }
    if (t == 0 && out_size > BATCH * OC) out[BATCH * OC] = sm[0] / (float)BATCH;
}

// ---------------------------------------------------------------------------
extern "C" void kernel_launch(void* const* d_in, const int* in_sizes, int n_in,
                              void* d_out, int out_size) {
    const float* x    = (const float*)d_in[0];
    const int*   ei   = (const int*)  d_in[1];
    const float* c1W  = (const float*)d_in[3];
    const float* c1b  = (const float*)d_in[4];
    const float* p1W  = (const float*)d_in[5];
    const float* p1b  = (const float*)d_in[6];
    const float* c2rW = (const float*)d_in[7];
    const float* c2rb = (const float*)d_in[8];
    const float* c2oW = (const float*)d_in[9];
    const float* p2W  = (const float*)d_in[10];
    const float* p2b  = (const float*)d_in[11];
    const float* c3rW = (const float*)d_in[12];
    const float* c3rb = (const float*)d_in[13];
    const float* c3oW = (const float*)d_in[14];
    const float* l1W  = (const float*)d_in[15];
    const float* l1b  = (const float*)d_in[16];
    const float* l2W  = (const float*)d_in[17];
    const float* l2b  = (const float*)d_in[18];
    float* out = (float*)d_out;
    int E = in_sizes[1] / 2;
    int eper = E / BATCH;

    void* sp = nullptr;
    cudaGetSymbolAddress(&sp, g_scratch);
    float* S = (float*)sp;
    int *csn, *cdn, *osn, *odn, *lsrc, *ldst;
    cudaGetSymbolAddress((void**)&csn, g_cnt_src);
    cudaGetSymbolAddress((void**)&cdn, g_cnt_dst);
    cudaGetSymbolAddress((void**)&osn, g_off_src);
    cudaGetSymbolAddress((void**)&odn, g_off_dst);
    cudaGetSymbolAddress((void**)&lsrc, g_list_src);
    cudaGetSymbolAddress((void**)&ldst, g_list_dst);

    cudaFuncSetAttribute(gram_fused_kernel, cudaFuncAttributeMaxDynamicSharedMemorySize, 49152);
    cudaFuncSetAttribute(stage2_mega_kernel, cudaFuncAttributeMaxDynamicSharedMemorySize, 85632);

    build_csr_kernel<<<BATCH, 512>>>(ei, E, eper, osn, csn, odn, cdn, lsrc, ldst,
                                     S + OFF_DEG, S + OFF_DFLAT);
    xwp_kernel<<<TOT / 8, dim3(32, 8)>>>(x, c1W, S + OFF_DEG, S + OFF_XWP);
    agg_softmax_kernel<<<TOT / 64, 256>>>(odn, cdn, ldst, S + OFF_XWP, S + OFF_DEG,
                                          c1b, p1W, p1b, S + OFF_H, S + OFF_S1);
    t1_gather_kernel<<<TOT * 32 / 256, 256>>>(osn, csn, lsrc, S + OFF_S1, S + OFF_T1);
    gram_fused_kernel<<<BATCH, 320, 49152>>>(S + OFF_S1, S + OFF_T1, S + OFF_H,
                                             S + OFF_DFLAT, S + OFF_ADJ1, S + OFF_X1,
                                             S + OFF_DFLAT2, S + OFF_LOSSB);
    stage2_mega_kernel<<<BATCH, 256, 85632>>>(S + OFF_ADJ1, S + OFF_X1, c2rW, c2rb, c2oW,
                                              p2W, p2b, S + OFF_DFLAT2, S + OFF_LOSSB,
                                              c3rW, c3rb, c3oW, l1W, l1b, l2W, l2b, out);
    final_kernel<<<1, 128>>>(S + OFF_LOSSB, out, out_size);
}